// round 1
// baseline (speedup 1.0000x reference)
#include <cuda_runtime.h>
#include <math.h>

// Problem constants (fixed by dataset)
#define NNODE 50000
#define NEDGE 320000
#define DEMB  128
#define DIN   192          // EMB + EA + ET
#define NB    3
#define LAM   0.01f
#define LNEPS 1e-5f

#define TILE_E 64
#define NTILE  (NEDGE / TILE_E)   // 5000
#define XPAD   68                 // row stride for xs/act (mult of 4 for float4 alignment)

// ---------------- device scratch (static allocation only) ----------------
__device__ float g_ct192[192], g_st192[192];
__device__ float g_ct384[384], g_st384[384];
__device__ float g_A[DIN * 768];          // combined FFT+complex-linear matrix, [n][band*256+cc]
__device__ float g_Wr[384 * 128];
__device__ float g_Wi[384 * 128];
__device__ float g_W[768 * 128];          // combined ifft+fre_w+comb_w matrix
__device__ float g_cvec[128];             // constant bias of msg2
__device__ float g_dvec[NB * 128];        // per-band contribution when band fully masked
__device__ float g_nodenorm[NNODE];
__device__ float g_energy[NEDGE];
__device__ float g_esum_part[256];
__device__ float g_esum;
__device__ unsigned char g_maskb[NEDGE];
__device__ float g_acc[NNODE * DEMB];     // node accumulator (init = boundary_condition)

// ---------------- precompute kernels ----------------
__global__ void k_tables() {
    int t = threadIdx.x;
    if (t < 192) {
        g_ct192[t] = (float)cospi(2.0 * t / 192.0);
        g_st192[t] = (float)sinpi(2.0 * t / 192.0);
    }
    if (t < 384) {
        g_ct384[t] = (float)cospi(2.0 * t / 384.0);
        g_st384[t] = (float)sinpi(2.0 * t / 384.0);
    }
    if (t < 256) g_esum_part[t] = 0.0f;
    if (t == 0) g_esum = 0.0f;
}

// A[n][c]: c = k*256 + cc.  cc<128 -> real-output col m=cc, else imag col m=cc-128
__global__ void k_buildA(const float* __restrict__ r1, const float* __restrict__ i1) {
    __shared__ float ct[192], st[192];
    int n = threadIdx.x;              // 192 threads
    int c = blockIdx.x;               // 768 blocks
    ct[n] = g_ct192[n]; st[n] = g_st192[n];
    __syncthreads();
    int k = c >> 8, cc = c & 255;
    const float* R = r1 + k * DIN * DEMB;
    const float* I = i1 + k * DIN * DEMB;
    float s = 0.0f;
    if (cc < 128) {
        int m = cc;
        for (int j = 0; j < 192; j++) {
            int t = (j * n) % 192;
            s += ct[t] * R[j * DEMB + m] + st[t] * I[j * DEMB + m];
        }
    } else {
        int m = cc - 128;
        for (int j = 0; j < 192; j++) {
            int t = (j * n) % 192;
            s += ct[t] * I[j * DEMB + m] - st[t] * R[j * DEMB + m];
        }
    }
    g_A[n * 768 + c] = s;
}

// Wr/Wi[j][p] = +-(1/384) * sum_n trig(2*pi*j*n/384) * fre_w[n][p]
__global__ void k_buildWrWi(const float* __restrict__ fre_w) {
    __shared__ float ct[384], st[384];
    int p = threadIdx.x;              // 128 threads
    int j = blockIdx.x;               // 384 blocks
    for (int t = p; t < 384; t += 128) { ct[t] = g_ct384[t]; st[t] = g_st384[t]; }
    __syncthreads();
    float sr = 0.0f, si = 0.0f;
    for (int n = 0; n < 384; n++) {
        int t = (j * n) % 384;
        float w = fre_w[n * 128 + p];
        sr += ct[t] * w;
        si -= st[t] * w;
    }
    g_Wr[j * 128 + p] = sr * (1.0f / 384.0f);
    g_Wi[j * 128 + p] = si * (1.0f / 384.0f);
}

// W[r][m] = sum_p Wsel[j][p] * comb_w[2p][m]
__global__ void k_buildW(const float* __restrict__ comb_w) {
    int m = threadIdx.x;              // 128 threads
    int r = blockIdx.x;               // 768 blocks
    int k = r >> 8, cc = r & 255;
    int j = k * 128 + (cc & 127);
    const float* src = (cc < 128) ? g_Wr : g_Wi;
    float s = 0.0f;
    for (int p = 0; p < 128; p++)
        s += src[j * 128 + p] * comb_w[(2 * p) * 128 + m];
    g_W[r * 128 + m] = s;
}

__global__ void k_buildCD(const float* __restrict__ fre_b, const float* __restrict__ comb_w,
                          const float* __restrict__ comb_b,
                          const float* __restrict__ rb1, const float* __restrict__ ib1) {
    int m = threadIdx.x;              // 128 threads
    float s = 0.0f;
    for (int p = 0; p < 128; p++)
        s += fre_b[p] * comb_w[(2 * p) * 128 + m];
    g_cvec[m] = s + comb_b[m];
    for (int k = 0; k < NB; k++) {
        float d = 0.0f;
        for (int j0 = 0; j0 < 128; j0++) {
            float ar = fmaxf(rb1[k * 128 + j0] - LAM, 0.0f);
            float ai = fmaxf(ib1[k * 128 + j0] - LAM, 0.0f);
            d += ar * g_W[(k * 256 + j0) * 128 + m]
               + ai * g_W[(k * 256 + 128 + j0) * 128 + m];
        }
        g_dvec[k * 128 + m] = d;
    }
}

// ---------------- energy / mask ----------------
__global__ void k_nodenorm(const float* __restrict__ hidden) {
    int tid = threadIdx.x, w = tid >> 5, lane = tid & 31;
    int n = blockIdx.x * 8 + w;       // 6250 blocks * 8 warps = 50000
    const float* h = hidden + (size_t)n * DEMB;
    float s = 0.0f;
    #pragma unroll
    for (int i = 0; i < 4; i++) { float v = h[lane + 32 * i]; s += v * v; }
    #pragma unroll
    for (int off = 16; off; off >>= 1) s += __shfl_xor_sync(0xffffffffu, s, off);
    if (lane == 0) g_nodenorm[n] = s;
}

__global__ void k_energy(const float* __restrict__ ea, const float* __restrict__ ete,
                         const int* __restrict__ ei) {
    __shared__ float wsum[8];
    int tid = threadIdx.x, w = tid >> 5, lane = tid & 31;
    int e = blockIdx.x * 8 + w;       // 40000 blocks
    float a = ea[(size_t)e * 32 + lane];
    float b = ete[(size_t)e * 32 + lane];
    float s = a * a + b * b;
    #pragma unroll
    for (int off = 16; off; off >>= 1) s += __shfl_xor_sync(0xffffffffu, s, off);
    if (lane == 0) {
        float en = 192.0f * (g_nodenorm[ei[e]] + s);
        g_energy[e] = en;
        wsum[w] = en;
    }
    __syncthreads();
    if (tid == 0) {
        float t = 0.0f;
        #pragma unroll
        for (int i = 0; i < 8; i++) t += wsum[i];
        atomicAdd(&g_esum_part[blockIdx.x & 255], t);
    }
}

__global__ void k_reduce_esum() {
    __shared__ float rs[8];
    int tid = threadIdx.x;
    float v = g_esum_part[tid];
    #pragma unroll
    for (int off = 16; off; off >>= 1) v += __shfl_xor_sync(0xffffffffu, v, off);
    if ((tid & 31) == 0) rs[tid >> 5] = v;
    __syncthreads();
    if (tid == 0) {
        float t = 0.0f;
        #pragma unroll
        for (int i = 0; i < 8; i++) t += rs[i];
        g_esum = t;
    }
}

__global__ void k_mask(const float* __restrict__ alpha) {
    int e = blockIdx.x * 256 + threadIdx.x;   // 1250 blocks
    float en = g_energy[e];
    float es = g_esum;
    unsigned char mb = 0;
    #pragma unroll
    for (int k = 0; k < NB; k++) {
        float al = alpha[k];
        float factor = (2.0f * (k + 1) - 1.0f) / (2.0f * NB);
        float Q = al * factor * es;
        float bnd = es / (al * (2.0f * NB));
        if (en >= Q - bnd && en <= Q + bnd) mb |= (1 << k);
    }
    g_maskb[e] = mb;
}

__global__ void k_initacc(const float* __restrict__ boundary) {
    const float4* s = (const float4*)boundary;
    float4* d = (float4*)g_acc;
    int n4 = NNODE * DEMB / 4;
    for (int i = blockIdx.x * blockDim.x + threadIdx.x; i < n4; i += gridDim.x * blockDim.x)
        d[i] = s[i];
}

// ---------------- main fused edge kernel ----------------
// smem layout (dynamic): xs[192][XPAD], act[256][XPAD], bs[8][256]
#define SMEM_EDGE ((DIN * XPAD + 256 * XPAD + 8 * 256) * 4)

__global__ void __launch_bounds__(256, 1)
k_edge(const float* __restrict__ hidden, const float* __restrict__ ea,
       const float* __restrict__ ete, const int* __restrict__ ei,
       const float* __restrict__ rb1, const float* __restrict__ ib1) {
    extern __shared__ float sm[];
    float* xs  = sm;                        // [192][XPAD]
    float* act = sm + DIN * XPAD;           // [256][XPAD]
    float* bs  = sm + DIN * XPAD + 256 * XPAD;  // [8][256] (GEMM2 reuses as [8][128])
    __shared__ int s_src[TILE_E];
    __shared__ int s_dst[TILE_E];
    __shared__ unsigned char s_mk[TILE_E];
    __shared__ int s_any[NB];

    int tid = threadIdx.x;
    int eb = blockIdx.x * TILE_E;

    if (tid < TILE_E) {
        s_src[tid] = ei[eb + tid];
        s_dst[tid] = ei[NEDGE + eb + tid];
        s_mk[tid]  = g_maskb[eb + tid];
    }
    __syncthreads();
    if (tid < NB) {
        int a = 0;
        for (int e = 0; e < TILE_E; e++) a |= (s_mk[e] >> tid) & 1;
        s_any[tid] = a;
    }
    // gather x tile (transposed: xs[feature][edge])
    for (int idx = tid; idx < TILE_E * DIN; idx += 256) {
        int e = idx / DIN, k = idx - e * DIN;
        float v;
        if (k < 128)      v = hidden[(size_t)s_src[e] * DEMB + k];
        else if (k < 160) v = ea[(size_t)(eb + e) * 32 + (k - 128)];
        else              v = ete[(size_t)(eb + e) * 32 + (k - 160)];
        xs[k * XPAD + e] = v;
    }
    __syncthreads();

    // msg2 accumulators: 4 edges x 8 cols per thread
    int ty2 = tid >> 4, tx2 = tid & 15;
    int m0 = tx2 * 8, e20 = ty2 * 4;
    float r2[4][8];
    {
        float base[8];
        #pragma unroll
        for (int j = 0; j < 8; j++) base[j] = g_cvec[m0 + j];
        for (int k = 0; k < NB; k++)
            if (!s_any[k])
                #pragma unroll
                for (int j = 0; j < 8; j++) base[j] += g_dvec[k * 128 + m0 + j];
        #pragma unroll
        for (int i = 0; i < 4; i++)
            #pragma unroll
            for (int j = 0; j < 8; j++) r2[i][j] = base[j];
    }

    int ty = tid >> 5, tx = tid & 31;
    int e10 = ty * 8, c0 = tx * 8;

    for (int k = 0; k < NB; k++) {
        if (!s_any[k]) continue;
        // ---- GEMM1: u[64][256] = x[64][192] @ A_k[192][256] ----
        float a1[8][8];
        #pragma unroll
        for (int i = 0; i < 8; i++)
            #pragma unroll
            for (int j = 0; j < 8; j++) a1[i][j] = 0.0f;

        for (int kc = 0; kc < DIN; kc += 8) {
            __syncthreads();
            for (int idx = tid; idx < 8 * 256; idx += 256) {
                int rr = idx >> 8, cc = idx & 255;
                bs[rr * 256 + cc] = g_A[(kc + rr) * 768 + k * 256 + cc];
            }
            __syncthreads();
            #pragma unroll
            for (int kk = 0; kk < 8; kk++) {
                float4 xa = *(const float4*)&xs[(kc + kk) * XPAD + e10];
                float4 xb = *(const float4*)&xs[(kc + kk) * XPAD + e10 + 4];
                float4 ba = *(const float4*)&bs[kk * 256 + c0];
                float4 bb = *(const float4*)&bs[kk * 256 + c0 + 4];
                float xv[8] = {xa.x, xa.y, xa.z, xa.w, xb.x, xb.y, xb.z, xb.w};
                float bv[8] = {ba.x, ba.y, ba.z, ba.w, bb.x, bb.y, bb.z, bb.w};
                #pragma unroll
                for (int i = 0; i < 8; i++)
                    #pragma unroll
                    for (int j = 0; j < 8; j++)
                        a1[i][j] = fmaf(xv[i], bv[j], a1[i][j]);
            }
        }
        __syncthreads();
        // ---- activation: act[c][e] = max(mask*u + bias - lam, 0) ----
        #pragma unroll
        for (int j = 0; j < 8; j++) {
            int c = c0 + j;
            float bias = (c < 128) ? rb1[k * 128 + c] : ib1[k * 128 + (c - 128)];
            #pragma unroll
            for (int i = 0; i < 8; i++) {
                int e = e10 + i;
                float mv = ((s_mk[e] >> k) & 1) ? 1.0f : 0.0f;
                act[c * XPAD + e] = fmaxf(fmaf(mv, a1[i][j], bias) - LAM, 0.0f);
            }
        }
        __syncthreads();
        // ---- GEMM2: msg2[64][128] += act[64][256] @ W_k[256][128] ----
        for (int cb = 0; cb < 256; cb += 8) {
            for (int idx = tid; idx < 8 * 128; idx += 256) {
                int rr = idx >> 7, cc = idx & 127;
                bs[rr * 128 + cc] = g_W[(k * 256 + cb + rr) * 128 + cc];
            }
            __syncthreads();
            #pragma unroll
            for (int cc = 0; cc < 8; cc++) {
                float4 av4 = *(const float4*)&act[(cb + cc) * XPAD + e20];
                float4 wa = *(const float4*)&bs[cc * 128 + m0];
                float4 wb = *(const float4*)&bs[cc * 128 + m0 + 4];
                float av[4] = {av4.x, av4.y, av4.z, av4.w};
                float wv[8] = {wa.x, wa.y, wa.z, wa.w, wb.x, wb.y, wb.z, wb.w};
                #pragma unroll
                for (int i = 0; i < 4; i++)
                    #pragma unroll
                    for (int j = 0; j < 8; j++)
                        r2[i][j] = fmaf(av[i], wv[j], r2[i][j]);
            }
            __syncthreads();
        }
    }

    // ---- scatter-add into node accumulator (vector reductions) ----
    #pragma unroll
    for (int i = 0; i < 4; i++) {
        int d = s_dst[e20 + i];
        float* p = g_acc + (size_t)d * DEMB + m0;
        asm volatile("red.global.add.v4.f32 [%0], {%1,%2,%3,%4};"
                     :: "l"(p), "f"(r2[i][0]), "f"(r2[i][1]), "f"(r2[i][2]), "f"(r2[i][3])
                     : "memory");
        asm volatile("red.global.add.v4.f32 [%0], {%1,%2,%3,%4};"
                     :: "l"(p + 4), "f"(r2[i][4]), "f"(r2[i][5]), "f"(r2[i][6]), "f"(r2[i][7])
                     : "memory");
    }
}

// ---------------- node epilogue: @lin_w + bias, LayerNorm, ReLU ----------------
#define SMEM_FINAL ((128 * 128 + 16 * 128) * 4)

__global__ void __launch_bounds__(256, 1)
k_final(const float* __restrict__ lin_w, const float* __restrict__ lin_b,
        const float* __restrict__ ln_g, const float* __restrict__ ln_b,
        float* __restrict__ out) {
    extern __shared__ float sm[];
    float* lw = sm;                 // [128][128]
    float* at = sm + 128 * 128;     // [16][128]
    int tid = threadIdx.x;
    int n0 = blockIdx.x * 16;       // 3125 blocks

    for (int idx = tid; idx < 128 * 128; idx += 256) lw[idx] = lin_w[idx];
    for (int idx = tid; idx < 16 * 128; idx += 256)  at[idx] = g_acc[(size_t)n0 * DEMB + idx];
    __syncthreads();

    int i = tid >> 4;               // node within tile
    int m0 = (tid & 15) * 8;        // output cols
    float t[8];
    #pragma unroll
    for (int j = 0; j < 8; j++) t[j] = lin_b[m0 + j];
    const float* ar = at + i * 128;
    for (int q = 0; q < 128; q++) {
        float av = ar[q];
        float4 w1 = *(const float4*)&lw[q * 128 + m0];
        float4 w2 = *(const float4*)&lw[q * 128 + m0 + 4];
        t[0] = fmaf(av, w1.x, t[0]); t[1] = fmaf(av, w1.y, t[1]);
        t[2] = fmaf(av, w1.z, t[2]); t[3] = fmaf(av, w1.w, t[3]);
        t[4] = fmaf(av, w2.x, t[4]); t[5] = fmaf(av, w2.y, t[5]);
        t[6] = fmaf(av, w2.z, t[6]); t[7] = fmaf(av, w2.w, t[7]);
    }
    // LayerNorm over 128 (16 threads per node, each holds 8)
    float s1 = 0.0f;
    #pragma unroll
    for (int j = 0; j < 8; j++) s1 += t[j];
    #pragma unroll
    for (int off = 8; off; off >>= 1) s1 += __shfl_xor_sync(0xffffffffu, s1, off, 16);
    float mu = s1 * (1.0f / 128.0f);
    float s2 = 0.0f;
    #pragma unroll
    for (int j = 0; j < 8; j++) { float d = t[j] - mu; s2 += d * d; }
    #pragma unroll
    for (int off = 8; off; off >>= 1) s2 += __shfl_xor_sync(0xffffffffu, s2, off, 16);
    float inv = rsqrtf(s2 * (1.0f / 128.0f) + LNEPS);
    #pragma unroll
    for (int j = 0; j < 8; j++) {
        int m = m0 + j;
        float y = (t[j] - mu) * inv * ln_g[m] + ln_b[m];
        out[(size_t)(n0 + i) * DEMB + m] = fmaxf(y, 0.0f);
    }
}

// ---------------- launcher ----------------
extern "C" void kernel_launch(void* const* d_in, const int* in_sizes, int n_in,
                              void* d_out, int out_size) {
    const float* hidden   = (const float*)d_in[0];
    const float* edge_attr= (const float*)d_in[1];
    const float* ete      = (const float*)d_in[2];
    const float* boundary = (const float*)d_in[3];
    const float* alpha    = (const float*)d_in[4];
    const float* r1       = (const float*)d_in[5];
    const float* i1       = (const float*)d_in[6];
    const float* rb1      = (const float*)d_in[7];
    const float* ib1      = (const float*)d_in[8];
    const float* fre_w    = (const float*)d_in[9];
    const float* fre_b    = (const float*)d_in[10];
    const float* comb_w   = (const float*)d_in[11];
    const float* comb_b   = (const float*)d_in[12];
    const float* lin_w    = (const float*)d_in[13];
    const float* lin_b    = (const float*)d_in[14];
    const float* ln_g     = (const float*)d_in[15];
    const float* ln_b     = (const float*)d_in[16];
    const int*   ei       = (const int*)d_in[17];
    float* out = (float*)d_out;

    cudaFuncSetAttribute(k_edge,  cudaFuncAttributeMaxDynamicSharedMemorySize, SMEM_EDGE);
    cudaFuncSetAttribute(k_final, cudaFuncAttributeMaxDynamicSharedMemorySize, SMEM_FINAL);

    k_tables<<<1, 384>>>();
    k_buildA<<<768, 192>>>(r1, i1);
    k_buildWrWi<<<384, 128>>>(fre_w);
    k_buildW<<<768, 128>>>(comb_w);
    k_buildCD<<<1, 128>>>(fre_b, comb_w, comb_b, rb1, ib1);
    k_nodenorm<<<NNODE / 8, 256>>>(hidden);
    k_energy<<<NEDGE / 8, 256>>>(edge_attr, ete, ei);
    k_reduce_esum<<<1, 256>>>();
    k_mask<<<NEDGE / 256, 256>>>(alpha);
    k_initacc<<<3125, 256>>>(boundary);
    k_edge<<<NTILE, 256, SMEM_EDGE>>>(hidden, edge_attr, ete, ei, rb1, ib1);
    k_final<<<NNODE / 16, 256, SMEM_FINAL>>>(lin_w, lin_b, ln_g, ln_b, out);
}

// round 3
// speedup vs baseline: 4.0487x; 4.0487x over previous
#include <cuda_runtime.h>
#include <cuda_fp16.h>
#include <math.h>
#include <stdint.h>

// Problem constants
#define NNODE 50000
#define NEDGE 320000
#define DEMB  128
#define DIN   192
#define NB    3
#define LAM   0.01f
#define LNEPS 1e-5f

#define TE    128
#define NT    (NEDGE / TE)        // 2500

// ---------------- device scratch ----------------
__device__ float g_ct192[192], g_st192[192];
__device__ float g_ct384[384], g_st384[384];
__device__ float g_A[DIN * 768];
__device__ float g_Wr[384 * 128];
__device__ float g_Wi[384 * 128];
__device__ float g_W[768 * 128];
__device__ float g_cvec[128];
__device__ float g_dvec[NB * 128];
__device__ float g_nodenorm[NNODE];
__device__ float g_energy[NEDGE];
__device__ float g_esum_part[256];
__device__ float g_esum;
__device__ unsigned char g_maskb[NEDGE];
__device__ float g_acc[NNODE * DEMB];

// fp16 hi/lo transposed operands: B1[band][n(256)][k(192)], B2[band][n(128)][k(256)]
__device__ __align__(16) __half g_B1h[NB * 256 * 192], g_B1l[NB * 256 * 192];
__device__ __align__(16) __half g_B2h[NB * 128 * 256], g_B2l[NB * 128 * 256];

// ---------------- helpers ----------------
__device__ __forceinline__ uint32_t smem_u32(const void* p) {
    uint32_t a;
    asm("{ .reg .u64 t; cvta.to.shared.u64 t, %1; cvt.u32.u64 %0, t; }" : "=r"(a) : "l"(p));
    return a;
}
__device__ __forceinline__ void splith(float v, __half& h, __half& l) {
    h = __float2half_rn(v);
    l = __float2half_rn(v - __half2float(h));
}

#define LDSM4(R, addr) \
    asm volatile("ldmatrix.sync.aligned.m8n8.x4.shared.b16 {%0,%1,%2,%3}, [%4];" \
        : "=r"((R)[0]), "=r"((R)[1]), "=r"((R)[2]), "=r"((R)[3]) : "r"(addr))

#define MMA16816(C, A, B0, B1) \
    asm volatile("mma.sync.aligned.m16n8k16.row.col.f32.f16.f16.f32 " \
        "{%0,%1,%2,%3}, {%4,%5,%6,%7}, {%8,%9}, {%0,%1,%2,%3};" \
        : "+f"((C)[0]), "+f"((C)[1]), "+f"((C)[2]), "+f"((C)[3]) \
        : "r"((A)[0]), "r"((A)[1]), "r"((A)[2]), "r"((A)[3]), "r"(B0), "r"(B1))

// one K=32 chunk: A from smem (row-major, aStride bytes), B from staging [128][40] halfs
__device__ __forceinline__ void chunk_mma(float (&acc)[2][8][4],
                                          uint32_t aAddr, uint32_t aStride, uint32_t bAddr) {
    #pragma unroll
    for (int k16 = 0; k16 < 32; k16 += 16) {
        uint32_t a0[4], a1[4], b[4][4];
        LDSM4(a0, aAddr + k16 * 2);
        LDSM4(a1, aAddr + 16 * aStride + k16 * 2);
        #pragma unroll
        for (int ntp = 0; ntp < 4; ntp++) LDSM4(b[ntp], bAddr + ntp * 16 * 80 + k16 * 2);
        #pragma unroll
        for (int ntp = 0; ntp < 4; ntp++) {
            MMA16816(acc[0][2 * ntp],     a0, b[ntp][0], b[ntp][1]);
            MMA16816(acc[0][2 * ntp + 1], a0, b[ntp][2], b[ntp][3]);
            MMA16816(acc[1][2 * ntp],     a1, b[ntp][0], b[ntp][1]);
            MMA16816(acc[1][2 * ntp + 1], a1, b[ntp][2], b[ntp][3]);
        }
    }
}

// ---------------- precompute (proven in R1) ----------------
__global__ void k_tables() {
    int t = threadIdx.x;
    if (t < 192) { g_ct192[t] = (float)cospi(2.0 * t / 192.0); g_st192[t] = (float)sinpi(2.0 * t / 192.0); }
    if (t < 384) { g_ct384[t] = (float)cospi(2.0 * t / 384.0); g_st384[t] = (float)sinpi(2.0 * t / 384.0); }
    if (t < 256) g_esum_part[t] = 0.0f;
    if (t == 0) g_esum = 0.0f;
}

__global__ void k_buildA(const float* __restrict__ r1, const float* __restrict__ i1) {
    __shared__ float ct[192], st[192];
    int n = threadIdx.x, c = blockIdx.x;
    ct[n] = g_ct192[n]; st[n] = g_st192[n];
    __syncthreads();
    int k = c >> 8, cc = c & 255;
    const float* R = r1 + k * DIN * DEMB;
    const float* I = i1 + k * DIN * DEMB;
    float s = 0.0f;
    if (cc < 128) {
        int m = cc;
        for (int j = 0; j < 192; j++) { int t = (j * n) % 192; s += ct[t] * R[j * DEMB + m] + st[t] * I[j * DEMB + m]; }
    } else {
        int m = cc - 128;
        for (int j = 0; j < 192; j++) { int t = (j * n) % 192; s += ct[t] * I[j * DEMB + m] - st[t] * R[j * DEMB + m]; }
    }
    g_A[n * 768 + c] = s;
}

__global__ void k_buildWrWi(const float* __restrict__ fre_w) {
    __shared__ float ct[384], st[384];
    int p = threadIdx.x, j = blockIdx.x;
    for (int t = p; t < 384; t += 128) { ct[t] = g_ct384[t]; st[t] = g_st384[t]; }
    __syncthreads();
    float sr = 0.0f, si = 0.0f;
    for (int n = 0; n < 384; n++) {
        int t = (j * n) % 384;
        float w = fre_w[n * 128 + p];
        sr += ct[t] * w; si -= st[t] * w;
    }
    g_Wr[j * 128 + p] = sr * (1.0f / 384.0f);
    g_Wi[j * 128 + p] = si * (1.0f / 384.0f);
}

__global__ void k_buildW(const float* __restrict__ comb_w) {
    int m = threadIdx.x, r = blockIdx.x;
    int k = r >> 8, cc = r & 255;
    int j = k * 128 + (cc & 127);
    const float* src = (cc < 128) ? g_Wr : g_Wi;
    float s = 0.0f;
    for (int p = 0; p < 128; p++) s += src[j * 128 + p] * comb_w[(2 * p) * 128 + m];
    g_W[r * 128 + m] = s;
}

__global__ void k_buildCD(const float* __restrict__ fre_b, const float* __restrict__ comb_w,
                          const float* __restrict__ comb_b,
                          const float* __restrict__ rb1, const float* __restrict__ ib1) {
    int m = threadIdx.x;
    float s = 0.0f;
    for (int p = 0; p < 128; p++) s += fre_b[p] * comb_w[(2 * p) * 128 + m];
    g_cvec[m] = s + comb_b[m];
    for (int k = 0; k < NB; k++) {
        float d = 0.0f;
        for (int j0 = 0; j0 < 128; j0++) {
            float ar = fmaxf(rb1[k * 128 + j0] - LAM, 0.0f);
            float ai = fmaxf(ib1[k * 128 + j0] - LAM, 0.0f);
            d += ar * g_W[(k * 256 + j0) * 128 + m] + ai * g_W[(k * 256 + 128 + j0) * 128 + m];
        }
        g_dvec[k * 128 + m] = d;
    }
}

// pack transposed fp16 hi/lo operands
__global__ void k_packB1() {     // 576 x 256
    int idx = blockIdx.x * 256 + threadIdx.x;    // 3*256*192
    int band = idx / 49152, r = idx % 49152;
    int n = r / 192, j = r % 192;
    float v = g_A[j * 768 + band * 256 + n];
    __half h, l; splith(v, h, l);
    g_B1h[idx] = h; g_B1l[idx] = l;
}
__global__ void k_packB2() {     // 384 x 256
    int idx = blockIdx.x * 256 + threadIdx.x;    // 3*128*256
    int band = idx / 32768, r = idx % 32768;
    int m = r / 256, c = r % 256;
    float v = g_W[(band * 256 + c) * 128 + m];
    __half h, l; splith(v, h, l);
    g_B2h[idx] = h; g_B2l[idx] = l;
}

// ---------------- energy / mask / init ----------------
__global__ void k_nodenorm(const float* __restrict__ hidden) {
    int tid = threadIdx.x, w = tid >> 5, lane = tid & 31;
    int n = blockIdx.x * 8 + w;
    const float* h = hidden + (size_t)n * DEMB;
    float s = 0.0f;
    #pragma unroll
    for (int i = 0; i < 4; i++) { float v = h[lane + 32 * i]; s += v * v; }
    #pragma unroll
    for (int off = 16; off; off >>= 1) s += __shfl_xor_sync(0xffffffffu, s, off);
    if (lane == 0) g_nodenorm[n] = s;
}

__global__ void k_energy(const float* __restrict__ ea, const float* __restrict__ ete,
                         const int* __restrict__ ei) {
    __shared__ float wsum[8];
    int tid = threadIdx.x, w = tid >> 5, lane = tid & 31;
    int e = blockIdx.x * 8 + w;
    float a = ea[(size_t)e * 32 + lane];
    float b = ete[(size_t)e * 32 + lane];
    float s = a * a + b * b;
    #pragma unroll
    for (int off = 16; off; off >>= 1) s += __shfl_xor_sync(0xffffffffu, s, off);
    if (lane == 0) { float en = 192.0f * (g_nodenorm[ei[e]] + s); g_energy[e] = en; wsum[w] = en; }
    __syncthreads();
    if (tid == 0) {
        float t = 0.0f;
        #pragma unroll
        for (int i = 0; i < 8; i++) t += wsum[i];
        atomicAdd(&g_esum_part[blockIdx.x & 255], t);
    }
}

__global__ void k_reduce_esum() {
    __shared__ float rs[8];
    int tid = threadIdx.x;
    float v = g_esum_part[tid];
    #pragma unroll
    for (int off = 16; off; off >>= 1) v += __shfl_xor_sync(0xffffffffu, v, off);
    if ((tid & 31) == 0) rs[tid >> 5] = v;
    __syncthreads();
    if (tid == 0) {
        float t = 0.0f;
        #pragma unroll
        for (int i = 0; i < 8; i++) t += rs[i];
        g_esum = t;
    }
}

__global__ void k_mask(const float* __restrict__ alpha) {
    int e = blockIdx.x * 256 + threadIdx.x;
    float en = g_energy[e], es = g_esum;
    unsigned char mb = 0;
    #pragma unroll
    for (int k = 0; k < NB; k++) {
        float al = alpha[k];
        float factor = (2.0f * (k + 1) - 1.0f) / (2.0f * NB);
        float Q = al * factor * es;
        float bnd = es / (al * (2.0f * NB));
        if (en >= Q - bnd && en <= Q + bnd) mb |= (1 << k);
    }
    g_maskb[e] = mb;
}

__global__ void k_initacc(const float* __restrict__ boundary) {
    const float4* s = (const float4*)boundary;
    float4* d = (float4*)g_acc;
    int n4 = NNODE * DEMB / 4;
    for (int i = blockIdx.x * blockDim.x + threadIdx.x; i < n4; i += gridDim.x * blockDim.x)
        d[i] = s[i];
}

// ---------------- main edge kernel (HMMA) ----------------
// dynamic smem:
//   Xhi [128][200] @0       (51200 B)
//   Xlo [128][200] @51200   (51200 B)
//   actHi[128][136] @102400 (34816 B)   (aliased by s_res fp32 [128][132])
//   actLo[128][136] @137216 (34816 B)
//   staging [2][128][40]    @172032 (20480 B)
#define OFF_XLO   51200
#define OFF_ACTH  102400
#define OFF_ACTL  137216
#define OFF_STG   172032
#define DYN_EDGE  192512

__global__ void __launch_bounds__(256, 1)
k_edge_mma(const float* __restrict__ hidden, const float* __restrict__ ea,
           const float* __restrict__ ete, const int* __restrict__ ei,
           const float* __restrict__ rb1, const float* __restrict__ ib1) {
    extern __shared__ char sb[];
    __half* s_xh = (__half*)sb;
    __half* s_xl = (__half*)(sb + OFF_XLO);
    __half* s_ah = (__half*)(sb + OFF_ACTH);
    __half* s_al = (__half*)(sb + OFF_ACTL);
    float*  s_res = (float*)(sb + OFF_ACTH);     // [128][132]
    uint32_t dynb = smem_u32(sb);

    __shared__ int s_src[TE], s_dst[TE];
    __shared__ unsigned char s_mk[TE];
    __shared__ int s_any[NB];
    __shared__ float s_bias[256], s_base[128];

    int tid = threadIdx.x, lane = tid & 31, wid = tid >> 5;
    int eb = blockIdx.x * TE;

    if (tid < TE) {
        s_src[tid] = ei[eb + tid];
        s_dst[tid] = ei[NEDGE + eb + tid];
        s_mk[tid]  = g_maskb[eb + tid];
    }
    __syncthreads();
    if (tid < NB) {
        int a = 0;
        for (int e = 0; e < TE; e++) a |= (s_mk[e] >> tid) & 1;
        s_any[tid] = a;
    }
    __syncthreads();
    if (tid < 128) {
        float b = g_cvec[tid];
        #pragma unroll
        for (int k = 0; k < NB; k++) if (!s_any[k]) b += g_dvec[k * 128 + tid];
        s_base[tid] = b;
    }
    bool anyband = s_any[0] || s_any[1] || s_any[2];

    // fragment lane geometry
    int m0 = (wid & 3) * 32, n0 = (wid >> 2) * 64;
    int rowA = ((lane >> 3) & 1) * 8 + (lane & 7);
    int colA = ((lane >> 4) & 1) * 8;
    int rowB = ((lane >> 4) & 1) * 8 + (lane & 7);
    int colB = ((lane >> 3) & 1) * 8;
    int n_st = tid >> 1;
    int p0b  = (tid & 1) * 32;     // byte offset within 64B staging row

    float acc2[2][8][4];
    #pragma unroll
    for (int i = 0; i < 2; i++)
        #pragma unroll
        for (int j = 0; j < 8; j++)
            #pragma unroll
            for (int q = 0; q < 4; q++) acc2[i][j][q] = 0.0f;

    if (anyband) {
        // ---- gather X tile, convert to f16 hi/lo ----
        for (int idx = tid; idx < TE * 48; idx += 256) {
            int r = idx / 48, q = idx - r * 48;
            float4 v;
            if (q < 32)      v = ((const float4*)(hidden + (size_t)s_src[r] * DEMB))[q];
            else if (q < 40) v = ((const float4*)(ea + (size_t)(eb + r) * 32))[q - 32];
            else             v = ((const float4*)(ete + (size_t)(eb + r) * 32))[q - 40];
            int j0 = q * 4;
            __half h0, l0, h1, l1, h2, l2, h3, l3;
            splith(v.x, h0, l0); splith(v.y, h1, l1); splith(v.z, h2, l2); splith(v.w, h3, l3);
            __half2* ph = (__half2*)(s_xh + r * 200 + j0);
            __half2* pl = (__half2*)(s_xl + r * 200 + j0);
            ph[0] = __halves2half2(h0, h1); ph[1] = __halves2half2(h2, h3);
            pl[0] = __halves2half2(l0, l1); pl[1] = __halves2half2(l2, l3);
        }

        for (int band = 0; band < NB; band++) {
            if (!s_any[band]) continue;
            if (tid < 128) s_bias[tid] = rb1[band * 128 + tid];
            else           s_bias[tid] = ib1[band * 128 + (tid - 128)];

            #pragma unroll 1
            for (int hh = 0; hh < 2; hh++) {
                float acc1[2][8][4];
                #pragma unroll
                for (int i = 0; i < 2; i++)
                    #pragma unroll
                    for (int j = 0; j < 8; j++)
                        #pragma unroll
                        for (int q = 0; q < 4; q++) acc1[i][j][q] = 0.0f;

                const __half* g1h = g_B1h + ((size_t)band * 256 + hh * 128) * 192;
                const __half* g1l = g_B1l + ((size_t)band * 256 + hh * 128) * 192;

                // ---- GEMM1: K' = 3 x 192 = 18 chunks ----
                uint4 pr0, pr1;
                {
                    const uint4* s = (const uint4*)((const char*)(g1h + n_st * 192) + p0b);
                    pr0 = s[0]; pr1 = s[1];
                }
                #pragma unroll 1
                for (int c = 0; c < 18; c++) {
                    uint4* dp = (uint4*)(sb + OFF_STG + (c & 1) * 10240 + n_st * 80 + p0b);
                    dp[0] = pr0; dp[1] = pr1;
                    __syncthreads();
                    if (c + 1 < 18) {
                        int t2 = (c + 1) / 6, kk2 = ((c + 1) % 6) * 32;
                        const __half* g = (t2 == 1) ? g1l : g1h;
                        const uint4* s = (const uint4*)((const char*)(g + n_st * 192 + kk2) + p0b);
                        pr0 = s[0]; pr1 = s[1];
                    }
                    int t = c / 6, kk = (c % 6) * 32;
                    uint32_t aAddr = dynb + ((t == 2) ? OFF_XLO : 0u)
                                   + (uint32_t)((m0 + rowA) * 400 + (kk + colA) * 2);
                    uint32_t bAddr = dynb + OFF_STG + (c & 1) * 10240
                                   + (uint32_t)((n0 + rowB) * 80 + colB * 2);
                    chunk_mma(acc1, aAddr, 400u, bAddr);
                }

                // ---- activation -> act hi/lo ----
                #pragma unroll
                for (int mt = 0; mt < 2; mt++) {
                    int r0 = m0 + mt * 16 + (lane >> 2);
                    float mk0 = (float)((s_mk[r0] >> band) & 1);
                    float mk1 = (float)((s_mk[r0 + 8] >> band) & 1);
                    #pragma unroll
                    for (int nt = 0; nt < 8; nt++) {
                        int cb = n0 + nt * 8 + (lane & 3) * 2;
                        float b0 = s_bias[hh * 128 + cb], b1 = s_bias[hh * 128 + cb + 1];
                        float a00 = fmaxf(fmaf(mk0, acc1[mt][nt][0], b0) - LAM, 0.0f);
                        float a01 = fmaxf(fmaf(mk0, acc1[mt][nt][1], b1) - LAM, 0.0f);
                        float a10 = fmaxf(fmaf(mk1, acc1[mt][nt][2], b0) - LAM, 0.0f);
                        float a11 = fmaxf(fmaf(mk1, acc1[mt][nt][3], b1) - LAM, 0.0f);
                        __half h0, l0, h1, l1;
                        splith(a00, h0, l0); splith(a01, h1, l1);
                        *(__half2*)(s_ah + r0 * 136 + cb) = __halves2half2(h0, h1);
                        *(__half2*)(s_al + r0 * 136 + cb) = __halves2half2(l0, l1);
                        splith(a10, h0, l0); splith(a11, h1, l1);
                        *(__half2*)(s_ah + (r0 + 8) * 136 + cb) = __halves2half2(h0, h1);
                        *(__half2*)(s_al + (r0 + 8) * 136 + cb) = __halves2half2(l0, l1);
                    }
                }

                // ---- GEMM2: K' = 3 x 128 = 12 chunks ----
                const __half* g2h = g_B2h + (size_t)band * 128 * 256 + hh * 128;
                const __half* g2l = g_B2l + (size_t)band * 128 * 256 + hh * 128;
                {
                    const uint4* s = (const uint4*)((const char*)(g2h + n_st * 256) + p0b);
                    pr0 = s[0]; pr1 = s[1];
                }
                #pragma unroll 1
                for (int c = 0; c < 12; c++) {
                    uint4* dp = (uint4*)(sb + OFF_STG + (c & 1) * 10240 + n_st * 80 + p0b);
                    dp[0] = pr0; dp[1] = pr1;
                    __syncthreads();
                    if (c + 1 < 12) {
                        int t2 = (c + 1) / 4, kk2 = ((c + 1) % 4) * 32;
                        const __half* g = (t2 == 1) ? g2l : g2h;
                        const uint4* s = (const uint4*)((const char*)(g + n_st * 256 + kk2) + p0b);
                        pr0 = s[0]; pr1 = s[1];
                    }
                    int t = c / 4, kk = (c % 4) * 32;
                    uint32_t aAddr = dynb + ((t == 2) ? OFF_ACTL : OFF_ACTH)
                                   + (uint32_t)((m0 + rowA) * 272 + (kk + colA) * 2);
                    uint32_t bAddr = dynb + OFF_STG + (c & 1) * 10240
                                   + (uint32_t)((n0 + rowB) * 80 + colB * 2);
                    chunk_mma(acc2, aAddr, 272u, bAddr);
                }
            }
        }
    }

    // ---- stage msg2 into smem (aliased with act) and scatter ----
    __syncthreads();
    if (anyband) {
        #pragma unroll
        for (int mt = 0; mt < 2; mt++) {
            int r0 = m0 + mt * 16 + (lane >> 2);
            #pragma unroll
            for (int nt = 0; nt < 8; nt++) {
                int cb = n0 + nt * 8 + (lane & 3) * 2;
                *(float2*)(s_res + r0 * 132 + cb)       = make_float2(acc2[mt][nt][0], acc2[mt][nt][1]);
                *(float2*)(s_res + (r0 + 8) * 132 + cb) = make_float2(acc2[mt][nt][2], acc2[mt][nt][3]);
            }
        }
    }
    __syncthreads();
    {
        int row = tid >> 1, cb = (tid & 1) * 64;
        int dst = s_dst[row];
        float* p = g_acc + (size_t)dst * DEMB + cb;
        #pragma unroll
        for (int j = 0; j < 16; j++) {
            int c = cb + 4 * j;
            float x0 = s_base[c], x1 = s_base[c + 1], x2 = s_base[c + 2], x3 = s_base[c + 3];
            if (anyband) {
                x0 += s_res[row * 132 + c];     x1 += s_res[row * 132 + c + 1];
                x2 += s_res[row * 132 + c + 2]; x3 += s_res[row * 132 + c + 3];
            }
            asm volatile("red.global.add.v4.f32 [%0], {%1,%2,%3,%4};"
                         :: "l"(p + 4 * j), "f"(x0), "f"(x1), "f"(x2), "f"(x3) : "memory");
        }
    }
}

// ---------------- node epilogue ----------------
#define SMEM_FINAL ((128 * 128 + 16 * 128) * 4)

__global__ void __launch_bounds__(256, 1)
k_final(const float* __restrict__ lin_w, const float* __restrict__ lin_b,
        const float* __restrict__ ln_g, const float* __restrict__ ln_b,
        float* __restrict__ out) {
    extern __shared__ float sm[];
    float* lw = sm;
    float* at = sm + 128 * 128;
    int tid = threadIdx.x;
    int n0 = blockIdx.x * 16;

    for (int idx = tid; idx < 128 * 128; idx += 256) lw[idx] = lin_w[idx];
    for (int idx = tid; idx < 16 * 128; idx += 256)  at[idx] = g_acc[(size_t)n0 * DEMB + idx];
    __syncthreads();

    int i = tid >> 4;
    int m0 = (tid & 15) * 8;
    float t[8];
    #pragma unroll
    for (int j = 0; j < 8; j++) t[j] = lin_b[m0 + j];
    const float* ar = at + i * 128;
    for (int q = 0; q < 128; q++) {
        float av = ar[q];
        float4 w1 = *(const float4*)&lw[q * 128 + m0];
        float4 w2 = *(const float4*)&lw[q * 128 + m0 + 4];
        t[0] = fmaf(av, w1.x, t[0]); t[1] = fmaf(av, w1.y, t[1]);
        t[2] = fmaf(av, w1.z, t[2]); t[3] = fmaf(av, w1.w, t[3]);
        t[4] = fmaf(av, w2.x, t[4]); t[5] = fmaf(av, w2.y, t[5]);
        t[6] = fmaf(av, w2.z, t[6]); t[7] = fmaf(av, w2.w, t[7]);
    }
    float s1 = 0.0f;
    #pragma unroll
    for (int j = 0; j < 8; j++) s1 += t[j];
    #pragma unroll
    for (int off = 8; off; off >>= 1) s1 += __shfl_xor_sync(0xffffffffu, s1, off, 16);
    float mu = s1 * (1.0f / 128.0f);
    float s2 = 0.0f;
    #pragma unroll
    for (int j = 0; j < 8; j++) { float d = t[j] - mu; s2 += d * d; }
    #pragma unroll
    for (int off = 8; off; off >>= 1) s2 += __shfl_xor_sync(0xffffffffu, s2, off, 16);
    float inv = rsqrtf(s2 * (1.0f / 128.0f) + LNEPS);
    #pragma unroll
    for (int j = 0; j < 8; j++) {
        int m = m0 + j;
        float y = (t[j] - mu) * inv * ln_g[m] + ln_b[m];
        out[(size_t)(n0 + i) * DEMB + m] = fmaxf(y, 0.0f);
    }
}

// ---------------- launcher ----------------
extern "C" void kernel_launch(void* const* d_in, const int* in_sizes, int n_in,
                              void* d_out, int out_size) {
    const float* hidden   = (const float*)d_in[0];
    const float* edge_attr= (const float*)d_in[1];
    const float* ete      = (const float*)d_in[2];
    const float* boundary = (const float*)d_in[3];
    const float* alpha    = (const float*)d_in[4];
    const float* r1       = (const float*)d_in[5];
    const float* i1       = (const float*)d_in[6];
    const float* rb1      = (const float*)d_in[7];
    const float* ib1      = (const float*)d_in[8];
    const float* fre_w    = (const float*)d_in[9];
    const float* fre_b    = (const float*)d_in[10];
    const float* comb_w   = (const float*)d_in[11];
    const float* comb_b   = (const float*)d_in[12];
    const float* lin_w    = (const float*)d_in[13];
    const float* lin_b    = (const float*)d_in[14];
    const float* ln_g     = (const float*)d_in[15];
    const float* ln_b     = (const float*)d_in[16];
    const int*   ei       = (const int*)d_in[17];
    float* out = (float*)d_out;

    cudaFuncSetAttribute(k_edge_mma, cudaFuncAttributeMaxDynamicSharedMemorySize, DYN_EDGE);
    cudaFuncSetAttribute(k_final,    cudaFuncAttributeMaxDynamicSharedMemorySize, SMEM_FINAL);

    k_tables<<<1, 384>>>();
    k_buildA<<<768, 192>>>(r1, i1);
    k_buildWrWi<<<384, 128>>>(fre_w);
    k_buildW<<<768, 128>>>(comb_w);
    k_buildCD<<<1, 128>>>(fre_b, comb_w, comb_b, rb1, ib1);
    k_packB1<<<576, 256>>>();
    k_packB2<<<384, 256>>>();
    k_nodenorm<<<NNODE / 8, 256>>>(hidden);
    k_energy<<<NEDGE / 8, 256>>>(edge_attr, ete, ei);
    k_reduce_esum<<<1, 256>>>();
    k_mask<<<NEDGE / 256, 256>>>(alpha);
    k_initacc<<<3125, 256>>>(boundary);
    k_edge_mma<<<NT, 256, DYN_EDGE>>>(hidden, edge_attr, ete, ei, rb1, ib1);
    k_final<<<NNODE / 16, 256, SMEM_FINAL>>>(lin_w, lin_b, ln_g, ln_b, out);
}

// round 5
// speedup vs baseline: 4.4381x; 1.0962x over previous
#include <cuda_runtime.h>
#include <cuda_fp16.h>
#include <math.h>
#include <stdint.h>

// Problem constants
#define NNODE 50000
#define NEDGE 320000
#define DEMB  128
#define DIN   192
#define NB    3
#define LAM   0.01f
#define LNEPS 1e-5f

#define TE    128
#define NT    (NEDGE / TE)        // 2500

// ---------------- device scratch ----------------
__device__ float g_ct192[192], g_st192[192];
__device__ float g_ct384[384], g_st384[384];
__device__ float g_A[DIN * 768];
__device__ float g_Wr[384 * 128];
__device__ float g_Wi[384 * 128];
__device__ float g_W[768 * 128];
__device__ float g_cvec[128];
__device__ float g_dvec[NB * 128];
__device__ float g_nodenorm[NNODE];
__device__ float g_energy[NEDGE];
__device__ float g_esum_part[256];
__device__ float g_esum;
__device__ unsigned char g_maskb[NEDGE];
__device__ float g_acc[NNODE * DEMB];

// fp16 hi/lo transposed operands: B1[band][n(256)][k(192)], B2[band][n(128)][k(256)]
__device__ __align__(16) __half g_B1h[NB * 256 * 192], g_B1l[NB * 256 * 192];
__device__ __align__(16) __half g_B2h[NB * 128 * 256], g_B2l[NB * 128 * 256];

// ---------------- helpers ----------------
__device__ __forceinline__ uint32_t smem_u32(const void* p) {
    uint32_t a;
    asm("{ .reg .u64 t; cvta.to.shared.u64 t, %1; cvt.u32.u64 %0, t; }" : "=r"(a) : "l"(p));
    return a;
}
__device__ __forceinline__ void splith(float v, __half& h, __half& l) {
    h = __float2half_rn(v);
    l = __float2half_rn(v - __half2float(h));
}

#define LDSM4(R, addr) \
    asm volatile("ldmatrix.sync.aligned.m8n8.x4.shared.b16 {%0,%1,%2,%3}, [%4];" \
        : "=r"((R)[0]), "=r"((R)[1]), "=r"((R)[2]), "=r"((R)[3]) : "r"(addr))

#define MMA16816(C, A, B0, B1) \
    asm volatile("mma.sync.aligned.m16n8k16.row.col.f32.f16.f16.f32 " \
        "{%0,%1,%2,%3}, {%4,%5,%6,%7}, {%8,%9}, {%0,%1,%2,%3};" \
        : "+f"((C)[0]), "+f"((C)[1]), "+f"((C)[2]), "+f"((C)[3]) \
        : "r"((A)[0]), "r"((A)[1]), "r"((A)[2]), "r"((A)[3]), "r"(B0), "r"(B1))

#define CP_COMMIT() asm volatile("cp.async.commit_group;" ::: "memory")
#define CP_WAIT0()  asm volatile("cp.async.wait_group 0;" ::: "memory")

// stage one 32-K chunk's hi+lo B slices (16KB total across 256 threads)
__device__ __forceinline__ void stage_chunk(uint32_t dstH, const __half* srcH, const __half* srcL) {
    asm volatile(
        "cp.async.cg.shared.global [%0], [%2], 16;\n\t"
        "cp.async.cg.shared.global [%1], [%3], 16;\n\t"
        :: "r"(dstH), "r"(dstH + 16), "l"(srcH), "l"(srcH + 8) : "memory");
    asm volatile(
        "cp.async.cg.shared.global [%0], [%2], 16;\n\t"
        "cp.async.cg.shared.global [%1], [%3], 16;\n\t"
        :: "r"(dstH + 10240), "r"(dstH + 10240 + 16), "l"(srcL), "l"(srcL + 8) : "memory");
}

// one K=32 chunk, 3-term split: Ahi*Bhi + Alo*Bhi + Ahi*Blo
__device__ __forceinline__ void chunk3(float (&acc)[2][8][4],
                                       uint32_t xhAddr, uint32_t xlAddr, uint32_t aStride,
                                       uint32_t bhAddr) {
    #pragma unroll
    for (int k16 = 0; k16 < 32; k16 += 16) {
        uint32_t ah0[4], ah1[4], al0[4], al1[4], b[4][4];
        LDSM4(ah0, xhAddr + k16 * 2);
        LDSM4(ah1, xhAddr + 16 * aStride + k16 * 2);
        LDSM4(al0, xlAddr + k16 * 2);
        LDSM4(al1, xlAddr + 16 * aStride + k16 * 2);
        #pragma unroll
        for (int ntp = 0; ntp < 4; ntp++) LDSM4(b[ntp], bhAddr + ntp * 16 * 80 + k16 * 2);
        #pragma unroll
        for (int ntp = 0; ntp < 4; ntp++) {
            MMA16816(acc[0][2 * ntp],     ah0, b[ntp][0], b[ntp][1]);
            MMA16816(acc[0][2 * ntp + 1], ah0, b[ntp][2], b[ntp][3]);
            MMA16816(acc[1][2 * ntp],     ah1, b[ntp][0], b[ntp][1]);
            MMA16816(acc[1][2 * ntp + 1], ah1, b[ntp][2], b[ntp][3]);
        }
        #pragma unroll
        for (int ntp = 0; ntp < 4; ntp++) {
            MMA16816(acc[0][2 * ntp],     al0, b[ntp][0], b[ntp][1]);
            MMA16816(acc[0][2 * ntp + 1], al0, b[ntp][2], b[ntp][3]);
            MMA16816(acc[1][2 * ntp],     al1, b[ntp][0], b[ntp][1]);
            MMA16816(acc[1][2 * ntp + 1], al1, b[ntp][2], b[ntp][3]);
        }
        #pragma unroll
        for (int ntp = 0; ntp < 4; ntp++) LDSM4(b[ntp], bhAddr + 10240 + ntp * 16 * 80 + k16 * 2);
        #pragma unroll
        for (int ntp = 0; ntp < 4; ntp++) {
            MMA16816(acc[0][2 * ntp],     ah0, b[ntp][0], b[ntp][1]);
            MMA16816(acc[0][2 * ntp + 1], ah0, b[ntp][2], b[ntp][3]);
            MMA16816(acc[1][2 * ntp],     ah1, b[ntp][0], b[ntp][1]);
            MMA16816(acc[1][2 * ntp + 1], ah1, b[ntp][2], b[ntp][3]);
        }
    }
}

// ---------------- precompute (proven) ----------------
__global__ void k_tables() {
    int t = threadIdx.x;
    if (t < 192) { g_ct192[t] = (float)cospi(2.0 * t / 192.0); g_st192[t] = (float)sinpi(2.0 * t / 192.0); }
    if (t < 384) { g_ct384[t] = (float)cospi(2.0 * t / 384.0); g_st384[t] = (float)sinpi(2.0 * t / 384.0); }
    if (t < 256) g_esum_part[t] = 0.0f;
    if (t == 0) g_esum = 0.0f;
}

__global__ void k_buildA(const float* __restrict__ r1, const float* __restrict__ i1) {
    __shared__ float ct[192], st[192];
    int n = threadIdx.x, c = blockIdx.x;
    ct[n] = g_ct192[n]; st[n] = g_st192[n];
    __syncthreads();
    int k = c >> 8, cc = c & 255;
    const float* R = r1 + k * DIN * DEMB;
    const float* I = i1 + k * DIN * DEMB;
    float s = 0.0f;
    if (cc < 128) {
        int m = cc;
        for (int j = 0; j < 192; j++) { int t = (j * n) % 192; s += ct[t] * R[j * DEMB + m] + st[t] * I[j * DEMB + m]; }
    } else {
        int m = cc - 128;
        for (int j = 0; j < 192; j++) { int t = (j * n) % 192; s += ct[t] * I[j * DEMB + m] - st[t] * R[j * DEMB + m]; }
    }
    g_A[n * 768 + c] = s;
}

__global__ void k_buildWrWi(const float* __restrict__ fre_w) {
    __shared__ float ct[384], st[384];
    int p = threadIdx.x, j = blockIdx.x;
    for (int t = p; t < 384; t += 128) { ct[t] = g_ct384[t]; st[t] = g_st384[t]; }
    __syncthreads();
    float sr = 0.0f, si = 0.0f;
    for (int n = 0; n < 384; n++) {
        int t = (j * n) % 384;
        float w = fre_w[n * 128 + p];
        sr += ct[t] * w; si -= st[t] * w;
    }
    g_Wr[j * 128 + p] = sr * (1.0f / 384.0f);
    g_Wi[j * 128 + p] = si * (1.0f / 384.0f);
}

__global__ void k_buildW(const float* __restrict__ comb_w) {
    int m = threadIdx.x, r = blockIdx.x;
    int k = r >> 8, cc = r & 255;
    int j = k * 128 + (cc & 127);
    const float* src = (cc < 128) ? g_Wr : g_Wi;
    float s = 0.0f;
    for (int p = 0; p < 128; p++) s += src[j * 128 + p] * comb_w[(2 * p) * 128 + m];
    g_W[r * 128 + m] = s;
}

__global__ void k_buildCD(const float* __restrict__ fre_b, const float* __restrict__ comb_w,
                          const float* __restrict__ comb_b,
                          const float* __restrict__ rb1, const float* __restrict__ ib1) {
    int m = threadIdx.x;
    float s = 0.0f;
    for (int p = 0; p < 128; p++) s += fre_b[p] * comb_w[(2 * p) * 128 + m];
    g_cvec[m] = s + comb_b[m];
    for (int k = 0; k < NB; k++) {
        float d = 0.0f;
        for (int j0 = 0; j0 < 128; j0++) {
            float ar = fmaxf(rb1[k * 128 + j0] - LAM, 0.0f);
            float ai = fmaxf(ib1[k * 128 + j0] - LAM, 0.0f);
            d += ar * g_W[(k * 256 + j0) * 128 + m] + ai * g_W[(k * 256 + 128 + j0) * 128 + m];
        }
        g_dvec[k * 128 + m] = d;
    }
}

__global__ void k_packB1() {
    int idx = blockIdx.x * 256 + threadIdx.x;
    int band = idx / 49152, r = idx % 49152;
    int n = r / 192, j = r % 192;
    float v = g_A[j * 768 + band * 256 + n];
    __half h, l; splith(v, h, l);
    g_B1h[idx] = h; g_B1l[idx] = l;
}
__global__ void k_packB2() {
    int idx = blockIdx.x * 256 + threadIdx.x;
    int band = idx / 32768, r = idx % 32768;
    int m = r / 256, c = r % 256;
    float v = g_W[(band * 256 + c) * 128 + m];
    __half h, l; splith(v, h, l);
    g_B2h[idx] = h; g_B2l[idx] = l;
}

// ---------------- energy / mask / init ----------------
__global__ void k_nodenorm(const float* __restrict__ hidden) {
    int tid = threadIdx.x, w = tid >> 5, lane = tid & 31;
    int n = blockIdx.x * 8 + w;
    const float* h = hidden + (size_t)n * DEMB;
    float s = 0.0f;
    #pragma unroll
    for (int i = 0; i < 4; i++) { float v = h[lane + 32 * i]; s += v * v; }
    #pragma unroll
    for (int off = 16; off; off >>= 1) s += __shfl_xor_sync(0xffffffffu, s, off);
    if (lane == 0) g_nodenorm[n] = s;
}

__global__ void k_energy(const float* __restrict__ ea, const float* __restrict__ ete,
                         const int* __restrict__ ei) {
    __shared__ float wsum[8];
    int tid = threadIdx.x, w = tid >> 5, lane = tid & 31;
    int e = blockIdx.x * 8 + w;
    float a = ea[(size_t)e * 32 + lane];
    float b = ete[(size_t)e * 32 + lane];
    float s = a * a + b * b;
    #pragma unroll
    for (int off = 16; off; off >>= 1) s += __shfl_xor_sync(0xffffffffu, s, off);
    if (lane == 0) { float en = 192.0f * (g_nodenorm[ei[e]] + s); g_energy[e] = en; wsum[w] = en; }
    __syncthreads();
    if (tid == 0) {
        float t = 0.0f;
        #pragma unroll
        for (int i = 0; i < 8; i++) t += wsum[i];
        atomicAdd(&g_esum_part[blockIdx.x & 255], t);
    }
}

__global__ void k_reduce_esum() {
    __shared__ float rs[8];
    int tid = threadIdx.x;
    float v = g_esum_part[tid];
    #pragma unroll
    for (int off = 16; off; off >>= 1) v += __shfl_xor_sync(0xffffffffu, v, off);
    if ((tid & 31) == 0) rs[tid >> 5] = v;
    __syncthreads();
    if (tid == 0) {
        float t = 0.0f;
        #pragma unroll
        for (int i = 0; i < 8; i++) t += rs[i];
        g_esum = t;
    }
}

__global__ void k_mask(const float* __restrict__ alpha) {
    int e = blockIdx.x * 256 + threadIdx.x;
    float en = g_energy[e], es = g_esum;
    unsigned char mb = 0;
    #pragma unroll
    for (int k = 0; k < NB; k++) {
        float al = alpha[k];
        float factor = (2.0f * (k + 1) - 1.0f) / (2.0f * NB);
        float Q = al * factor * es;
        float bnd = es / (al * (2.0f * NB));
        if (en >= Q - bnd && en <= Q + bnd) mb |= (1 << k);
    }
    g_maskb[e] = mb;
}

__global__ void k_initacc(const float* __restrict__ boundary) {
    const float4* s = (const float4*)boundary;
    float4* d = (float4*)g_acc;
    int n4 = NNODE * DEMB / 4;
    for (int i = blockIdx.x * blockDim.x + threadIdx.x; i < n4; i += gridDim.x * blockDim.x)
        d[i] = s[i];
}

// ---------------- main edge kernel (HMMA, cp.async pipelined) ----------------
// dynamic smem:
//   Xhi [128][200] @0       (51200)
//   Xlo [128][200] @51200   (51200)
//   actHi[128][136] @102400 (34816)   (aliased by s_res fp32 [128][132])
//   actLo[128][136] @137216 (34816)
//   staging [2 buf][2 hl][128][40] @172032 (40960)
#define OFF_XLO   51200
#define OFF_ACTH  102400
#define OFF_ACTL  137216
#define OFF_STG   172032
#define DYN_EDGE  212992

__global__ void __launch_bounds__(256, 1)
k_edge_mma(const float* __restrict__ hidden, const float* __restrict__ ea,
           const float* __restrict__ ete, const int* __restrict__ ei,
           const float* __restrict__ rb1, const float* __restrict__ ib1) {
    extern __shared__ char sb[];
    __half* s_xh = (__half*)sb;
    __half* s_xl = (__half*)(sb + OFF_XLO);
    __half* s_ah = (__half*)(sb + OFF_ACTH);
    __half* s_al = (__half*)(sb + OFF_ACTL);
    float*  s_res = (float*)(sb + OFF_ACTH);     // [128][132]
    uint32_t dynb = smem_u32(sb);

    __shared__ int s_src[TE], s_dst[TE];
    __shared__ unsigned char s_mk[TE];
    __shared__ int s_any[NB];
    __shared__ float s_bias[256], s_base[128];

    int tid = threadIdx.x, lane = tid & 31, wid = tid >> 5;
    int eb = blockIdx.x * TE;

    if (tid < TE) {
        s_src[tid] = ei[eb + tid];
        s_dst[tid] = ei[NEDGE + eb + tid];
        s_mk[tid]  = g_maskb[eb + tid];
    }
    __syncthreads();
    if (tid < NB) {
        int a = 0;
        for (int e = 0; e < TE; e++) a |= (s_mk[e] >> tid) & 1;
        s_any[tid] = a;
    }
    __syncthreads();
    if (tid < 128) {
        float b = g_cvec[tid];
        #pragma unroll
        for (int k = 0; k < NB; k++) if (!s_any[k]) b += g_dvec[k * 128 + tid];
        s_base[tid] = b;
    }
    bool anyband = s_any[0] || s_any[1] || s_any[2];

    // fragment geometry
    int m0 = (wid & 3) * 32, n0 = (wid >> 2) * 64;
    int rowA = ((lane >> 3) & 1) * 8 + (lane & 7);
    int colA = ((lane >> 4) & 1) * 8;
    int rowB = ((lane >> 4) & 1) * 8 + (lane & 7);
    int colB = ((lane >> 3) & 1) * 8;
    int n_st = tid >> 1;
    int p0h  = (tid & 1) * 16;     // half offset within 32-half chunk row
    uint32_t stgDst = dynb + OFF_STG + (uint32_t)(n_st * 80 + (tid & 1) * 32);

    float acc2[2][8][4];
    #pragma unroll
    for (int i = 0; i < 2; i++)
        #pragma unroll
        for (int j = 0; j < 8; j++)
            #pragma unroll
            for (int q = 0; q < 4; q++) acc2[i][j][q] = 0.0f;

    if (anyband) {
        // ---- gather X tile, convert to f16 hi/lo ----
        for (int idx = tid; idx < TE * 48; idx += 256) {
            int r = idx / 48, q = idx - r * 48;
            float4 v;
            if (q < 32)      v = ((const float4*)(hidden + (size_t)s_src[r] * DEMB))[q];
            else if (q < 40) v = ((const float4*)(ea + (size_t)(eb + r) * 32))[q - 32];
            else             v = ((const float4*)(ete + (size_t)(eb + r) * 32))[q - 40];
            int j0 = q * 4;
            __half h0, l0, h1, l1, h2, l2, h3, l3;
            splith(v.x, h0, l0); splith(v.y, h1, l1); splith(v.z, h2, l2); splith(v.w, h3, l3);
            __half2* ph = (__half2*)(s_xh + r * 200 + j0);
            __half2* pl = (__half2*)(s_xl + r * 200 + j0);
            ph[0] = __halves2half2(h0, h1); ph[1] = __halves2half2(h2, h3);
            pl[0] = __halves2half2(l0, l1); pl[1] = __halves2half2(l2, l3);
        }

        // segment list: (band,hh) pairs
        int segBand[NB]; int nseg = 0;
        #pragma unroll
        for (int k = 0; k < NB; k++) if (s_any[k]) segBand[nseg++] = k;
        int totseg = nseg * 2;

        // prefetch segment 0 GEMM1 chunk 0 into buf0
        {
            int b0 = segBand[0];
            const __half* h = g_B1h + ((size_t)b0 * 256) * 192 + n_st * 192 + p0h;
            const __half* l = g_B1l + ((size_t)b0 * 256) * 192 + n_st * 192 + p0h;
            stage_chunk(stgDst, h, l);
            CP_COMMIT();
        }

        for (int s = 0; s < totseg; s++) {
            int band = segBand[s >> 1], hh = s & 1;
            if (hh == 0) {
                if (tid < 128) s_bias[tid] = rb1[band * 128 + tid];
                else           s_bias[tid] = ib1[band * 128 + (tid - 128)];
            }
            const __half* g1h = g_B1h + ((size_t)band * 256 + hh * 128) * 192 + n_st * 192 + p0h;
            const __half* g1l = g_B1l + ((size_t)band * 256 + hh * 128) * 192 + n_st * 192 + p0h;
            const __half* g2h = g_B2h + (size_t)band * 32768 + hh * 128 + n_st * 256 + p0h;
            const __half* g2l = g_B2l + (size_t)band * 32768 + hh * 128 + n_st * 256 + p0h;

            float acc1[2][8][4];
            #pragma unroll
            for (int i = 0; i < 2; i++)
                #pragma unroll
                for (int j = 0; j < 8; j++)
                    #pragma unroll
                    for (int q = 0; q < 4; q++) acc1[i][j][q] = 0.0f;

            // ---- GEMM1: 6 K-chunks ----
            #pragma unroll 1
            for (int c = 0; c < 6; c++) {
                CP_WAIT0();
                __syncthreads();
                if (c < 5) stage_chunk(stgDst + ((c + 1) & 1) * 20480, g1h + (c + 1) * 32, g1l + (c + 1) * 32);
                else       stage_chunk(stgDst, g2h, g2l);   // GEMM2 chunk 0 -> buf0
                CP_COMMIT();
                uint32_t xh = dynb + (uint32_t)((m0 + rowA) * 400 + (c * 32 + colA) * 2);
                uint32_t bh = dynb + OFF_STG + (c & 1) * 20480 + (uint32_t)((n0 + rowB) * 80 + colB * 2);
                chunk3(acc1, xh, xh + OFF_XLO, 400u, bh);
            }

            // ---- activation -> act hi/lo (overlaps with GEMM2 chunk0 cp.async) ----
            #pragma unroll
            for (int mt = 0; mt < 2; mt++) {
                int r0 = m0 + mt * 16 + (lane >> 2);
                float mk0 = (float)((s_mk[r0] >> band) & 1);
                float mk1 = (float)((s_mk[r0 + 8] >> band) & 1);
                #pragma unroll
                for (int nt = 0; nt < 8; nt++) {
                    int cb = n0 + nt * 8 + (lane & 3) * 2;
                    float b0 = s_bias[hh * 128 + cb], b1 = s_bias[hh * 128 + cb + 1];
                    float a00 = fmaxf(fmaf(mk0, acc1[mt][nt][0], b0) - LAM, 0.0f);
                    float a01 = fmaxf(fmaf(mk0, acc1[mt][nt][1], b1) - LAM, 0.0f);
                    float a10 = fmaxf(fmaf(mk1, acc1[mt][nt][2], b0) - LAM, 0.0f);
                    float a11 = fmaxf(fmaf(mk1, acc1[mt][nt][3], b1) - LAM, 0.0f);
                    __half h0, l0, h1, l1;
                    splith(a00, h0, l0); splith(a01, h1, l1);
                    *(__half2*)(s_ah + r0 * 136 + cb) = __halves2half2(h0, h1);
                    *(__half2*)(s_al + r0 * 136 + cb) = __halves2half2(l0, l1);
                    splith(a10, h0, l0); splith(a11, h1, l1);
                    *(__half2*)(s_ah + (r0 + 8) * 136 + cb) = __halves2half2(h0, h1);
                    *(__half2*)(s_al + (r0 + 8) * 136 + cb) = __halves2half2(l0, l1);
                }
            }

            // ---- GEMM2: 4 K-chunks ----
            #pragma unroll 1
            for (int c = 0; c < 4; c++) {
                CP_WAIT0();
                __syncthreads();          // publishes act + staged chunk
                if (c < 3) stage_chunk(stgDst + ((c + 1) & 1) * 20480, g2h + (c + 1) * 32, g2l + (c + 1) * 32);
                else if (s + 1 < totseg) {
                    int nb = segBand[(s + 1) >> 1], nhh = (s + 1) & 1;
                    const __half* nh = g_B1h + ((size_t)nb * 256 + nhh * 128) * 192 + n_st * 192 + p0h;
                    const __half* nl = g_B1l + ((size_t)nb * 256 + nhh * 128) * 192 + n_st * 192 + p0h;
                    stage_chunk(stgDst, nh, nl);   // next segment GEMM1 chunk0 -> buf0
                }
                CP_COMMIT();
                uint32_t ah = dynb + OFF_ACTH + (uint32_t)((m0 + rowA) * 272 + (c * 32 + colA) * 2);
                uint32_t bh = dynb + OFF_STG + (c & 1) * 20480 + (uint32_t)((n0 + rowB) * 80 + colB * 2);
                chunk3(acc2, ah, ah + (OFF_ACTL - OFF_ACTH), 272u, bh);
            }
        }
    }

    // ---- stage msg2 into smem (aliased with act) and scatter ----
    __syncthreads();
    if (anyband) {
        #pragma unroll
        for (int mt = 0; mt < 2; mt++) {
            int r0 = m0 + mt * 16 + (lane >> 2);
            #pragma unroll
            for (int nt = 0; nt < 8; nt++) {
                int cb = n0 + nt * 8 + (lane & 3) * 2;
                *(float2*)(s_res + r0 * 132 + cb)       = make_float2(acc2[mt][nt][0], acc2[mt][nt][1]);
                *(float2*)(s_res + (r0 + 8) * 132 + cb) = make_float2(acc2[mt][nt][2], acc2[mt][nt][3]);
            }
        }
    }
    __syncthreads();
    {
        int row = tid >> 1, cb = (tid & 1) * 64;
        int dst = s_dst[row];
        float* p = g_acc + (size_t)dst * DEMB + cb;
        #pragma unroll
        for (int j = 0; j < 16; j++) {
            int c = cb + 4 * j;
            float x0 = s_base[c], x1 = s_base[c + 1], x2 = s_base[c + 2], x3 = s_base[c + 3];
            if (anyband) {
                x0 += s_res[row * 132 + c];     x1 += s_res[row * 132 + c + 1];
                x2 += s_res[row * 132 + c + 2]; x3 += s_res[row * 132 + c + 3];
            }
            asm volatile("red.global.add.v4.f32 [%0], {%1,%2,%3,%4};"
                         :: "l"(p + 4 * j), "f"(x0), "f"(x1), "f"(x2), "f"(x3) : "memory");
        }
    }
}

// ---------------- node epilogue (32 nodes/block, guarded tail) ----------------
#define SMEM_FINAL ((128 * 128 + 32 * 128) * 4)

__global__ void __launch_bounds__(256, 1)
k_final(const float* __restrict__ lin_w, const float* __restrict__ lin_b,
        const float* __restrict__ ln_g, const float* __restrict__ ln_b,
        float* __restrict__ out) {
    extern __shared__ float sm[];
    float* lw = sm;
    float* at = sm + 128 * 128;
    int tid = threadIdx.x;
    int n0 = blockIdx.x * 32;
    int nvalid = NNODE - n0; if (nvalid > 32) nvalid = 32;

    for (int idx = tid; idx < 128 * 128; idx += 256) lw[idx] = lin_w[idx];
    for (int idx = tid; idx < nvalid * 128; idx += 256) at[idx] = g_acc[(size_t)n0 * DEMB + idx];
    __syncthreads();

    int m0 = (tid & 15) * 8;
    #pragma unroll 1
    for (int g = 0; g < 2; g++) {
        int i = (tid >> 4) + g * 16;
        if (i >= nvalid) continue;
        float t[8];
        #pragma unroll
        for (int j = 0; j < 8; j++) t[j] = lin_b[m0 + j];
        const float* ar = at + i * 128;
        for (int q = 0; q < 128; q++) {
            float av = ar[q];
            float4 w1 = *(const float4*)&lw[q * 128 + m0];
            float4 w2 = *(const float4*)&lw[q * 128 + m0 + 4];
            t[0] = fmaf(av, w1.x, t[0]); t[1] = fmaf(av, w1.y, t[1]);
            t[2] = fmaf(av, w1.z, t[2]); t[3] = fmaf(av, w1.w, t[3]);
            t[4] = fmaf(av, w2.x, t[4]); t[5] = fmaf(av, w2.y, t[5]);
            t[6] = fmaf(av, w2.z, t[6]); t[7] = fmaf(av, w2.w, t[7]);
        }
        float s1 = 0.0f;
        #pragma unroll
        for (int j = 0; j < 8; j++) s1 += t[j];
        #pragma unroll
        for (int off = 8; off; off >>= 1) s1 += __shfl_xor_sync(0xffffffffu, s1, off, 16);
        float mu = s1 * (1.0f / 128.0f);
        float s2 = 0.0f;
        #pragma unroll
        for (int j = 0; j < 8; j++) { float d = t[j] - mu; s2 += d * d; }
        #pragma unroll
        for (int off = 8; off; off >>= 1) s2 += __shfl_xor_sync(0xffffffffu, s2, off, 16);
        float inv = rsqrtf(s2 * (1.0f / 128.0f) + LNEPS);
        #pragma unroll
        for (int j = 0; j < 8; j++) {
            int m = m0 + j;
            float y = (t[j] - mu) * inv * ln_g[m] + ln_b[m];
            out[(size_t)(n0 + i) * DEMB + m] = fmaxf(y, 0.0f);
        }
    }
}

// ---------------- launcher ----------------
extern "C" void kernel_launch(void* const* d_in, const int* in_sizes, int n_in,
                              void* d_out, int out_size) {
    const float* hidden   = (const float*)d_in[0];
    const float* edge_attr= (const float*)d_in[1];
    const float* ete      = (const float*)d_in[2];
    const float* boundary = (const float*)d_in[3];
    const float* alpha    = (const float*)d_in[4];
    const float* r1       = (const float*)d_in[5];
    const float* i1       = (const float*)d_in[6];
    const float* rb1      = (const float*)d_in[7];
    const float* ib1      = (const float*)d_in[8];
    const float* fre_w    = (const float*)d_in[9];
    const float* fre_b    = (const float*)d_in[10];
    const float* comb_w   = (const float*)d_in[11];
    const float* comb_b   = (const float*)d_in[12];
    const float* lin_w    = (const float*)d_in[13];
    const float* lin_b    = (const float*)d_in[14];
    const float* ln_g     = (const float*)d_in[15];
    const float* ln_b     = (const float*)d_in[16];
    const int*   ei       = (const int*)d_in[17];
    float* out = (float*)d_out;

    cudaFuncSetAttribute(k_edge_mma, cudaFuncAttributeMaxDynamicSharedMemorySize, DYN_EDGE);
    cudaFuncSetAttribute(k_final,    cudaFuncAttributeMaxDynamicSharedMemorySize, SMEM_FINAL);

    k_tables<<<1, 384>>>();
    k_buildA<<<768, 192>>>(r1, i1);
    k_buildWrWi<<<384, 128>>>(fre_w);
    k_buildW<<<768, 128>>>(comb_w);
    k_buildCD<<<1, 128>>>(fre_b, comb_w, comb_b, rb1, ib1);
    k_packB1<<<576, 256>>>();
    k_packB2<<<384, 256>>>();
    k_nodenorm<<<NNODE / 8, 256>>>(hidden);
    k_energy<<<NEDGE / 8, 256>>>(edge_attr, ete, ei);
    k_reduce_esum<<<1, 256>>>();
    k_mask<<<NEDGE / 256, 256>>>(alpha);
    k_initacc<<<3125, 256>>>(boundary);
    k_edge_mma<<<NT, 256, DYN_EDGE>>>(hidden, edge_attr, ete, ei, rb1, ib1);
    k_final<<<(NNODE + 31) / 32, 256, SMEM_FINAL>>>(lin_w, lin_b, ln_g, ln_b, out);
}

// round 6
// speedup vs baseline: 5.4431x; 1.2265x over previous
#include <cuda_runtime.h>
#include <cuda_fp16.h>
#include <math.h>
#include <stdint.h>

// Problem constants
#define NNODE 50000
#define NEDGE 320000
#define DEMB  128
#define DIN   192
#define NB    3
#define LAM   0.01f
#define LNEPS 1e-5f

#define TE    128
#define NT    (NEDGE / TE)        // 2500

// ---------------- device scratch ----------------
__device__ float g_ct192[192], g_st192[192];
__device__ float g_ct384[384], g_st384[384];
__device__ float g_A[DIN * 768];
__device__ float g_Wr[384 * 128];
__device__ float g_Wi[384 * 128];
__device__ float g_W[768 * 128];
__device__ float g_cvec[128];
__device__ float g_dvec[NB * 128];
__device__ float g_nodenorm[NNODE];
__device__ float g_energy[NEDGE];
__device__ float g_esum_part[256];
__device__ float g_esum;
__device__ unsigned char g_maskb[NEDGE];
__device__ float g_acc[NNODE * DEMB];

// fp16 transposed operands (weights rounded to fp16 — hi only):
// B1[band][n(256)][k(192)], B2[band][n(128)][k(256)]
__device__ __align__(16) __half g_B1h[NB * 256 * 192];
__device__ __align__(16) __half g_B2h[NB * 128 * 256];

// ---------------- helpers ----------------
__device__ __forceinline__ uint32_t smem_u32(const void* p) {
    uint32_t a;
    asm("{ .reg .u64 t; cvta.to.shared.u64 t, %1; cvt.u32.u64 %0, t; }" : "=r"(a) : "l"(p));
    return a;
}
__device__ __forceinline__ void splith(float v, __half& h, __half& l) {
    h = __float2half_rn(v);
    l = __float2half_rn(v - __half2float(h));
}

#define LDSM4(R, addr) \
    asm volatile("ldmatrix.sync.aligned.m8n8.x4.shared.b16 {%0,%1,%2,%3}, [%4];" \
        : "=r"((R)[0]), "=r"((R)[1]), "=r"((R)[2]), "=r"((R)[3]) : "r"(addr))

#define MMA16816(C, A, B0, B1) \
    asm volatile("mma.sync.aligned.m16n8k16.row.col.f32.f16.f16.f32 " \
        "{%0,%1,%2,%3}, {%4,%5,%6,%7}, {%8,%9}, {%0,%1,%2,%3};" \
        : "+f"((C)[0]), "+f"((C)[1]), "+f"((C)[2]), "+f"((C)[3]) \
        : "r"((A)[0]), "r"((A)[1]), "r"((A)[2]), "r"((A)[3]), "r"(B0), "r"(B1))

#define CP_COMMIT() asm volatile("cp.async.commit_group;" ::: "memory")
#define CP_WAIT0()  asm volatile("cp.async.wait_group 0;" ::: "memory")

// stage one 32-K chunk's B slice (8KB across 256 threads)
__device__ __forceinline__ void stage_chunk(uint32_t dstH, const __half* srcH) {
    asm volatile(
        "cp.async.cg.shared.global [%0], [%2], 16;\n\t"
        "cp.async.cg.shared.global [%1], [%3], 16;\n\t"
        :: "r"(dstH), "r"(dstH + 16), "l"(srcH), "l"(srcH + 8) : "memory");
}

// one K=32 chunk, 2-term split: Ahi*Bhi + Alo*Bhi  (B pre-rounded to fp16)
__device__ __forceinline__ void chunk2(float (&acc)[2][8][4],
                                       uint32_t xhAddr, uint32_t xlAddr, uint32_t aStride,
                                       uint32_t bhAddr) {
    #pragma unroll
    for (int k16 = 0; k16 < 32; k16 += 16) {
        uint32_t ah0[4], ah1[4], al0[4], al1[4], b[4][4];
        LDSM4(ah0, xhAddr + k16 * 2);
        LDSM4(ah1, xhAddr + 16 * aStride + k16 * 2);
        LDSM4(al0, xlAddr + k16 * 2);
        LDSM4(al1, xlAddr + 16 * aStride + k16 * 2);
        #pragma unroll
        for (int ntp = 0; ntp < 4; ntp++) LDSM4(b[ntp], bhAddr + ntp * 16 * 80 + k16 * 2);
        #pragma unroll
        for (int ntp = 0; ntp < 4; ntp++) {
            MMA16816(acc[0][2 * ntp],     ah0, b[ntp][0], b[ntp][1]);
            MMA16816(acc[0][2 * ntp + 1], ah0, b[ntp][2], b[ntp][3]);
            MMA16816(acc[1][2 * ntp],     ah1, b[ntp][0], b[ntp][1]);
            MMA16816(acc[1][2 * ntp + 1], ah1, b[ntp][2], b[ntp][3]);
        }
        #pragma unroll
        for (int ntp = 0; ntp < 4; ntp++) {
            MMA16816(acc[0][2 * ntp],     al0, b[ntp][0], b[ntp][1]);
            MMA16816(acc[0][2 * ntp + 1], al0, b[ntp][2], b[ntp][3]);
            MMA16816(acc[1][2 * ntp],     al1, b[ntp][0], b[ntp][1]);
            MMA16816(acc[1][2 * ntp + 1], al1, b[ntp][2], b[ntp][3]);
        }
    }
}

// ---------------- precompute (proven) ----------------
__global__ void k_tables() {
    int t = threadIdx.x;
    if (t < 192) { g_ct192[t] = (float)cospi(2.0 * t / 192.0); g_st192[t] = (float)sinpi(2.0 * t / 192.0); }
    if (t < 384) { g_ct384[t] = (float)cospi(2.0 * t / 384.0); g_st384[t] = (float)sinpi(2.0 * t / 384.0); }
    if (t < 256) g_esum_part[t] = 0.0f;
    if (t == 0) g_esum = 0.0f;
}

__global__ void k_buildA(const float* __restrict__ r1, const float* __restrict__ i1) {
    __shared__ float ct[192], st[192];
    int n = threadIdx.x, c = blockIdx.x;
    ct[n] = g_ct192[n]; st[n] = g_st192[n];
    __syncthreads();
    int k = c >> 8, cc = c & 255;
    const float* R = r1 + k * DIN * DEMB;
    const float* I = i1 + k * DIN * DEMB;
    float s = 0.0f;
    if (cc < 128) {
        int m = cc;
        for (int j = 0; j < 192; j++) { int t = (j * n) % 192; s += ct[t] * R[j * DEMB + m] + st[t] * I[j * DEMB + m]; }
    } else {
        int m = cc - 128;
        for (int j = 0; j < 192; j++) { int t = (j * n) % 192; s += ct[t] * I[j * DEMB + m] - st[t] * R[j * DEMB + m]; }
    }
    g_A[n * 768 + c] = s;
}

__global__ void k_buildWrWi(const float* __restrict__ fre_w) {
    __shared__ float ct[384], st[384];
    int p = threadIdx.x, j = blockIdx.x;
    for (int t = p; t < 384; t += 128) { ct[t] = g_ct384[t]; st[t] = g_st384[t]; }
    __syncthreads();
    float sr = 0.0f, si = 0.0f;
    for (int n = 0; n < 384; n++) {
        int t = (j * n) % 384;
        float w = fre_w[n * 128 + p];
        sr += ct[t] * w; si -= st[t] * w;
    }
    g_Wr[j * 128 + p] = sr * (1.0f / 384.0f);
    g_Wi[j * 128 + p] = si * (1.0f / 384.0f);
}

__global__ void k_buildW(const float* __restrict__ comb_w) {
    int m = threadIdx.x, r = blockIdx.x;
    int k = r >> 8, cc = r & 255;
    int j = k * 128 + (cc & 127);
    const float* src = (cc < 128) ? g_Wr : g_Wi;
    float s = 0.0f;
    for (int p = 0; p < 128; p++) s += src[j * 128 + p] * comb_w[(2 * p) * 128 + m];
    g_W[r * 128 + m] = s;
}

__global__ void k_buildCD(const float* __restrict__ fre_b, const float* __restrict__ comb_w,
                          const float* __restrict__ comb_b,
                          const float* __restrict__ rb1, const float* __restrict__ ib1) {
    int m = threadIdx.x;
    float s = 0.0f;
    for (int p = 0; p < 128; p++) s += fre_b[p] * comb_w[(2 * p) * 128 + m];
    g_cvec[m] = s + comb_b[m];
    for (int k = 0; k < NB; k++) {
        float d = 0.0f;
        for (int j0 = 0; j0 < 128; j0++) {
            float ar = fmaxf(rb1[k * 128 + j0] - LAM, 0.0f);
            float ai = fmaxf(ib1[k * 128 + j0] - LAM, 0.0f);
            d += ar * g_W[(k * 256 + j0) * 128 + m] + ai * g_W[(k * 256 + 128 + j0) * 128 + m];
        }
        g_dvec[k * 128 + m] = d;
    }
}

__global__ void k_packB1() {
    int idx = blockIdx.x * 256 + threadIdx.x;
    int band = idx / 49152, r = idx % 49152;
    int n = r / 192, j = r % 192;
    g_B1h[idx] = __float2half_rn(g_A[j * 768 + band * 256 + n]);
}
__global__ void k_packB2() {
    int idx = blockIdx.x * 256 + threadIdx.x;
    int band = idx / 32768, r = idx % 32768;
    int m = r / 256, c = r % 256;
    g_B2h[idx] = __float2half_rn(g_W[(band * 256 + c) * 128 + m]);
}

// ---------------- energy / mask / init ----------------
__global__ void k_nodenorm(const float* __restrict__ hidden) {
    int tid = threadIdx.x, w = tid >> 5, lane = tid & 31;
    int n = blockIdx.x * 8 + w;
    const float* h = hidden + (size_t)n * DEMB;
    float s = 0.0f;
    #pragma unroll
    for (int i = 0; i < 4; i++) { float v = h[lane + 32 * i]; s += v * v; }
    #pragma unroll
    for (int off = 16; off; off >>= 1) s += __shfl_xor_sync(0xffffffffu, s, off);
    if (lane == 0) g_nodenorm[n] = s;
}

__global__ void k_energy(const float* __restrict__ ea, const float* __restrict__ ete,
                         const int* __restrict__ ei) {
    __shared__ float wsum[8];
    int tid = threadIdx.x, w = tid >> 5, lane = tid & 31;
    int e = blockIdx.x * 8 + w;
    float a = ea[(size_t)e * 32 + lane];
    float b = ete[(size_t)e * 32 + lane];
    float s = a * a + b * b;
    #pragma unroll
    for (int off = 16; off; off >>= 1) s += __shfl_xor_sync(0xffffffffu, s, off);
    if (lane == 0) { float en = 192.0f * (g_nodenorm[ei[e]] + s); g_energy[e] = en; wsum[w] = en; }
    __syncthreads();
    if (tid == 0) {
        float t = 0.0f;
        #pragma unroll
        for (int i = 0; i < 8; i++) t += wsum[i];
        atomicAdd(&g_esum_part[blockIdx.x & 255], t);
    }
}

__global__ void k_reduce_esum() {
    __shared__ float rs[8];
    int tid = threadIdx.x;
    float v = g_esum_part[tid];
    #pragma unroll
    for (int off = 16; off; off >>= 1) v += __shfl_xor_sync(0xffffffffu, v, off);
    if ((tid & 31) == 0) rs[tid >> 5] = v;
    __syncthreads();
    if (tid == 0) {
        float t = 0.0f;
        #pragma unroll
        for (int i = 0; i < 8; i++) t += rs[i];
        g_esum = t;
    }
}

__global__ void k_mask(const float* __restrict__ alpha) {
    int e = blockIdx.x * 256 + threadIdx.x;
    float en = g_energy[e], es = g_esum;
    unsigned char mb = 0;
    #pragma unroll
    for (int k = 0; k < NB; k++) {
        float al = alpha[k];
        float factor = (2.0f * (k + 1) - 1.0f) / (2.0f * NB);
        float Q = al * factor * es;
        float bnd = es / (al * (2.0f * NB));
        if (en >= Q - bnd && en <= Q + bnd) mb |= (1 << k);
    }
    g_maskb[e] = mb;
}

__global__ void k_initacc(const float* __restrict__ boundary) {
    const float4* s = (const float4*)boundary;
    float4* d = (float4*)g_acc;
    int n4 = NNODE * DEMB / 4;
    for (int i = blockIdx.x * blockDim.x + threadIdx.x; i < n4; i += gridDim.x * blockDim.x)
        d[i] = s[i];
}

// ---------------- main edge kernel (HMMA, 2-term split, cp.async) ----------------
// dynamic smem:
//   Xhi [128][200] @0       (51200)
//   Xlo [128][200] @51200   (51200)
//   actHi[128][136] @102400 (34816)   (aliased by s_res fp32 [128][132])
//   actLo[128][136] @137216 (34816)
//   staging [2 buf][128][40] @172032  (20480)
#define OFF_XLO   51200
#define OFF_ACTH  102400
#define OFF_ACTL  137216
#define OFF_STG   172032
#define DYN_EDGE  192512

__global__ void __launch_bounds__(256, 1)
k_edge_mma(const float* __restrict__ hidden, const float* __restrict__ ea,
           const float* __restrict__ ete, const int* __restrict__ ei,
           const float* __restrict__ rb1, const float* __restrict__ ib1) {
    extern __shared__ char sb[];
    __half* s_xh = (__half*)sb;
    __half* s_xl = (__half*)(sb + OFF_XLO);
    __half* s_ah = (__half*)(sb + OFF_ACTH);
    __half* s_al = (__half*)(sb + OFF_ACTL);
    float*  s_res = (float*)(sb + OFF_ACTH);     // [128][132]
    uint32_t dynb = smem_u32(sb);

    __shared__ int s_src[TE], s_dst[TE];
    __shared__ unsigned char s_mk[TE];
    __shared__ int s_any[NB];
    __shared__ float s_bias[256], s_base[128];

    int tid = threadIdx.x, lane = tid & 31, wid = tid >> 5;
    int eb = blockIdx.x * TE;

    if (tid < TE) {
        s_src[tid] = ei[eb + tid];
        s_dst[tid] = ei[NEDGE + eb + tid];
        s_mk[tid]  = g_maskb[eb + tid];
    }
    __syncthreads();
    if (tid < NB) {
        int a = 0;
        for (int e = 0; e < TE; e++) a |= (s_mk[e] >> tid) & 1;
        s_any[tid] = a;
    }
    __syncthreads();
    if (tid < 128) {
        float b = g_cvec[tid];
        #pragma unroll
        for (int k = 0; k < NB; k++) if (!s_any[k]) b += g_dvec[k * 128 + tid];
        s_base[tid] = b;
    }
    bool anyband = s_any[0] || s_any[1] || s_any[2];

    // fragment geometry
    int m0 = (wid & 3) * 32, n0 = (wid >> 2) * 64;
    int rowA = ((lane >> 3) & 1) * 8 + (lane & 7);
    int colA = ((lane >> 4) & 1) * 8;
    int rowB = ((lane >> 4) & 1) * 8 + (lane & 7);
    int colB = ((lane >> 3) & 1) * 8;
    int n_st = tid >> 1;
    int p0h  = (tid & 1) * 16;     // half offset within 32-half chunk row
    uint32_t stgDst = dynb + OFF_STG + (uint32_t)(n_st * 80 + (tid & 1) * 32);

    float acc2[2][8][4];
    #pragma unroll
    for (int i = 0; i < 2; i++)
        #pragma unroll
        for (int j = 0; j < 8; j++)
            #pragma unroll
            for (int q = 0; q < 4; q++) acc2[i][j][q] = 0.0f;

    if (anyband) {
        // ---- gather X tile, convert to f16 hi/lo ----
        for (int idx = tid; idx < TE * 48; idx += 256) {
            int r = idx / 48, q = idx - r * 48;
            float4 v;
            if (q < 32)      v = ((const float4*)(hidden + (size_t)s_src[r] * DEMB))[q];
            else if (q < 40) v = ((const float4*)(ea + (size_t)(eb + r) * 32))[q - 32];
            else             v = ((const float4*)(ete + (size_t)(eb + r) * 32))[q - 40];
            int j0 = q * 4;
            __half h0, l0, h1, l1, h2, l2, h3, l3;
            splith(v.x, h0, l0); splith(v.y, h1, l1); splith(v.z, h2, l2); splith(v.w, h3, l3);
            __half2* ph = (__half2*)(s_xh + r * 200 + j0);
            __half2* pl = (__half2*)(s_xl + r * 200 + j0);
            ph[0] = __halves2half2(h0, h1); ph[1] = __halves2half2(h2, h3);
            pl[0] = __halves2half2(l0, l1); pl[1] = __halves2half2(l2, l3);
        }

        // segment list: (band,hh) pairs
        int segBand[NB]; int nseg = 0;
        #pragma unroll
        for (int k = 0; k < NB; k++) if (s_any[k]) segBand[nseg++] = k;
        int totseg = nseg * 2;

        // prefetch segment 0 GEMM1 chunk 0 into buf0
        {
            int b0 = segBand[0];
            stage_chunk(stgDst, g_B1h + ((size_t)b0 * 256) * 192 + n_st * 192 + p0h);
            CP_COMMIT();
        }

        for (int s = 0; s < totseg; s++) {
            int band = segBand[s >> 1], hh = s & 1;
            if (hh == 0) {
                if (tid < 128) s_bias[tid] = rb1[band * 128 + tid];
                else           s_bias[tid] = ib1[band * 128 + (tid - 128)];
            }
            const __half* g1h = g_B1h + ((size_t)band * 256 + hh * 128) * 192 + n_st * 192 + p0h;
            const __half* g2h = g_B2h + (size_t)band * 32768 + hh * 128 + n_st * 256 + p0h;

            float acc1[2][8][4];
            #pragma unroll
            for (int i = 0; i < 2; i++)
                #pragma unroll
                for (int j = 0; j < 8; j++)
                    #pragma unroll
                    for (int q = 0; q < 4; q++) acc1[i][j][q] = 0.0f;

            // ---- GEMM1: 6 K-chunks ----
            #pragma unroll 1
            for (int c = 0; c < 6; c++) {
                CP_WAIT0();
                __syncthreads();
                if (c < 5) stage_chunk(stgDst + ((c + 1) & 1) * 10240, g1h + (c + 1) * 32);
                else       stage_chunk(stgDst, g2h);   // GEMM2 chunk 0 -> buf0
                CP_COMMIT();
                uint32_t xh = dynb + (uint32_t)((m0 + rowA) * 400 + (c * 32 + colA) * 2);
                uint32_t bh = dynb + OFF_STG + (c & 1) * 10240 + (uint32_t)((n0 + rowB) * 80 + colB * 2);
                chunk2(acc1, xh, xh + OFF_XLO, 400u, bh);
            }

            // ---- activation -> act hi/lo ----
            #pragma unroll
            for (int mt = 0; mt < 2; mt++) {
                int r0 = m0 + mt * 16 + (lane >> 2);
                float mk0 = (float)((s_mk[r0] >> band) & 1);
                float mk1 = (float)((s_mk[r0 + 8] >> band) & 1);
                #pragma unroll
                for (int nt = 0; nt < 8; nt++) {
                    int cb = n0 + nt * 8 + (lane & 3) * 2;
                    float b0 = s_bias[hh * 128 + cb], b1 = s_bias[hh * 128 + cb + 1];
                    float a00 = fmaxf(fmaf(mk0, acc1[mt][nt][0], b0) - LAM, 0.0f);
                    float a01 = fmaxf(fmaf(mk0, acc1[mt][nt][1], b1) - LAM, 0.0f);
                    float a10 = fmaxf(fmaf(mk1, acc1[mt][nt][2], b0) - LAM, 0.0f);
                    float a11 = fmaxf(fmaf(mk1, acc1[mt][nt][3], b1) - LAM, 0.0f);
                    __half h0, l0, h1, l1;
                    splith(a00, h0, l0); splith(a01, h1, l1);
                    *(__half2*)(s_ah + r0 * 136 + cb) = __halves2half2(h0, h1);
                    *(__half2*)(s_al + r0 * 136 + cb) = __halves2half2(l0, l1);
                    splith(a10, h0, l0); splith(a11, h1, l1);
                    *(__half2*)(s_ah + (r0 + 8) * 136 + cb) = __halves2half2(h0, h1);
                    *(__half2*)(s_al + (r0 + 8) * 136 + cb) = __halves2half2(l0, l1);
                }
            }

            // ---- GEMM2: 4 K-chunks ----
            #pragma unroll 1
            for (int c = 0; c < 4; c++) {
                CP_WAIT0();
                __syncthreads();          // publishes act + staged chunk
                if (c < 3) stage_chunk(stgDst + ((c + 1) & 1) * 10240, g2h + (c + 1) * 32);
                else if (s + 1 < totseg) {
                    int nb = segBand[(s + 1) >> 1], nhh = (s + 1) & 1;
                    stage_chunk(stgDst, g_B1h + ((size_t)nb * 256 + nhh * 128) * 192 + n_st * 192 + p0h);
                }
                CP_COMMIT();
                uint32_t ah = dynb + OFF_ACTH + (uint32_t)((m0 + rowA) * 272 + (c * 32 + colA) * 2);
                uint32_t bh = dynb + OFF_STG + (c & 1) * 10240 + (uint32_t)((n0 + rowB) * 80 + colB * 2);
                chunk2(acc2, ah, ah + (OFF_ACTL - OFF_ACTH), 272u, bh);
            }
        }
    }

    // ---- stage msg2 into smem (aliased with act) and scatter ----
    __syncthreads();
    if (anyband) {
        #pragma unroll
        for (int mt = 0; mt < 2; mt++) {
            int r0 = m0 + mt * 16 + (lane >> 2);
            #pragma unroll
            for (int nt = 0; nt < 8; nt++) {
                int cb = n0 + nt * 8 + (lane & 3) * 2;
                *(float2*)(s_res + r0 * 132 + cb)       = make_float2(acc2[mt][nt][0], acc2[mt][nt][1]);
                *(float2*)(s_res + (r0 + 8) * 132 + cb) = make_float2(acc2[mt][nt][2], acc2[mt][nt][3]);
            }
        }
    }
    __syncthreads();
    {
        int row = tid >> 1, cb = (tid & 1) * 64;
        int dst = s_dst[row];
        float* p = g_acc + (size_t)dst * DEMB + cb;
        #pragma unroll
        for (int j = 0; j < 16; j++) {
            int c = cb + 4 * j;
            float x0 = s_base[c], x1 = s_base[c + 1], x2 = s_base[c + 2], x3 = s_base[c + 3];
            if (anyband) {
                x0 += s_res[row * 132 + c];     x1 += s_res[row * 132 + c + 1];
                x2 += s_res[row * 132 + c + 2]; x3 += s_res[row * 132 + c + 3];
            }
            asm volatile("red.global.add.v4.f32 [%0], {%1,%2,%3,%4};"
                         :: "l"(p + 4 * j), "f"(x0), "f"(x1), "f"(x2), "f"(x3) : "memory");
        }
    }
}

// ---------------- node epilogue (32 nodes/block, fused pair, guarded) ----------------
#define SMEM_FINAL ((128 * 128 + 32 * 128) * 4)

__global__ void __launch_bounds__(256, 1)
k_final(const float* __restrict__ lin_w, const float* __restrict__ lin_b,
        const float* __restrict__ ln_g, const float* __restrict__ ln_b,
        float* __restrict__ out) {
    extern __shared__ float sm[];
    float* lw = sm;
    float* at = sm + 128 * 128;
    int tid = threadIdx.x;
    int n0 = blockIdx.x * 32;
    int nvalid = NNODE - n0; if (nvalid > 32) nvalid = 32;

    for (int idx = tid; idx < 128 * 128; idx += 256) lw[idx] = lin_w[idx];
    for (int idx = tid; idx < nvalid * 128; idx += 256) at[idx] = g_acc[(size_t)n0 * DEMB + idx];
    __syncthreads();

    int m0 = (tid & 15) * 8;
    int i0 = tid >> 4, i1 = i0 + 16;
    float t0[8], t1[8];
    #pragma unroll
    for (int j = 0; j < 8; j++) { t0[j] = lin_b[m0 + j]; t1[j] = t0[j]; }
    const float* ar0 = at + i0 * 128;
    const float* ar1 = at + i1 * 128;
    bool v1 = (i1 < nvalid);
    for (int q = 0; q < 128; q++) {
        float4 w1 = *(const float4*)&lw[q * 128 + m0];
        float4 w2 = *(const float4*)&lw[q * 128 + m0 + 4];
        float a0 = ar0[q];
        float a1 = v1 ? ar1[q] : 0.0f;
        t0[0] = fmaf(a0, w1.x, t0[0]); t0[1] = fmaf(a0, w1.y, t0[1]);
        t0[2] = fmaf(a0, w1.z, t0[2]); t0[3] = fmaf(a0, w1.w, t0[3]);
        t0[4] = fmaf(a0, w2.x, t0[4]); t0[5] = fmaf(a0, w2.y, t0[5]);
        t0[6] = fmaf(a0, w2.z, t0[6]); t0[7] = fmaf(a0, w2.w, t0[7]);
        t1[0] = fmaf(a1, w1.x, t1[0]); t1[1] = fmaf(a1, w1.y, t1[1]);
        t1[2] = fmaf(a1, w1.z, t1[2]); t1[3] = fmaf(a1, w1.w, t1[3]);
        t1[4] = fmaf(a1, w2.x, t1[4]); t1[5] = fmaf(a1, w2.y, t1[5]);
        t1[6] = fmaf(a1, w2.z, t1[6]); t1[7] = fmaf(a1, w2.w, t1[7]);
    }
    // LayerNorm for node i0
    {
        float s1 = 0.0f;
        #pragma unroll
        for (int j = 0; j < 8; j++) s1 += t0[j];
        #pragma unroll
        for (int off = 8; off; off >>= 1) s1 += __shfl_xor_sync(0xffffffffu, s1, off, 16);
        float mu = s1 * (1.0f / 128.0f);
        float s2 = 0.0f;
        #pragma unroll
        for (int j = 0; j < 8; j++) { float d = t0[j] - mu; s2 += d * d; }
        #pragma unroll
        for (int off = 8; off; off >>= 1) s2 += __shfl_xor_sync(0xffffffffu, s2, off, 16);
        float inv = rsqrtf(s2 * (1.0f / 128.0f) + LNEPS);
        if (i0 < nvalid) {
            #pragma unroll
            for (int j = 0; j < 8; j++) {
                int m = m0 + j;
                float y = (t0[j] - mu) * inv * ln_g[m] + ln_b[m];
                out[(size_t)(n0 + i0) * DEMB + m] = fmaxf(y, 0.0f);
            }
        }
    }
    // LayerNorm for node i1
    {
        float s1 = 0.0f;
        #pragma unroll
        for (int j = 0; j < 8; j++) s1 += t1[j];
        #pragma unroll
        for (int off = 8; off; off >>= 1) s1 += __shfl_xor_sync(0xffffffffu, s1, off, 16);
        float mu = s1 * (1.0f / 128.0f);
        float s2 = 0.0f;
        #pragma unroll
        for (int j = 0; j < 8; j++) { float d = t1[j] - mu; s2 += d * d; }
        #pragma unroll
        for (int off = 8; off; off >>= 1) s2 += __shfl_xor_sync(0xffffffffu, s2, off, 16);
        float inv = rsqrtf(s2 * (1.0f / 128.0f) + LNEPS);
        if (v1) {
            #pragma unroll
            for (int j = 0; j < 8; j++) {
                int m = m0 + j;
                float y = (t1[j] - mu) * inv * ln_g[m] + ln_b[m];
                out[(size_t)(n0 + i1) * DEMB + m] = fmaxf(y, 0.0f);
            }
        }
    }
}

// ---------------- launcher ----------------
extern "C" void kernel_launch(void* const* d_in, const int* in_sizes, int n_in,
                              void* d_out, int out_size) {
    const float* hidden   = (const float*)d_in[0];
    const float* edge_attr= (const float*)d_in[1];
    const float* ete      = (const float*)d_in[2];
    const float* boundary = (const float*)d_in[3];
    const float* alpha    = (const float*)d_in[4];
    const float* r1       = (const float*)d_in[5];
    const float* i1       = (const float*)d_in[6];
    const float* rb1      = (const float*)d_in[7];
    const float* ib1      = (const float*)d_in[8];
    const float* fre_w    = (const float*)d_in[9];
    const float* fre_b    = (const float*)d_in[10];
    const float* comb_w   = (const float*)d_in[11];
    const float* comb_b   = (const float*)d_in[12];
    const float* lin_w    = (const float*)d_in[13];
    const float* lin_b    = (const float*)d_in[14];
    const float* ln_g     = (const float*)d_in[15];
    const float* ln_b     = (const float*)d_in[16];
    const int*   ei       = (const int*)d_in[17];
    float* out = (float*)d_out;

    cudaFuncSetAttribute(k_edge_mma, cudaFuncAttributeMaxDynamicSharedMemorySize, DYN_EDGE);
    cudaFuncSetAttribute(k_final,    cudaFuncAttributeMaxDynamicSharedMemorySize, SMEM_FINAL);

    k_tables<<<1, 384>>>();
    k_buildA<<<768, 192>>>(r1, i1);
    k_buildWrWi<<<384, 128>>>(fre_w);
    k_buildW<<<768, 128>>>(comb_w);
    k_buildCD<<<1, 128>>>(fre_b, comb_w, comb_b, rb1, ib1);
    k_packB1<<<576, 256>>>();
    k_packB2<<<384, 256>>>();
    k_nodenorm<<<NNODE / 8, 256>>>(hidden);
    k_energy<<<NEDGE / 8, 256>>>(edge_attr, ete, ei);
    k_reduce_esum<<<1, 256>>>();
    k_mask<<<NEDGE / 256, 256>>>(alpha);
    k_initacc<<<3125, 256>>>(boundary);
    k_edge_mma<<<NT, 256, DYN_EDGE>>>(hidden, edge_attr, ete, ei, rb1, ib1);
    k_final<<<(NNODE + 31) / 32, 256, SMEM_FINAL>>>(lin_w, lin_b, ln_g, ln_b, out);
}

// round 8
// speedup vs baseline: 5.9392x; 1.0911x over previous
#include <cuda_runtime.h>
#include <cuda_fp16.h>
#include <math.h>
#include <stdint.h>

// Problem constants
#define NNODE 50000
#define NEDGE 320000
#define DEMB  128
#define DIN   192
#define NB    3
#define LAM   0.01f
#define LNEPS 1e-5f

#define TE    128
#define NT    (NEDGE / TE)        // 2500

// ---------------- device scratch ----------------
__device__ float g_ct192[192], g_st192[192];
__device__ float g_ct384[384], g_st384[384];
__device__ float g_A[DIN * 768];
__device__ float g_Wr[384 * 128];
__device__ float g_Wi[384 * 128];
__device__ float g_W[768 * 128];
__device__ float g_cvec[128];
__device__ float g_dvec[NB * 128];
__device__ float g_nodenorm[NNODE];
__device__ float g_energy[NEDGE];
__device__ float g_esum_part[256];
__device__ float g_esum;
__device__ unsigned char g_maskb[NEDGE];
__device__ float g_acc[NNODE * DEMB];

// fp16 transposed operands: B1[band][n(256)][k(192)], B2[band][n(128)][k(256)]
__device__ __align__(16) __half g_B1h[NB * 256 * 192];
__device__ __align__(16) __half g_B2h[NB * 128 * 256];

// ---------------- helpers ----------------
__device__ __forceinline__ uint32_t smem_u32(const void* p) {
    uint32_t a;
    asm("{ .reg .u64 t; cvta.to.shared.u64 t, %1; cvt.u32.u64 %0, t; }" : "=r"(a) : "l"(p));
    return a;
}

#define LDSM4(R, addr) \
    asm volatile("ldmatrix.sync.aligned.m8n8.x4.shared.b16 {%0,%1,%2,%3}, [%4];" \
        : "=r"((R)[0]), "=r"((R)[1]), "=r"((R)[2]), "=r"((R)[3]) : "r"(addr))

#define MMA16816(C, A, B0, B1) \
    asm volatile("mma.sync.aligned.m16n8k16.row.col.f32.f16.f16.f32 " \
        "{%0,%1,%2,%3}, {%4,%5,%6,%7}, {%8,%9}, {%0,%1,%2,%3};" \
        : "+f"((C)[0]), "+f"((C)[1]), "+f"((C)[2]), "+f"((C)[3]) \
        : "r"((A)[0]), "r"((A)[1]), "r"((A)[2]), "r"((A)[3]), "r"(B0), "r"(B1))

#define CP_COMMIT() asm volatile("cp.async.commit_group;" ::: "memory")
#define CP_WAIT0()  asm volatile("cp.async.wait_group 0;" ::: "memory")

// stage one 32-K chunk's B slice (8KB across 256 threads; 32B per thread)
__device__ __forceinline__ void stage_chunk(uint32_t dstH, const __half* srcH) {
    asm volatile(
        "cp.async.cg.shared.global [%0], [%2], 16;\n\t"
        "cp.async.cg.shared.global [%1], [%3], 16;\n\t"
        :: "r"(dstH), "r"(dstH + 16), "l"(srcH), "l"(srcH + 8) : "memory");
}

// one K=32 chunk, single fp16 term
__device__ __forceinline__ void chunk1(float (&acc)[2][8][4],
                                       uint32_t aAddr, uint32_t aStride, uint32_t bAddr) {
    #pragma unroll
    for (int k16 = 0; k16 < 32; k16 += 16) {
        uint32_t a0[4], a1[4], b[4][4];
        LDSM4(a0, aAddr + k16 * 2);
        LDSM4(a1, aAddr + 16 * aStride + k16 * 2);
        #pragma unroll
        for (int ntp = 0; ntp < 4; ntp++) LDSM4(b[ntp], bAddr + ntp * 16 * 80 + k16 * 2);
        #pragma unroll
        for (int ntp = 0; ntp < 4; ntp++) {
            MMA16816(acc[0][2 * ntp],     a0, b[ntp][0], b[ntp][1]);
            MMA16816(acc[0][2 * ntp + 1], a0, b[ntp][2], b[ntp][3]);
            MMA16816(acc[1][2 * ntp],     a1, b[ntp][0], b[ntp][1]);
            MMA16816(acc[1][2 * ntp + 1], a1, b[ntp][2], b[ntp][3]);
        }
    }
}

// ---------------- precompute (proven) ----------------
__global__ void k_tables() {
    int t = threadIdx.x;
    if (t < 192) { g_ct192[t] = (float)cospi(2.0 * t / 192.0); g_st192[t] = (float)sinpi(2.0 * t / 192.0); }
    if (t < 384) { g_ct384[t] = (float)cospi(2.0 * t / 384.0); g_st384[t] = (float)sinpi(2.0 * t / 384.0); }
    if (t < 256) g_esum_part[t] = 0.0f;
    if (t == 0) g_esum = 0.0f;
}

__global__ void k_buildA(const float* __restrict__ r1, const float* __restrict__ i1) {
    __shared__ float ct[192], st[192];
    int n = threadIdx.x, c = blockIdx.x;
    ct[n] = g_ct192[n]; st[n] = g_st192[n];
    __syncthreads();
    int k = c >> 8, cc = c & 255;
    const float* R = r1 + k * DIN * DEMB;
    const float* I = i1 + k * DIN * DEMB;
    float s = 0.0f;
    if (cc < 128) {
        int m = cc;
        for (int j = 0; j < 192; j++) { int t = (j * n) % 192; s += ct[t] * R[j * DEMB + m] + st[t] * I[j * DEMB + m]; }
    } else {
        int m = cc - 128;
        for (int j = 0; j < 192; j++) { int t = (j * n) % 192; s += ct[t] * I[j * DEMB + m] - st[t] * R[j * DEMB + m]; }
    }
    g_A[n * 768 + c] = s;
}

__global__ void k_buildWrWi(const float* __restrict__ fre_w) {
    __shared__ float ct[384], st[384];
    int p = threadIdx.x, j = blockIdx.x;
    for (int t = p; t < 384; t += 128) { ct[t] = g_ct384[t]; st[t] = g_st384[t]; }
    __syncthreads();
    float sr = 0.0f, si = 0.0f;
    for (int n = 0; n < 384; n++) {
        int t = (j * n) % 384;
        float w = fre_w[n * 128 + p];
        sr += ct[t] * w; si -= st[t] * w;
    }
    g_Wr[j * 128 + p] = sr * (1.0f / 384.0f);
    g_Wi[j * 128 + p] = si * (1.0f / 384.0f);
}

__global__ void k_buildW(const float* __restrict__ comb_w) {
    int m = threadIdx.x, r = blockIdx.x;
    int k = r >> 8, cc = r & 255;
    int j = k * 128 + (cc & 127);
    const float* src = (cc < 128) ? g_Wr : g_Wi;
    float s = 0.0f;
    for (int p = 0; p < 128; p++) s += src[j * 128 + p] * comb_w[(2 * p) * 128 + m];
    g_W[r * 128 + m] = s;
}

__global__ void k_buildCD(const float* __restrict__ fre_b, const float* __restrict__ comb_w,
                          const float* __restrict__ comb_b,
                          const float* __restrict__ rb1, const float* __restrict__ ib1) {
    int m = threadIdx.x;
    float s = 0.0f;
    for (int p = 0; p < 128; p++) s += fre_b[p] * comb_w[(2 * p) * 128 + m];
    g_cvec[m] = s + comb_b[m];
    for (int k = 0; k < NB; k++) {
        float d = 0.0f;
        for (int j0 = 0; j0 < 128; j0++) {
            float ar = fmaxf(rb1[k * 128 + j0] - LAM, 0.0f);
            float ai = fmaxf(ib1[k * 128 + j0] - LAM, 0.0f);
            d += ar * g_W[(k * 256 + j0) * 128 + m] + ai * g_W[(k * 256 + 128 + j0) * 128 + m];
        }
        g_dvec[k * 128 + m] = d;
    }
}

__global__ void k_packB1() {
    int idx = blockIdx.x * 256 + threadIdx.x;
    int band = idx / 49152, r = idx % 49152;
    int n = r / 192, j = r % 192;
    g_B1h[idx] = __float2half_rn(g_A[j * 768 + band * 256 + n]);
}
__global__ void k_packB2() {
    int idx = blockIdx.x * 256 + threadIdx.x;
    int band = idx / 32768, r = idx % 32768;
    int m = r / 256, c = r % 256;
    g_B2h[idx] = __float2half_rn(g_W[(band * 256 + c) * 128 + m]);
}

// ---------------- energy / mask / init ----------------
__global__ void k_nodenorm(const float* __restrict__ hidden) {
    int tid = threadIdx.x, w = tid >> 5, lane = tid & 31;
    int n = blockIdx.x * 8 + w;
    const float* h = hidden + (size_t)n * DEMB;
    float s = 0.0f;
    #pragma unroll
    for (int i = 0; i < 4; i++) { float v = h[lane + 32 * i]; s += v * v; }
    #pragma unroll
    for (int off = 16; off; off >>= 1) s += __shfl_xor_sync(0xffffffffu, s, off);
    if (lane == 0) g_nodenorm[n] = s;
}

__global__ void k_energy(const float* __restrict__ ea, const float* __restrict__ ete,
                         const int* __restrict__ ei) {
    __shared__ float wsum[8];
    int tid = threadIdx.x, w = tid >> 5, lane = tid & 31;
    int e = blockIdx.x * 8 + w;
    float a = ea[(size_t)e * 32 + lane];
    float b = ete[(size_t)e * 32 + lane];
    float s = a * a + b * b;
    #pragma unroll
    for (int off = 16; off; off >>= 1) s += __shfl_xor_sync(0xffffffffu, s, off);
    if (lane == 0) { float en = 192.0f * (g_nodenorm[ei[e]] + s); g_energy[e] = en; wsum[w] = en; }
    __syncthreads();
    if (tid == 0) {
        float t = 0.0f;
        #pragma unroll
        for (int i = 0; i < 8; i++) t += wsum[i];
        atomicAdd(&g_esum_part[blockIdx.x & 255], t);
    }
}

__global__ void k_reduce_esum() {
    __shared__ float rs[8];
    int tid = threadIdx.x;
    float v = g_esum_part[tid];
    #pragma unroll
    for (int off = 16; off; off >>= 1) v += __shfl_xor_sync(0xffffffffu, v, off);
    if ((tid & 31) == 0) rs[tid >> 5] = v;
    __syncthreads();
    if (tid == 0) {
        float t = 0.0f;
        #pragma unroll
        for (int i = 0; i < 8; i++) t += rs[i];
        g_esum = t;
    }
}

__global__ void k_mask(const float* __restrict__ alpha) {
    int e = blockIdx.x * 256 + threadIdx.x;
    float en = g_energy[e], es = g_esum;
    unsigned char mb = 0;
    #pragma unroll
    for (int k = 0; k < NB; k++) {
        float al = alpha[k];
        float factor = (2.0f * (k + 1) - 1.0f) / (2.0f * NB);
        float Q = al * factor * es;
        float bnd = es / (al * (2.0f * NB));
        if (en >= Q - bnd && en <= Q + bnd) mb |= (1 << k);
    }
    g_maskb[e] = mb;
}

__global__ void k_initacc(const float* __restrict__ boundary) {
    const float4* s = (const float4*)boundary;
    float4* d = (float4*)g_acc;
    int n4 = NNODE * DEMB / 4;
    for (int i = blockIdx.x * blockDim.x + threadIdx.x; i < n4; i += gridDim.x * blockDim.x)
        d[i] = s[i];
}

// ---------------- main edge kernel (HMMA, pure fp16, cp.async) ----------------
// dynamic smem:
//   Xh  [128][200] @0      (51200)
//   actH[128][136] @51200  (34816)
//   staging [2 buf][128][40] @86016 (20480)
//   s_res fp32 [128][132] aliases @0 (post-GEMM only)
#define OFF_ACTH  51200
#define OFF_STG   86016
#define DYN_EDGE  106496

__global__ void __launch_bounds__(256, 1)
k_edge_mma(const float* __restrict__ hidden, const float* __restrict__ ea,
           const float* __restrict__ ete, const int* __restrict__ ei,
           const float* __restrict__ rb1, const float* __restrict__ ib1) {
    extern __shared__ char sb[];
    __half* s_xh = (__half*)sb;
    __half* s_ah = (__half*)(sb + OFF_ACTH);
    float*  s_res = (float*)sb;                  // [128][132], post-GEMM alias
    uint32_t dynb = smem_u32(sb);

    __shared__ int s_src[TE], s_dst[TE];
    __shared__ unsigned char s_mk[TE];
    __shared__ int s_any[NB];
    __shared__ float s_bias[256], s_base[128];

    int tid = threadIdx.x, lane = tid & 31, wid = tid >> 5;
    int eb = blockIdx.x * TE;

    if (tid < TE) {
        s_src[tid] = ei[eb + tid];
        s_dst[tid] = ei[NEDGE + eb + tid];
        s_mk[tid]  = g_maskb[eb + tid];
    }
    __syncthreads();
    if (tid < NB) {
        int a = 0;
        for (int e = 0; e < TE; e++) a |= (s_mk[e] >> tid) & 1;
        s_any[tid] = a;
    }
    __syncthreads();
    if (tid < 128) {
        float b = g_cvec[tid];
        #pragma unroll
        for (int k = 0; k < NB; k++) if (!s_any[k]) b += g_dvec[k * 128 + tid];
        s_base[tid] = b;
    }
    bool anyband = s_any[0] || s_any[1] || s_any[2];

    // fragment geometry
    int m0 = (wid & 3) * 32, n0 = (wid >> 2) * 64;
    int rowA = ((lane >> 3) & 1) * 8 + (lane & 7);
    int colA = ((lane >> 4) & 1) * 8;
    int rowB = ((lane >> 4) & 1) * 8 + (lane & 7);
    int colB = ((lane >> 3) & 1) * 8;
    int n_st = tid >> 1;
    int p0h  = (tid & 1) * 16;
    uint32_t stgDst = dynb + OFF_STG + (uint32_t)(n_st * 80 + (tid & 1) * 32);

    float acc2[2][8][4];
    #pragma unroll
    for (int i = 0; i < 2; i++)
        #pragma unroll
        for (int j = 0; j < 8; j++)
            #pragma unroll
            for (int q = 0; q < 4; q++) acc2[i][j][q] = 0.0f;

    if (anyband) {
        // ---- gather X tile, round to fp16 ----
        for (int idx = tid; idx < TE * 48; idx += 256) {
            int r = idx / 48, q = idx - r * 48;
            float4 v;
            if (q < 32)      v = ((const float4*)(hidden + (size_t)s_src[r] * DEMB))[q];
            else if (q < 40) v = ((const float4*)(ea + (size_t)(eb + r) * 32))[q - 32];
            else             v = ((const float4*)(ete + (size_t)(eb + r) * 32))[q - 40];
            __half2* ph = (__half2*)(s_xh + r * 200 + q * 4);
            ph[0] = __floats2half2_rn(v.x, v.y);
            ph[1] = __floats2half2_rn(v.z, v.w);
        }

        // segment list: (band,hh) pairs
        int segBand[NB]; int nseg = 0;
        #pragma unroll
        for (int k = 0; k < NB; k++) if (s_any[k]) segBand[nseg++] = k;
        int totseg = nseg * 2;

        // prefetch segment 0 GEMM1 chunk 0 into buf0
        {
            int b0 = segBand[0];
            stage_chunk(stgDst, g_B1h + ((size_t)b0 * 256) * 192 + n_st * 192 + p0h);
            CP_COMMIT();
        }

        for (int s = 0; s < totseg; s++) {
            int band = segBand[s >> 1], hh = s & 1;
            if (hh == 0) {
                if (tid < 128) s_bias[tid] = rb1[band * 128 + tid];
                else           s_bias[tid] = ib1[band * 128 + (tid - 128)];
            }
            const __half* g1h = g_B1h + ((size_t)band * 256 + hh * 128) * 192 + n_st * 192 + p0h;
            const __half* g2h = g_B2h + (size_t)band * 32768 + hh * 128 + n_st * 256 + p0h;

            float acc1[2][8][4];
            #pragma unroll
            for (int i = 0; i < 2; i++)
                #pragma unroll
                for (int j = 0; j < 8; j++)
                    #pragma unroll
                    for (int q = 0; q < 4; q++) acc1[i][j][q] = 0.0f;

            // ---- GEMM1: 6 K-chunks ----
            #pragma unroll 1
            for (int c = 0; c < 6; c++) {
                CP_WAIT0();
                __syncthreads();
                if (c < 5) stage_chunk(stgDst + ((c + 1) & 1) * 10240, g1h + (c + 1) * 32);
                else       stage_chunk(stgDst, g2h);   // GEMM2 chunk 0 -> buf0
                CP_COMMIT();
                uint32_t xh = dynb + (uint32_t)((m0 + rowA) * 400 + (c * 32 + colA) * 2);
                uint32_t bh = dynb + OFF_STG + (c & 1) * 10240 + (uint32_t)((n0 + rowB) * 80 + colB * 2);
                chunk1(acc1, xh, 400u, bh);
            }

            // ---- activation -> act fp16 ----
            #pragma unroll
            for (int mt = 0; mt < 2; mt++) {
                int r0 = m0 + mt * 16 + (lane >> 2);
                float mk0 = (float)((s_mk[r0] >> band) & 1);
                float mk1 = (float)((s_mk[r0 + 8] >> band) & 1);
                #pragma unroll
                for (int nt = 0; nt < 8; nt++) {
                    int cb = n0 + nt * 8 + (lane & 3) * 2;
                    float b0 = s_bias[hh * 128 + cb], b1 = s_bias[hh * 128 + cb + 1];
                    float a00 = fmaxf(fmaf(mk0, acc1[mt][nt][0], b0) - LAM, 0.0f);
                    float a01 = fmaxf(fmaf(mk0, acc1[mt][nt][1], b1) - LAM, 0.0f);
                    float a10 = fmaxf(fmaf(mk1, acc1[mt][nt][2], b0) - LAM, 0.0f);
                    float a11 = fmaxf(fmaf(mk1, acc1[mt][nt][3], b1) - LAM, 0.0f);
                    *(__half2*)(s_ah + r0 * 136 + cb)       = __floats2half2_rn(a00, a01);
                    *(__half2*)(s_ah + (r0 + 8) * 136 + cb) = __floats2half2_rn(a10, a11);
                }
            }

            // ---- GEMM2: 4 K-chunks ----
            #pragma unroll 1
            for (int c = 0; c < 4; c++) {
                CP_WAIT0();
                __syncthreads();          // publishes act + staged chunk
                if (c < 3) stage_chunk(stgDst + ((c + 1) & 1) * 10240, g2h + (c + 1) * 32);
                else if (s + 1 < totseg) {
                    int nb = segBand[(s + 1) >> 1], nhh = (s + 1) & 1;
                    stage_chunk(stgDst, g_B1h + ((size_t)nb * 256 + nhh * 128) * 192 + n_st * 192 + p0h);
                }
                CP_COMMIT();
                uint32_t ah = dynb + OFF_ACTH + (uint32_t)((m0 + rowA) * 272 + (c * 32 + colA) * 2);
                uint32_t bh = dynb + OFF_STG + (c & 1) * 10240 + (uint32_t)((n0 + rowB) * 80 + colB * 2);
                chunk1(acc2, ah, 272u, bh);
            }
        }
    }

    // ---- stage msg2 into smem (aliases X/act region) and scatter ----
    __syncthreads();
    if (anyband) {
        #pragma unroll
        for (int mt = 0; mt < 2; mt++) {
            int r0 = m0 + mt * 16 + (lane >> 2);
            #pragma unroll
            for (int nt = 0; nt < 8; nt++) {
                int cb = n0 + nt * 8 + (lane & 3) * 2;
                *(float2*)(s_res + r0 * 132 + cb)       = make_float2(acc2[mt][nt][0], acc2[mt][nt][1]);
                *(float2*)(s_res + (r0 + 8) * 132 + cb) = make_float2(acc2[mt][nt][2], acc2[mt][nt][3]);
            }
        }
    }
    __syncthreads();
    {
        int row = tid >> 1, cb = (tid & 1) * 64;
        int dst = s_dst[row];
        float* p = g_acc + (size_t)dst * DEMB + cb;
        #pragma unroll
        for (int j = 0; j < 16; j++) {
            int c = cb + 4 * j;
            float x0 = s_base[c], x1 = s_base[c + 1], x2 = s_base[c + 2], x3 = s_base[c + 3];
            if (anyband) {
                x0 += s_res[row * 132 + c];     x1 += s_res[row * 132 + c + 1];
                x2 += s_res[row * 132 + c + 2]; x3 += s_res[row * 132 + c + 3];
            }
            asm volatile("red.global.add.v4.f32 [%0], {%1,%2,%3,%4};"
                         :: "l"(p + 4 * j), "f"(x0), "f"(x1), "f"(x2), "f"(x3) : "memory");
        }
    }
}

// ---------------- node epilogue (32 nodes/block, fused pair, guarded) ----------------
#define SMEM_FINAL ((128 * 128 + 32 * 128) * 4)

__global__ void __launch_bounds__(256, 1)
k_final(const float* __restrict__ lin_w, const float* __restrict__ lin_b,
        const float* __restrict__ ln_g, const float* __restrict__ ln_b,
        float* __restrict__ out) {
    extern __shared__ float sm[];
    float* lw = sm;
    float* at = sm + 128 * 128;
    int tid = threadIdx.x;
    int n0 = blockIdx.x * 32;
    int nvalid = NNODE - n0; if (nvalid > 32) nvalid = 32;

    for (int idx = tid; idx < 128 * 128; idx += 256) lw[idx] = lin_w[idx];
    for (int idx = tid; idx < nvalid * 128; idx += 256) at[idx] = g_acc[(size_t)n0 * DEMB + idx];
    __syncthreads();

    int m0 = (tid & 15) * 8;
    int i0 = tid >> 4, i1 = i0 + 16;
    float t0[8], t1[8];
    #pragma unroll
    for (int j = 0; j < 8; j++) { t0[j] = lin_b[m0 + j]; t1[j] = t0[j]; }
    const float* ar0 = at + i0 * 128;
    const float* ar1 = at + i1 * 128;
    bool v1 = (i1 < nvalid);
    for (int q = 0; q < 128; q++) {
        float4 w1 = *(const float4*)&lw[q * 128 + m0];
        float4 w2 = *(const float4*)&lw[q * 128 + m0 + 4];
        float a0 = ar0[q];
        float a1 = v1 ? ar1[q] : 0.0f;
        t0[0] = fmaf(a0, w1.x, t0[0]); t0[1] = fmaf(a0, w1.y, t0[1]);
        t0[2] = fmaf(a0, w1.z, t0[2]); t0[3] = fmaf(a0, w1.w, t0[3]);
        t0[4] = fmaf(a0, w2.x, t0[4]); t0[5] = fmaf(a0, w2.y, t0[5]);
        t0[6] = fmaf(a0, w2.z, t0[6]); t0[7] = fmaf(a0, w2.w, t0[7]);
        t1[0] = fmaf(a1, w1.x, t1[0]); t1[1] = fmaf(a1, w1.y, t1[1]);
        t1[2] = fmaf(a1, w1.z, t1[2]); t1[3] = fmaf(a1, w1.w, t1[3]);
        t1[4] = fmaf(a1, w2.x, t1[4]); t1[5] = fmaf(a1, w2.y, t1[5]);
        t1[6] = fmaf(a1, w2.z, t1[6]); t1[7] = fmaf(a1, w2.w, t1[7]);
    }
    {
        float s1 = 0.0f;
        #pragma unroll
        for (int j = 0; j < 8; j++) s1 += t0[j];
        #pragma unroll
        for (int off = 8; off; off >>= 1) s1 += __shfl_xor_sync(0xffffffffu, s1, off, 16);
        float mu = s1 * (1.0f / 128.0f);
        float s2 = 0.0f;
        #pragma unroll
        for (int j = 0; j < 8; j++) { float d = t0[j] - mu; s2 += d * d; }
        #pragma unroll
        for (int off = 8; off; off >>= 1) s2 += __shfl_xor_sync(0xffffffffu, s2, off, 16);
        float inv = rsqrtf(s2 * (1.0f / 128.0f) + LNEPS);
        if (i0 < nvalid) {
            #pragma unroll
            for (int j = 0; j < 8; j++) {
                int m = m0 + j;
                float y = (t0[j] - mu) * inv * ln_g[m] + ln_b[m];
                out[(size_t)(n0 + i0) * DEMB + m] = fmaxf(y, 0.0f);
            }
        }
    }
    {
        float s1 = 0.0f;
        #pragma unroll
        for (int j = 0; j < 8; j++) s1 += t1[j];
        #pragma unroll
        for (int off = 8; off; off >>= 1) s1 += __shfl_xor_sync(0xffffffffu, s1, off, 16);
        float mu = s1 * (1.0f / 128.0f);
        float s2 = 0.0f;
        #pragma unroll
        for (int j = 0; j < 8; j++) { float d = t1[j] - mu; s2 += d * d; }
        #pragma unroll
        for (int off = 8; off; off >>= 1) s2 += __shfl_xor_sync(0xffffffffu, s2, off, 16);
        float inv = rsqrtf(s2 * (1.0f / 128.0f) + LNEPS);
        if (v1) {
            #pragma unroll
            for (int j = 0; j < 8; j++) {
                int m = m0 + j;
                float y = (t1[j] - mu) * inv * ln_g[m] + ln_b[m];
                out[(size_t)(n0 + i1) * DEMB + m] = fmaxf(y, 0.0f);
            }
        }
    }
}

// ---------------- launcher ----------------
extern "C" void kernel_launch(void* const* d_in, const int* in_sizes, int n_in,
                              void* d_out, int out_size) {
    const float* hidden   = (const float*)d_in[0];
    const float* edge_attr= (const float*)d_in[1];
    const float* ete      = (const float*)d_in[2];
    const float* boundary = (const float*)d_in[3];
    const float* alpha    = (const float*)d_in[4];
    const float* r1       = (const float*)d_in[5];
    const float* i1       = (const float*)d_in[6];
    const float* rb1      = (const float*)d_in[7];
    const float* ib1      = (const float*)d_in[8];
    const float* fre_w    = (const float*)d_in[9];
    const float* fre_b    = (const float*)d_in[10];
    const float* comb_w   = (const float*)d_in[11];
    const float* comb_b   = (const float*)d_in[12];
    const float* lin_w    = (const float*)d_in[13];
    const float* lin_b    = (const float*)d_in[14];
    const float* ln_g     = (const float*)d_in[15];
    const float* ln_b     = (const float*)d_in[16];
    const int*   ei       = (const int*)d_in[17];
    float* out = (float*)d_out;

    cudaFuncSetAttribute(k_edge_mma, cudaFuncAttributeMaxDynamicSharedMemorySize, DYN_EDGE);
    cudaFuncSetAttribute(k_final,    cudaFuncAttributeMaxDynamicSharedMemorySize, SMEM_FINAL);

    k_tables<<<1, 384>>>();
    k_buildA<<<768, 192>>>(r1, i1);
    k_buildWrWi<<<384, 128>>>(fre_w);
    k_buildW<<<768, 128>>>(comb_w);
    k_buildCD<<<1, 128>>>(fre_b, comb_w, comb_b, rb1, ib1);
    k_packB1<<<576, 256>>>();
    k_packB2<<<384, 256>>>();
    k_nodenorm<<<NNODE / 8, 256>>>(hidden);
    k_energy<<<NEDGE / 8, 256>>>(edge_attr, ete, ei);
    k_reduce_esum<<<1, 256>>>();
    k_mask<<<NEDGE / 256, 256>>>(alpha);
    k_initacc<<<3125, 256>>>(boundary);
    k_edge_mma<<<NT, 256, DYN_EDGE>>>(hidden, edge_attr, ete, ei, rb1, ib1);
    k_final<<<(NNODE + 31) / 32, 256, SMEM_FINAL>>>(lin_w, lin_b, ln_g, ln_b, out);
}

// round 9
// speedup vs baseline: 6.5511x; 1.1030x over previous
#include <cuda_runtime.h>
#include <cuda_fp16.h>
#include <math.h>
#include <stdint.h>

// Problem constants
#define NNODE 50000
#define NEDGE 320000
#define DEMB  128
#define DIN   192
#define NB    3
#define LAM   0.01f
#define LNEPS 1e-5f

#define TE    64
#define NT    (NEDGE / TE)        // 5000

// ---------------- device scratch ----------------
__device__ float g_Wr[384 * 128];
__device__ float g_Wi[384 * 128];
__device__ float g_W[768 * 128];
__device__ float g_cvec[128];
__device__ float g_dvec[NB * 128];
__device__ float g_nodenorm[NNODE];
__device__ float g_energy[NEDGE];
__device__ float g_esum_part[256];
__device__ float g_esum;
__device__ unsigned char g_maskb[NEDGE];
__device__ float g_acc[NNODE * DEMB];

// fp16 transposed operands: B1[band][n(256)][k(192)], B2[band][m(128)][c(256)]
__device__ __align__(16) __half g_B1h[NB * 256 * 192];
__device__ __align__(16) __half g_B2h[NB * 128 * 256];

// ---------------- helpers ----------------
__device__ __forceinline__ uint32_t smem_u32(const void* p) {
    uint32_t a;
    asm("{ .reg .u64 t; cvta.to.shared.u64 t, %1; cvt.u32.u64 %0, t; }" : "=r"(a) : "l"(p));
    return a;
}

#define LDSM4(R, addr) \
    asm volatile("ldmatrix.sync.aligned.m8n8.x4.shared.b16 {%0,%1,%2,%3}, [%4];" \
        : "=r"((R)[0]), "=r"((R)[1]), "=r"((R)[2]), "=r"((R)[3]) : "r"(addr))

#define MMA16816(C, A, B0, B1) \
    asm volatile("mma.sync.aligned.m16n8k16.row.col.f32.f16.f16.f32 " \
        "{%0,%1,%2,%3}, {%4,%5,%6,%7}, {%8,%9}, {%0,%1,%2,%3};" \
        : "+f"((C)[0]), "+f"((C)[1]), "+f"((C)[2]), "+f"((C)[3]) \
        : "r"((A)[0]), "r"((A)[1]), "r"((A)[2]), "r"((A)[3]), "r"(B0), "r"(B1))

#define CP_COMMIT() asm volatile("cp.async.commit_group;" ::: "memory")
#define CP_WAIT0()  asm volatile("cp.async.wait_group 0;" ::: "memory")

// stage one 32-K chunk's B slice (8KB across 128 threads; 64B per thread = 1 row)
__device__ __forceinline__ void stage_chunk(uint32_t dst, const __half* src) {
    asm volatile(
        "cp.async.cg.shared.global [%0], [%4], 16;\n\t"
        "cp.async.cg.shared.global [%1], [%5], 16;\n\t"
        "cp.async.cg.shared.global [%2], [%6], 16;\n\t"
        "cp.async.cg.shared.global [%3], [%7], 16;\n\t"
        :: "r"(dst), "r"(dst + 16), "r"(dst + 32), "r"(dst + 48),
           "l"(src), "l"(src + 8), "l"(src + 16), "l"(src + 24) : "memory");
}

// one K=32 chunk, single fp16 term; warp computes 32 rows x 64 cols
__device__ __forceinline__ void chunk1(float (&acc)[2][8][4],
                                       uint32_t aAddr, uint32_t aStride, uint32_t bAddr) {
    #pragma unroll
    for (int k16 = 0; k16 < 32; k16 += 16) {
        uint32_t a0[4], a1[4], b[4][4];
        LDSM4(a0, aAddr + k16 * 2);
        LDSM4(a1, aAddr + 16 * aStride + k16 * 2);
        #pragma unroll
        for (int ntp = 0; ntp < 4; ntp++) LDSM4(b[ntp], bAddr + ntp * 16 * 80 + k16 * 2);
        #pragma unroll
        for (int ntp = 0; ntp < 4; ntp++) {
            MMA16816(acc[0][2 * ntp],     a0, b[ntp][0], b[ntp][1]);
            MMA16816(acc[0][2 * ntp + 1], a0, b[ntp][2], b[ntp][3]);
            MMA16816(acc[1][2 * ntp],     a1, b[ntp][0], b[ntp][1]);
            MMA16816(acc[1][2 * ntp + 1], a1, b[ntp][2], b[ntp][3]);
        }
    }
}

// ---------------- precompute ----------------
// A combined matrix, written directly as fp16 transposed blob
__global__ void k_buildA(const float* __restrict__ r1, const float* __restrict__ i1) {
    __shared__ float ct[192], st[192];
    int n = threadIdx.x, c = blockIdx.x;
    ct[n] = (float)cospi(2.0 * n / 192.0);
    st[n] = (float)sinpi(2.0 * n / 192.0);
    __syncthreads();
    int k = c >> 8, cc = c & 255;
    const float* R = r1 + k * DIN * DEMB;
    const float* I = i1 + k * DIN * DEMB;
    float s = 0.0f;
    if (cc < 128) {
        int m = cc;
        for (int j = 0; j < 192; j++) { int t = (j * n) % 192; s += ct[t] * R[j * DEMB + m] + st[t] * I[j * DEMB + m]; }
    } else {
        int m = cc - 128;
        for (int j = 0; j < 192; j++) { int t = (j * n) % 192; s += ct[t] * I[j * DEMB + m] - st[t] * R[j * DEMB + m]; }
    }
    g_B1h[c * 192 + n] = __float2half_rn(s);
}

__global__ void k_buildWrWi(const float* __restrict__ fre_w) {
    __shared__ float ct[384], st[384];
    int p = threadIdx.x, j = blockIdx.x;
    for (int t = p; t < 384; t += 128) {
        ct[t] = (float)cospi(2.0 * t / 384.0);
        st[t] = (float)sinpi(2.0 * t / 384.0);
    }
    __syncthreads();
    float sr = 0.0f, si = 0.0f;
    for (int n = 0; n < 384; n++) {
        int t = (j * n) % 384;
        float w = fre_w[n * 128 + p];
        sr += ct[t] * w; si -= st[t] * w;
    }
    g_Wr[j * 128 + p] = sr * (1.0f / 384.0f);
    g_Wi[j * 128 + p] = si * (1.0f / 384.0f);
}

__global__ void k_buildW(const float* __restrict__ comb_w) {
    int m = threadIdx.x, r = blockIdx.x;
    int k = r >> 8, cc = r & 255;
    int j = k * 128 + (cc & 127);
    const float* src = (cc < 128) ? g_Wr : g_Wi;
    float s = 0.0f;
    for (int p = 0; p < 128; p++) s += src[j * 128 + p] * comb_w[(2 * p) * 128 + m];
    g_W[r * 128 + m] = s;
    g_B2h[k * 32768 + m * 256 + cc] = __float2half_rn(s);
}

__global__ void k_buildCD(const float* __restrict__ fre_b, const float* __restrict__ comb_w,
                          const float* __restrict__ comb_b,
                          const float* __restrict__ rb1, const float* __restrict__ ib1) {
    int m = threadIdx.x;
    float s = 0.0f;
    for (int p = 0; p < 128; p++) s += fre_b[p] * comb_w[(2 * p) * 128 + m];
    g_cvec[m] = s + comb_b[m];
    for (int k = 0; k < NB; k++) {
        float d = 0.0f;
        for (int j0 = 0; j0 < 128; j0++) {
            float ar = fmaxf(rb1[k * 128 + j0] - LAM, 0.0f);
            float ai = fmaxf(ib1[k * 128 + j0] - LAM, 0.0f);
            d += ar * g_W[(k * 256 + j0) * 128 + m] + ai * g_W[(k * 256 + 128 + j0) * 128 + m];
        }
        g_dvec[k * 128 + m] = d;
    }
}

// ---------------- energy / mask / init ----------------
__global__ void k_nodenorm(const float* __restrict__ hidden) {
    int tid = threadIdx.x, w = tid >> 5, lane = tid & 31;
    if (blockIdx.x == 0) g_esum_part[tid] = 0.0f;   // re-zero each graph replay
    int n = blockIdx.x * 8 + w;
    const float* h = hidden + (size_t)n * DEMB;
    float s = 0.0f;
    #pragma unroll
    for (int i = 0; i < 4; i++) { float v = h[lane + 32 * i]; s += v * v; }
    #pragma unroll
    for (int off = 16; off; off >>= 1) s += __shfl_xor_sync(0xffffffffu, s, off);
    if (lane == 0) g_nodenorm[n] = s;
}

__global__ void k_energy(const float* __restrict__ ea, const float* __restrict__ ete,
                         const int* __restrict__ ei) {
    __shared__ float wsum[8];
    int tid = threadIdx.x, w = tid >> 5, lane = tid & 31;
    int e = blockIdx.x * 8 + w;
    float a = ea[(size_t)e * 32 + lane];
    float b = ete[(size_t)e * 32 + lane];
    float s = a * a + b * b;
    #pragma unroll
    for (int off = 16; off; off >>= 1) s += __shfl_xor_sync(0xffffffffu, s, off);
    if (lane == 0) { float en = 192.0f * (g_nodenorm[ei[e]] + s); g_energy[e] = en; wsum[w] = en; }
    __syncthreads();
    if (tid == 0) {
        float t = 0.0f;
        #pragma unroll
        for (int i = 0; i < 8; i++) t += wsum[i];
        atomicAdd(&g_esum_part[blockIdx.x & 255], t);
    }
}

__global__ void k_reduce_esum() {
    __shared__ float rs[8];
    int tid = threadIdx.x;
    float v = g_esum_part[tid];
    #pragma unroll
    for (int off = 16; off; off >>= 1) v += __shfl_xor_sync(0xffffffffu, v, off);
    if ((tid & 31) == 0) rs[tid >> 5] = v;
    __syncthreads();
    if (tid == 0) {
        float t = 0.0f;
        #pragma unroll
        for (int i = 0; i < 8; i++) t += rs[i];
        g_esum = t;
    }
}

__global__ void k_mask(const float* __restrict__ alpha) {
    int e = blockIdx.x * 256 + threadIdx.x;
    float en = g_energy[e], es = g_esum;
    unsigned char mb = 0;
    #pragma unroll
    for (int k = 0; k < NB; k++) {
        float al = alpha[k];
        float factor = (2.0f * (k + 1) - 1.0f) / (2.0f * NB);
        float Q = al * factor * es;
        float bnd = es / (al * (2.0f * NB));
        if (en >= Q - bnd && en <= Q + bnd) mb |= (1 << k);
    }
    g_maskb[e] = mb;
}

__global__ void k_initacc(const float* __restrict__ boundary) {
    const float4* s = (const float4*)boundary;
    float4* d = (float4*)g_acc;
    int n4 = NNODE * DEMB / 4;
    for (int i = blockIdx.x * blockDim.x + threadIdx.x; i < n4; i += gridDim.x * blockDim.x)
        d[i] = s[i];
}

// ---------------- main edge kernel (HMMA fp16, 64-edge tiles, 3 CTAs/SM) ----------------
// dynamic smem:
//   Xh  [64][200] @0      (25600)
//   actH[64][136] @25600  (17408)
//   staging [2 buf][128][40] @43008 (20480)
//   s_res fp32 [64][132] aliases @0 (post-GEMM only)
#define OFF_ACTH  25600
#define OFF_STG   43008
#define DYN_EDGE  63488

__global__ void __launch_bounds__(128, 3)
k_edge_mma(const float* __restrict__ hidden, const float* __restrict__ ea,
           const float* __restrict__ ete, const int* __restrict__ ei,
           const float* __restrict__ rb1, const float* __restrict__ ib1) {
    extern __shared__ char sb[];
    __half* s_xh = (__half*)sb;
    __half* s_ah = (__half*)(sb + OFF_ACTH);
    float*  s_res = (float*)sb;                  // [64][132], post-GEMM alias
    uint32_t dynb = smem_u32(sb);

    __shared__ int s_src[TE], s_dst[TE];
    __shared__ unsigned char s_mk[TE];
    __shared__ int s_any[NB];
    __shared__ float s_bias[256], s_base[128];

    int tid = threadIdx.x, lane = tid & 31, wid = tid >> 5;
    int eb = blockIdx.x * TE;

    if (tid < TE) {
        s_src[tid] = ei[eb + tid];
        s_dst[tid] = ei[NEDGE + eb + tid];
        s_mk[tid]  = g_maskb[eb + tid];
    }
    __syncthreads();
    if (tid < NB) {
        int a = 0;
        for (int e = 0; e < TE; e++) a |= (s_mk[e] >> tid) & 1;
        s_any[tid] = a;
    }
    __syncthreads();
    {
        float b = g_cvec[tid];
        #pragma unroll
        for (int k = 0; k < NB; k++) if (!s_any[k]) b += g_dvec[k * 128 + tid];
        s_base[tid] = b;
    }
    bool anyband = s_any[0] || s_any[1] || s_any[2];

    // fragment geometry: 4 warps = 2m x 2n
    int m0 = (wid & 1) * 32, n0 = (wid >> 1) * 64;
    int rowA = ((lane >> 3) & 1) * 8 + (lane & 7);
    int colA = ((lane >> 4) & 1) * 8;
    int rowB = ((lane >> 4) & 1) * 8 + (lane & 7);
    int colB = ((lane >> 3) & 1) * 8;
    uint32_t stgDst = dynb + OFF_STG + (uint32_t)(tid * 80);

    float acc2[2][8][4];
    #pragma unroll
    for (int i = 0; i < 2; i++)
        #pragma unroll
        for (int j = 0; j < 8; j++)
            #pragma unroll
            for (int q = 0; q < 4; q++) acc2[i][j][q] = 0.0f;

    if (anyband) {
        // ---- gather X tile, round to fp16 ----
        for (int idx = tid; idx < TE * 48; idx += 128) {
            int r = idx / 48, q = idx - r * 48;
            float4 v;
            if (q < 32)      v = ((const float4*)(hidden + (size_t)s_src[r] * DEMB))[q];
            else if (q < 40) v = ((const float4*)(ea + (size_t)(eb + r) * 32))[q - 32];
            else             v = ((const float4*)(ete + (size_t)(eb + r) * 32))[q - 40];
            __half2* ph = (__half2*)(s_xh + r * 200 + q * 4);
            ph[0] = __floats2half2_rn(v.x, v.y);
            ph[1] = __floats2half2_rn(v.z, v.w);
        }

        // segment list: (band,hh) pairs
        int segBand[NB]; int nseg = 0;
        #pragma unroll
        for (int k = 0; k < NB; k++) if (s_any[k]) segBand[nseg++] = k;
        int totseg = nseg * 2;

        // prefetch segment 0 GEMM1 chunk 0 into buf0
        stage_chunk(stgDst, g_B1h + ((size_t)segBand[0] * 256 + tid) * 192);
        CP_COMMIT();

        for (int s = 0; s < totseg; s++) {
            int band = segBand[s >> 1], hh = s & 1;
            if (hh == 0) {
                s_bias[tid]       = rb1[band * 128 + tid];
                s_bias[tid + 128] = ib1[band * 128 + tid];
            }
            const __half* g1h = g_B1h + ((size_t)band * 256 + hh * 128 + tid) * 192;
            const __half* g2h = g_B2h + (size_t)band * 32768 + (size_t)tid * 256 + hh * 128;

            float acc1[2][8][4];
            #pragma unroll
            for (int i = 0; i < 2; i++)
                #pragma unroll
                for (int j = 0; j < 8; j++)
                    #pragma unroll
                    for (int q = 0; q < 4; q++) acc1[i][j][q] = 0.0f;

            // ---- GEMM1: 6 K-chunks ----
            #pragma unroll 1
            for (int c = 0; c < 6; c++) {
                CP_WAIT0();
                __syncthreads();
                if (c < 5) stage_chunk(stgDst + ((c + 1) & 1) * 10240, g1h + (c + 1) * 32);
                else       stage_chunk(stgDst, g2h);   // GEMM2 chunk 0 -> buf0
                CP_COMMIT();
                uint32_t xh = dynb + (uint32_t)((m0 + rowA) * 400 + (c * 32 + colA) * 2);
                uint32_t bh = dynb + OFF_STG + (c & 1) * 10240 + (uint32_t)((n0 + rowB) * 80 + colB * 2);
                chunk1(acc1, xh, 400u, bh);
            }

            // ---- activation -> act fp16 ----
            #pragma unroll
            for (int mt = 0; mt < 2; mt++) {
                int r0 = m0 + mt * 16 + (lane >> 2);
                float mk0 = (float)((s_mk[r0] >> band) & 1);
                float mk1 = (float)((s_mk[r0 + 8] >> band) & 1);
                #pragma unroll
                for (int nt = 0; nt < 8; nt++) {
                    int cb = n0 + nt * 8 + (lane & 3) * 2;
                    float b0 = s_bias[hh * 128 + cb], b1 = s_bias[hh * 128 + cb + 1];
                    float a00 = fmaxf(fmaf(mk0, acc1[mt][nt][0], b0) - LAM, 0.0f);
                    float a01 = fmaxf(fmaf(mk0, acc1[mt][nt][1], b1) - LAM, 0.0f);
                    float a10 = fmaxf(fmaf(mk1, acc1[mt][nt][2], b0) - LAM, 0.0f);
                    float a11 = fmaxf(fmaf(mk1, acc1[mt][nt][3], b1) - LAM, 0.0f);
                    *(__half2*)(s_ah + r0 * 136 + cb)       = __floats2half2_rn(a00, a01);
                    *(__half2*)(s_ah + (r0 + 8) * 136 + cb) = __floats2half2_rn(a10, a11);
                }
            }

            // ---- GEMM2: 4 K-chunks ----
            #pragma unroll 1
            for (int c = 0; c < 4; c++) {
                CP_WAIT0();
                __syncthreads();          // publishes act + staged chunk
                if (c < 3) stage_chunk(stgDst + ((c + 1) & 1) * 10240, g2h + (c + 1) * 32);
                else if (s + 1 < totseg) {
                    int nb = segBand[(s + 1) >> 1], nhh = (s + 1) & 1;
                    stage_chunk(stgDst, g_B1h + ((size_t)nb * 256 + nhh * 128 + tid) * 192);
                }
                CP_COMMIT();
                uint32_t ah = dynb + OFF_ACTH + (uint32_t)((m0 + rowA) * 272 + (c * 32 + colA) * 2);
                uint32_t bh = dynb + OFF_STG + (c & 1) * 10240 + (uint32_t)((n0 + rowB) * 80 + colB * 2);
                chunk1(acc2, ah, 272u, bh);
            }
        }
    }

    // ---- stage msg2 into smem (aliases X/act region) and scatter ----
    __syncthreads();
    if (anyband) {
        #pragma unroll
        for (int mt = 0; mt < 2; mt++) {
            int r0 = m0 + mt * 16 + (lane >> 2);
            #pragma unroll
            for (int nt = 0; nt < 8; nt++) {
                int cb = n0 + nt * 8 + (lane & 3) * 2;
                *(float2*)(s_res + r0 * 132 + cb)       = make_float2(acc2[mt][nt][0], acc2[mt][nt][1]);
                *(float2*)(s_res + (r0 + 8) * 132 + cb) = make_float2(acc2[mt][nt][2], acc2[mt][nt][3]);
            }
        }
    }
    __syncthreads();
    {
        int row = tid >> 1, cb = (tid & 1) * 64;
        int dst = s_dst[row];
        float* p = g_acc + (size_t)dst * DEMB + cb;
        #pragma unroll
        for (int j = 0; j < 16; j++) {
            int c = cb + 4 * j;
            float x0 = s_base[c], x1 = s_base[c + 1], x2 = s_base[c + 2], x3 = s_base[c + 3];
            if (anyband) {
                x0 += s_res[row * 132 + c];     x1 += s_res[row * 132 + c + 1];
                x2 += s_res[row * 132 + c + 2]; x3 += s_res[row * 132 + c + 3];
            }
            asm volatile("red.global.add.v4.f32 [%0], {%1,%2,%3,%4};"
                         :: "l"(p + 4 * j), "f"(x0), "f"(x1), "f"(x2), "f"(x3) : "memory");
        }
    }
}

// ---------------- node epilogue (32 nodes/block, fused pair, guarded) ----------------
#define SMEM_FINAL ((128 * 128 + 32 * 128) * 4)

__global__ void __launch_bounds__(256, 1)
k_final(const float* __restrict__ lin_w, const float* __restrict__ lin_b,
        const float* __restrict__ ln_g, const float* __restrict__ ln_b,
        float* __restrict__ out) {
    extern __shared__ float sm[];
    float* lw = sm;
    float* at = sm + 128 * 128;
    int tid = threadIdx.x;
    int n0 = blockIdx.x * 32;
    int nvalid = NNODE - n0; if (nvalid > 32) nvalid = 32;

    for (int idx = tid; idx < 128 * 128; idx += 256) lw[idx] = lin_w[idx];
    for (int idx = tid; idx < nvalid * 128; idx += 256) at[idx] = g_acc[(size_t)n0 * DEMB + idx];
    __syncthreads();

    int m0 = (tid & 15) * 8;
    int i0 = tid >> 4, i1 = i0 + 16;
    float t0[8], t1[8];
    #pragma unroll
    for (int j = 0; j < 8; j++) { t0[j] = lin_b[m0 + j]; t1[j] = t0[j]; }
    const float* ar0 = at + i0 * 128;
    const float* ar1 = at + i1 * 128;
    bool v1 = (i1 < nvalid);
    for (int q = 0; q < 128; q++) {
        float4 w1 = *(const float4*)&lw[q * 128 + m0];
        float4 w2 = *(const float4*)&lw[q * 128 + m0 + 4];
        float a0 = ar0[q];
        float a1 = v1 ? ar1[q] : 0.0f;
        t0[0] = fmaf(a0, w1.x, t0[0]); t0[1] = fmaf(a0, w1.y, t0[1]);
        t0[2] = fmaf(a0, w1.z, t0[2]); t0[3] = fmaf(a0, w1.w, t0[3]);
        t0[4] = fmaf(a0, w2.x, t0[4]); t0[5] = fmaf(a0, w2.y, t0[5]);
        t0[6] = fmaf(a0, w2.z, t0[6]); t0[7] = fmaf(a0, w2.w, t0[7]);
        t1[0] = fmaf(a1, w1.x, t1[0]); t1[1] = fmaf(a1, w1.y, t1[1]);
        t1[2] = fmaf(a1, w1.z, t1[2]); t1[3] = fmaf(a1, w1.w, t1[3]);
        t1[4] = fmaf(a1, w2.x, t1[4]); t1[5] = fmaf(a1, w2.y, t1[5]);
        t1[6] = fmaf(a1, w2.z, t1[6]); t1[7] = fmaf(a1, w2.w, t1[7]);
    }
    {
        float s1 = 0.0f;
        #pragma unroll
        for (int j = 0; j < 8; j++) s1 += t0[j];
        #pragma unroll
        for (int off = 8; off; off >>= 1) s1 += __shfl_xor_sync(0xffffffffu, s1, off, 16);
        float mu = s1 * (1.0f / 128.0f);
        float s2 = 0.0f;
        #pragma unroll
        for (int j = 0; j < 8; j++) { float d = t0[j] - mu; s2 += d * d; }
        #pragma unroll
        for (int off = 8; off; off >>= 1) s2 += __shfl_xor_sync(0xffffffffu, s2, off, 16);
        float inv = rsqrtf(s2 * (1.0f / 128.0f) + LNEPS);
        if (i0 < nvalid) {
            #pragma unroll
            for (int j = 0; j < 8; j++) {
                int m = m0 + j;
                float y = (t0[j] - mu) * inv * ln_g[m] + ln_b[m];
                out[(size_t)(n0 + i0) * DEMB + m] = fmaxf(y, 0.0f);
            }
        }
    }
    {
        float s1 = 0.0f;
        #pragma unroll
        for (int j = 0; j < 8; j++) s1 += t1[j];
        #pragma unroll
        for (int off = 8; off; off >>= 1) s1 += __shfl_xor_sync(0xffffffffu, s1, off, 16);
        float mu = s1 * (1.0f / 128.0f);
        float s2 = 0.0f;
        #pragma unroll
        for (int j = 0; j < 8; j++) { float d = t1[j] - mu; s2 += d * d; }
        #pragma unroll
        for (int off = 8; off; off >>= 1) s2 += __shfl_xor_sync(0xffffffffu, s2, off, 16);
        float inv = rsqrtf(s2 * (1.0f / 128.0f) + LNEPS);
        if (v1) {
            #pragma unroll
            for (int j = 0; j < 8; j++) {
                int m = m0 + j;
                float y = (t1[j] - mu) * inv * ln_g[m] + ln_b[m];
                out[(size_t)(n0 + i1) * DEMB + m] = fmaxf(y, 0.0f);
            }
        }
    }
}

// ---------------- launcher ----------------
extern "C" void kernel_launch(void* const* d_in, const int* in_sizes, int n_in,
                              void* d_out, int out_size) {
    const float* hidden   = (const float*)d_in[0];
    const float* edge_attr= (const float*)d_in[1];
    const float* ete      = (const float*)d_in[2];
    const float* boundary = (const float*)d_in[3];
    const float* alpha    = (const float*)d_in[4];
    const float* r1       = (const float*)d_in[5];
    const float* i1       = (const float*)d_in[6];
    const float* rb1      = (const float*)d_in[7];
    const float* ib1      = (const float*)d_in[8];
    const float* fre_w    = (const float*)d_in[9];
    const float* fre_b    = (const float*)d_in[10];
    const float* comb_w   = (const float*)d_in[11];
    const float* comb_b   = (const float*)d_in[12];
    const float* lin_w    = (const float*)d_in[13];
    const float* lin_b    = (const float*)d_in[14];
    const float* ln_g     = (const float*)d_in[15];
    const float* ln_b     = (const float*)d_in[16];
    const int*   ei       = (const int*)d_in[17];
    float* out = (float*)d_out;

    cudaFuncSetAttribute(k_edge_mma, cudaFuncAttributeMaxDynamicSharedMemorySize, DYN_EDGE);
    cudaFuncSetAttribute(k_final,    cudaFuncAttributeMaxDynamicSharedMemorySize, SMEM_FINAL);

    k_buildA<<<768, 192>>>(r1, i1);
    k_buildWrWi<<<384, 128>>>(fre_w);
    k_buildW<<<768, 128>>>(comb_w);
    k_buildCD<<<1, 128>>>(fre_b, comb_w, comb_b, rb1, ib1);
    k_nodenorm<<<NNODE / 8, 256>>>(hidden);
    k_energy<<<NEDGE / 8, 256>>>(edge_attr, ete, ei);
    k_reduce_esum<<<1, 256>>>();
    k_mask<<<NEDGE / 256, 256>>>(alpha);
    k_initacc<<<3125, 256>>>(boundary);
    k_edge_mma<<<NT, 128, DYN_EDGE>>>(hidden, edge_attr, ete, ei, rb1, ib1);
    k_final<<<(NNODE + 31) / 32, 256, SMEM_FINAL>>>(lin_w, lin_b, ln_g, ln_b, out);
}

// round 11
// speedup vs baseline: 7.3113x; 1.1160x over previous
#include <cuda_runtime.h>
#include <cuda_fp16.h>
#include <math.h>
#include <stdint.h>

// Problem constants
#define NNODE 50000
#define NEDGE 320000
#define DEMB  128
#define DIN   192
#define NB    3
#define LAM   0.01f
#define LNEPS 1e-5f

#define TE    64
#define NT    (NEDGE / TE)        // 5000

// ---------------- device scratch ----------------
__device__ float g_Wr[384 * 128];
__device__ float g_Wi[384 * 128];
__device__ float g_W[768 * 128];
__device__ float g_cvec[128];
__device__ float g_dvec[NB * 128];
__device__ float g_nodenorm[NNODE];
__device__ float g_energy[NEDGE];
__device__ float g_esum_part[256];
__device__ float g_esum;
__device__ unsigned char g_maskb[NEDGE];
__device__ float g_acc[NNODE * DEMB];

// fp16 transposed operands: B1[band][n(256)][k(192)], B2[band][m(128)][c(256)]
__device__ __align__(16) __half g_B1h[NB * 256 * 192];
__device__ __align__(16) __half g_B2h[NB * 128 * 256];

// ---------------- helpers ----------------
__device__ __forceinline__ uint32_t smem_u32(const void* p) {
    uint32_t a;
    asm("{ .reg .u64 t; cvta.to.shared.u64 t, %1; cvt.u32.u64 %0, t; }" : "=r"(a) : "l"(p));
    return a;
}

#define LDSM4(R, addr) \
    asm volatile("ldmatrix.sync.aligned.m8n8.x4.shared.b16 {%0,%1,%2,%3}, [%4];" \
        : "=r"((R)[0]), "=r"((R)[1]), "=r"((R)[2]), "=r"((R)[3]) : "r"(addr))

#define MMA16816(C, A, B0, B1) \
    asm volatile("mma.sync.aligned.m16n8k16.row.col.f32.f16.f16.f32 " \
        "{%0,%1,%2,%3}, {%4,%5,%6,%7}, {%8,%9}, {%0,%1,%2,%3};" \
        : "+f"((C)[0]), "+f"((C)[1]), "+f"((C)[2]), "+f"((C)[3]) \
        : "r"((A)[0]), "r"((A)[1]), "r"((A)[2]), "r"((A)[3]), "r"(B0), "r"(B1))

#define CP_COMMIT() asm volatile("cp.async.commit_group;" ::: "memory")
#define CP_WAIT0()  asm volatile("cp.async.wait_group 0;" ::: "memory")

// stage one 32-K chunk's B slice (8KB across 128 threads; 64B per thread = 1 row)
__device__ __forceinline__ void stage_chunk(uint32_t dst, const __half* src) {
    asm volatile(
        "cp.async.cg.shared.global [%0], [%4], 16;\n\t"
        "cp.async.cg.shared.global [%1], [%5], 16;\n\t"
        "cp.async.cg.shared.global [%2], [%6], 16;\n\t"
        "cp.async.cg.shared.global [%3], [%7], 16;\n\t"
        :: "r"(dst), "r"(dst + 16), "r"(dst + 32), "r"(dst + 48),
           "l"(src), "l"(src + 8), "l"(src + 16), "l"(src + 24) : "memory");
}

// one K=32 chunk, single fp16 term; warp computes 32 rows x 64 cols
__device__ __forceinline__ void chunk1(float (&acc)[2][8][4],
                                       uint32_t aAddr, uint32_t aStride, uint32_t bAddr) {
    #pragma unroll
    for (int k16 = 0; k16 < 32; k16 += 16) {
        uint32_t a0[4], a1[4], b[4][4];
        LDSM4(a0, aAddr + k16 * 2);
        LDSM4(a1, aAddr + 16 * aStride + k16 * 2);
        #pragma unroll
        for (int ntp = 0; ntp < 4; ntp++) LDSM4(b[ntp], bAddr + ntp * 16 * 80 + k16 * 2);
        #pragma unroll
        for (int ntp = 0; ntp < 4; ntp++) {
            MMA16816(acc[0][2 * ntp],     a0, b[ntp][0], b[ntp][1]);
            MMA16816(acc[0][2 * ntp + 1], a0, b[ntp][2], b[ntp][3]);
            MMA16816(acc[1][2 * ntp],     a1, b[ntp][0], b[ntp][1]);
            MMA16816(acc[1][2 * ntp + 1], a1, b[ntp][2], b[ntp][3]);
        }
    }
}

// ---------------- precompute ----------------
__global__ void k_buildA(const float* __restrict__ r1, const float* __restrict__ i1) {
    __shared__ float ct[192], st[192];
    int n = threadIdx.x, c = blockIdx.x;
    ct[n] = (float)cospi(2.0 * n / 192.0);
    st[n] = (float)sinpi(2.0 * n / 192.0);
    __syncthreads();
    int k = c >> 8, cc = c & 255;
    const float* R = r1 + k * DIN * DEMB;
    const float* I = i1 + k * DIN * DEMB;
    float s = 0.0f;
    if (cc < 128) {
        int m = cc;
        for (int j = 0; j < 192; j++) { int t = (j * n) % 192; s += ct[t] * R[j * DEMB + m] + st[t] * I[j * DEMB + m]; }
    } else {
        int m = cc - 128;
        for (int j = 0; j < 192; j++) { int t = (j * n) % 192; s += ct[t] * I[j * DEMB + m] - st[t] * R[j * DEMB + m]; }
    }
    g_B1h[c * 192 + n] = __float2half_rn(s);
}

__global__ void k_buildWrWi(const float* __restrict__ fre_w) {
    __shared__ float ct[384], st[384];
    int p = threadIdx.x, j = blockIdx.x;
    for (int t = p; t < 384; t += 128) {
        ct[t] = (float)cospi(2.0 * t / 384.0);
        st[t] = (float)sinpi(2.0 * t / 384.0);
    }
    __syncthreads();
    float sr = 0.0f, si = 0.0f;
    for (int n = 0; n < 384; n++) {
        int t = (j * n) % 384;
        float w = fre_w[n * 128 + p];
        sr += ct[t] * w; si -= st[t] * w;
    }
    g_Wr[j * 128 + p] = sr * (1.0f / 384.0f);
    g_Wi[j * 128 + p] = si * (1.0f / 384.0f);
}

__global__ void k_buildW(const float* __restrict__ comb_w) {
    int m = threadIdx.x, r = blockIdx.x;
    int k = r >> 8, cc = r & 255;
    int j = k * 128 + (cc & 127);
    const float* src = (cc < 128) ? g_Wr : g_Wi;
    float s = 0.0f;
    for (int p = 0; p < 128; p++) s += src[j * 128 + p] * comb_w[(2 * p) * 128 + m];
    g_W[r * 128 + m] = s;
    g_B2h[k * 32768 + m * 256 + cc] = __float2half_rn(s);
}

// parallel: blocks 0..383 -> dvec[k][m], blocks 384..511 -> cvec[m]; 128-way reduce
__global__ void k_buildCD(const float* __restrict__ fre_b, const float* __restrict__ comb_w,
                          const float* __restrict__ comb_b,
                          const float* __restrict__ rb1, const float* __restrict__ ib1) {
    __shared__ float red[4];
    int b = blockIdx.x, tid = threadIdx.x, lane = tid & 31, wid = tid >> 5;
    float v;
    if (b < 384) {
        int k = b >> 7, m = b & 127, j0 = tid;
        float ar = fmaxf(rb1[k * 128 + j0] - LAM, 0.0f);
        float ai = fmaxf(ib1[k * 128 + j0] - LAM, 0.0f);
        v = ar * g_W[(k * 256 + j0) * 128 + m] + ai * g_W[(k * 256 + 128 + j0) * 128 + m];
    } else {
        int m = b - 384;
        v = fre_b[tid] * comb_w[(2 * tid) * 128 + m];
    }
    #pragma unroll
    for (int off = 16; off; off >>= 1) v += __shfl_xor_sync(0xffffffffu, v, off);
    if (lane == 0) red[wid] = v;
    __syncthreads();
    if (tid == 0) {
        float t = red[0] + red[1] + red[2] + red[3];
        if (b < 384) g_dvec[(b >> 7) * 128 + (b & 127)] = t;
        else         g_cvec[b - 384] = t + comb_b[b - 384];
    }
}

// ---------------- energy / mask / init ----------------
__global__ void k_nodenorm(const float* __restrict__ hidden) {
    int tid = threadIdx.x, w = tid >> 5, lane = tid & 31;
    if (blockIdx.x == 0) g_esum_part[tid] = 0.0f;   // re-zero each graph replay
    int n = blockIdx.x * 8 + w;
    const float* h = hidden + (size_t)n * DEMB;
    float s = 0.0f;
    #pragma unroll
    for (int i = 0; i < 4; i++) { float v = h[lane + 32 * i]; s += v * v; }
    #pragma unroll
    for (int off = 16; off; off >>= 1) s += __shfl_xor_sync(0xffffffffu, s, off);
    if (lane == 0) g_nodenorm[n] = s;
}

__global__ void k_energy(const float* __restrict__ ea, const float* __restrict__ ete,
                         const int* __restrict__ ei) {
    __shared__ float wsum[8];
    int tid = threadIdx.x, w = tid >> 5, lane = tid & 31;
    int e = blockIdx.x * 8 + w;
    float a = ea[(size_t)e * 32 + lane];
    float b = ete[(size_t)e * 32 + lane];
    float s = a * a + b * b;
    #pragma unroll
    for (int off = 16; off; off >>= 1) s += __shfl_xor_sync(0xffffffffu, s, off);
    if (lane == 0) { float en = 192.0f * (g_nodenorm[ei[e]] + s); g_energy[e] = en; wsum[w] = en; }
    __syncthreads();
    if (tid == 0) {
        float t = 0.0f;
        #pragma unroll
        for (int i = 0; i < 8; i++) t += wsum[i];
        atomicAdd(&g_esum_part[blockIdx.x & 255], t);
    }
}

__global__ void k_reduce_esum() {
    __shared__ float rs[8];
    int tid = threadIdx.x;
    float v = g_esum_part[tid];
    #pragma unroll
    for (int off = 16; off; off >>= 1) v += __shfl_xor_sync(0xffffffffu, v, off);
    if ((tid & 31) == 0) rs[tid >> 5] = v;
    __syncthreads();
    if (tid == 0) {
        float t = 0.0f;
        #pragma unroll
        for (int i = 0; i < 8; i++) t += rs[i];
        g_esum = t;
    }
}

__global__ void k_mask(const float* __restrict__ alpha) {
    int e = blockIdx.x * 256 + threadIdx.x;
    float en = g_energy[e], es = g_esum;
    unsigned char mb = 0;
    #pragma unroll
    for (int k = 0; k < NB; k++) {
        float al = alpha[k];
        float factor = (2.0f * (k + 1) - 1.0f) / (2.0f * NB);
        float Q = al * factor * es;
        float bnd = es / (al * (2.0f * NB));
        if (en >= Q - bnd && en <= Q + bnd) mb |= (1 << k);
    }
    g_maskb[e] = mb;
}

__global__ void k_initacc(const float* __restrict__ boundary) {
    const float4* s = (const float4*)boundary;
    float4* d = (float4*)g_acc;
    int n4 = NNODE * DEMB / 4;
    for (int i = blockIdx.x * blockDim.x + threadIdx.x; i < n4; i += gridDim.x * blockDim.x)
        d[i] = s[i];
}

// ---------------- main edge kernel (HMMA fp16, 64-edge tiles, 3 CTAs/SM) ----------------
// dynamic smem:
//   Xh  [64][200] @0      (25600)
//   actH[64][136] @25600  (17408)
//   staging [2 buf][128][40] @43008 (20480)
//   s_res fp32 [64][132] aliases @0 (post-GEMM only)
#define OFF_ACTH  25600
#define OFF_STG   43008
#define DYN_EDGE  63488

__global__ void __launch_bounds__(128, 3)
k_edge_mma(const float* __restrict__ hidden, const float* __restrict__ ea,
           const float* __restrict__ ete, const int* __restrict__ ei,
           const float* __restrict__ rb1, const float* __restrict__ ib1) {
    extern __shared__ char sb[];
    __half* s_xh = (__half*)sb;
    __half* s_ah = (__half*)(sb + OFF_ACTH);
    float*  s_res = (float*)sb;                  // [64][132], post-GEMM alias
    uint32_t dynb = smem_u32(sb);

    __shared__ int s_src[TE], s_dst[TE];
    __shared__ unsigned char s_mk[TE];
    __shared__ int s_any[NB];
    __shared__ float s_bias[256], s_base[128];

    int tid = threadIdx.x, lane = tid & 31, wid = tid >> 5;
    int eb = blockIdx.x * TE;

    if (tid < TE) {
        s_src[tid] = ei[eb + tid];
        s_dst[tid] = ei[NEDGE + eb + tid];
        s_mk[tid]  = g_maskb[eb + tid];
    }
    __syncthreads();
    if (tid < NB) {
        int a = 0;
        for (int e = 0; e < TE; e++) a |= (s_mk[e] >> tid) & 1;
        s_any[tid] = a;
    }
    __syncthreads();
    {
        float b = g_cvec[tid];
        #pragma unroll
        for (int k = 0; k < NB; k++) if (!s_any[k]) b += g_dvec[k * 128 + tid];
        s_base[tid] = b;
    }
    bool anyband = s_any[0] || s_any[1] || s_any[2];

    // fragment geometry: 4 warps = 2m x 2n
    int m0 = (wid & 1) * 32, n0 = (wid >> 1) * 64;
    int rowA = ((lane >> 3) & 1) * 8 + (lane & 7);
    int colA = ((lane >> 4) & 1) * 8;
    int rowB = ((lane >> 4) & 1) * 8 + (lane & 7);
    int colB = ((lane >> 3) & 1) * 8;
    uint32_t stgDst = dynb + OFF_STG + (uint32_t)(tid * 80);

    float acc2[2][8][4];
    #pragma unroll
    for (int i = 0; i < 2; i++)
        #pragma unroll
        for (int j = 0; j < 8; j++)
            #pragma unroll
            for (int q = 0; q < 4; q++) acc2[i][j][q] = 0.0f;

    if (anyband) {
        // ---- gather X tile, round to fp16 ----
        for (int idx = tid; idx < TE * 48; idx += 128) {
            int r = idx / 48, q = idx - r * 48;
            float4 v;
            if (q < 32)      v = ((const float4*)(hidden + (size_t)s_src[r] * DEMB))[q];
            else if (q < 40) v = ((const float4*)(ea + (size_t)(eb + r) * 32))[q - 32];
            else             v = ((const float4*)(ete + (size_t)(eb + r) * 32))[q - 40];
            __half2* ph = (__half2*)(s_xh + r * 200 + q * 4);
            ph[0] = __floats2half2_rn(v.x, v.y);
            ph[1] = __floats2half2_rn(v.z, v.w);
        }

        // segment list: (band,hh) pairs
        int segBand[NB]; int nseg = 0;
        #pragma unroll
        for (int k = 0; k < NB; k++) if (s_any[k]) segBand[nseg++] = k;
        int totseg = nseg * 2;

        // prefetch segment 0 GEMM1 chunk 0 into buf0
        stage_chunk(stgDst, g_B1h + ((size_t)segBand[0] * 256 + tid) * 192);
        CP_COMMIT();

        for (int s = 0; s < totseg; s++) {
            int band = segBand[s >> 1], hh = s & 1;
            if (hh == 0) {
                s_bias[tid]       = rb1[band * 128 + tid];
                s_bias[tid + 128] = ib1[band * 128 + tid];
            }
            const __half* g1h = g_B1h + ((size_t)band * 256 + hh * 128 + tid) * 192;
            const __half* g2h = g_B2h + (size_t)band * 32768 + (size_t)tid * 256 + hh * 128;

            float acc1[2][8][4];
            #pragma unroll
            for (int i = 0; i < 2; i++)
                #pragma unroll
                for (int j = 0; j < 8; j++)
                    #pragma unroll
                    for (int q = 0; q < 4; q++) acc1[i][j][q] = 0.0f;

            // ---- GEMM1: 6 K-chunks ----
            #pragma unroll 1
            for (int c = 0; c < 6; c++) {
                CP_WAIT0();
                __syncthreads();
                if (c < 5) stage_chunk(stgDst + ((c + 1) & 1) * 10240, g1h + (c + 1) * 32);
                else       stage_chunk(stgDst, g2h);   // GEMM2 chunk 0 -> buf0
                CP_COMMIT();
                uint32_t xh = dynb + (uint32_t)((m0 + rowA) * 400 + (c * 32 + colA) * 2);
                uint32_t bh = dynb + OFF_STG + (c & 1) * 10240 + (uint32_t)((n0 + rowB) * 80 + colB * 2);
                chunk1(acc1, xh, 400u, bh);
            }

            // ---- activation -> act fp16 ----
            #pragma unroll
            for (int mt = 0; mt < 2; mt++) {
                int r0 = m0 + mt * 16 + (lane >> 2);
                float mk0 = (float)((s_mk[r0] >> band) & 1);
                float mk1 = (float)((s_mk[r0 + 8] >> band) & 1);
                #pragma unroll
                for (int nt = 0; nt < 8; nt++) {
                    int cb = n0 + nt * 8 + (lane & 3) * 2;
                    float b0 = s_bias[hh * 128 + cb], b1 = s_bias[hh * 128 + cb + 1];
                    float a00 = fmaxf(fmaf(mk0, acc1[mt][nt][0], b0) - LAM, 0.0f);
                    float a01 = fmaxf(fmaf(mk0, acc1[mt][nt][1], b1) - LAM, 0.0f);
                    float a10 = fmaxf(fmaf(mk1, acc1[mt][nt][2], b0) - LAM, 0.0f);
                    float a11 = fmaxf(fmaf(mk1, acc1[mt][nt][3], b1) - LAM, 0.0f);
                    *(__half2*)(s_ah + r0 * 136 + cb)       = __floats2half2_rn(a00, a01);
                    *(__half2*)(s_ah + (r0 + 8) * 136 + cb) = __floats2half2_rn(a10, a11);
                }
            }

            // ---- GEMM2: 4 K-chunks ----
            #pragma unroll 1
            for (int c = 0; c < 4; c++) {
                CP_WAIT0();
                __syncthreads();          // publishes act + staged chunk
                if (c < 3) stage_chunk(stgDst + ((c + 1) & 1) * 10240, g2h + (c + 1) * 32);
                else if (s + 1 < totseg) {
                    int nb = segBand[(s + 1) >> 1], nhh = (s + 1) & 1;
                    stage_chunk(stgDst, g_B1h + ((size_t)nb * 256 + nhh * 128 + tid) * 192);
                }
                CP_COMMIT();
                uint32_t ah = dynb + OFF_ACTH + (uint32_t)((m0 + rowA) * 272 + (c * 32 + colA) * 2);
                uint32_t bh = dynb + OFF_STG + (c & 1) * 10240 + (uint32_t)((n0 + rowB) * 80 + colB * 2);
                chunk1(acc2, ah, 272u, bh);
            }
        }
    }

    // ---- stage msg2 into smem (aliases X/act region) and scatter ----
    __syncthreads();
    if (anyband) {
        #pragma unroll
        for (int mt = 0; mt < 2; mt++) {
            int r0 = m0 + mt * 16 + (lane >> 2);
            #pragma unroll
            for (int nt = 0; nt < 8; nt++) {
                int cb = n0 + nt * 8 + (lane & 3) * 2;
                *(float2*)(s_res + r0 * 132 + cb)       = make_float2(acc2[mt][nt][0], acc2[mt][nt][1]);
                *(float2*)(s_res + (r0 + 8) * 132 + cb) = make_float2(acc2[mt][nt][2], acc2[mt][nt][3]);
            }
        }
    }
    __syncthreads();
    {
        int row = tid >> 1, cb = (tid & 1) * 64;
        int dst = s_dst[row];
        float* p = g_acc + (size_t)dst * DEMB + cb;
        #pragma unroll
        for (int j = 0; j < 16; j++) {
            int c = cb + 4 * j;
            float x0 = s_base[c], x1 = s_base[c + 1], x2 = s_base[c + 2], x3 = s_base[c + 3];
            if (anyband) {
                x0 += s_res[row * 132 + c];     x1 += s_res[row * 132 + c + 1];
                x2 += s_res[row * 132 + c + 2]; x3 += s_res[row * 132 + c + 3];
            }
            asm volatile("red.global.add.v4.f32 [%0], {%1,%2,%3,%4};"
                         :: "l"(p + 4 * j), "f"(x0), "f"(x1), "f"(x2), "f"(x3) : "memory");
        }
    }
}

// ---------------- node epilogue (64 nodes/block, 4 per thread-group, guarded) ----------------
#define SMEM_FINAL ((128 * 128 + 64 * 128) * 4)

__global__ void __launch_bounds__(256, 1)
k_final(const float* __restrict__ lin_w, const float* __restrict__ lin_b,
        const float* __restrict__ ln_g, const float* __restrict__ ln_b,
        float* __restrict__ out) {
    extern __shared__ float sm[];
    float* lw = sm;
    float* at = sm + 128 * 128;
    int tid = threadIdx.x;
    int n0 = blockIdx.x * 64;
    int nvalid = NNODE - n0; if (nvalid > 64) nvalid = 64;

    for (int idx = tid; idx < 128 * 128; idx += 256) lw[idx] = lin_w[idx];
    for (int idx = tid; idx < nvalid * 128; idx += 256) at[idx] = g_acc[(size_t)n0 * DEMB + idx];
    __syncthreads();

    int m0 = (tid & 15) * 8;
    int ib = tid >> 4;                 // 0..15
    float t[4][8];
    #pragma unroll
    for (int g = 0; g < 4; g++)
        #pragma unroll
        for (int j = 0; j < 8; j++) t[g][j] = lin_b[m0 + j];
    const float* ar0 = at + ib * 128;
    bool v1 = (ib + 16 < nvalid), v2 = (ib + 32 < nvalid), v3 = (ib + 48 < nvalid);
    for (int q = 0; q < 128; q++) {
        float4 w1 = *(const float4*)&lw[q * 128 + m0];
        float4 w2 = *(const float4*)&lw[q * 128 + m0 + 4];
        float a0 = ar0[q];
        float a1 = v1 ? ar0[16 * 128 + q] : 0.0f;
        float a2 = v2 ? ar0[32 * 128 + q] : 0.0f;
        float a3 = v3 ? ar0[48 * 128 + q] : 0.0f;
        t[0][0] = fmaf(a0, w1.x, t[0][0]); t[0][1] = fmaf(a0, w1.y, t[0][1]);
        t[0][2] = fmaf(a0, w1.z, t[0][2]); t[0][3] = fmaf(a0, w1.w, t[0][3]);
        t[0][4] = fmaf(a0, w2.x, t[0][4]); t[0][5] = fmaf(a0, w2.y, t[0][5]);
        t[0][6] = fmaf(a0, w2.z, t[0][6]); t[0][7] = fmaf(a0, w2.w, t[0][7]);
        t[1][0] = fmaf(a1, w1.x, t[1][0]); t[1][1] = fmaf(a1, w1.y, t[1][1]);
        t[1][2] = fmaf(a1, w1.z, t[1][2]); t[1][3] = fmaf(a1, w1.w, t[1][3]);
        t[1][4] = fmaf(a1, w2.x, t[1][4]); t[1][5] = fmaf(a1, w2.y, t[1][5]);
        t[1][6] = fmaf(a1, w2.z, t[1][6]); t[1][7] = fmaf(a1, w2.w, t[1][7]);
        t[2][0] = fmaf(a2, w1.x, t[2][0]); t[2][1] = fmaf(a2, w1.y, t[2][1]);
        t[2][2] = fmaf(a2, w1.z, t[2][2]); t[2][3] = fmaf(a2, w1.w, t[2][3]);
        t[2][4] = fmaf(a2, w2.x, t[2][4]); t[2][5] = fmaf(a2, w2.y, t[2][5]);
        t[2][6] = fmaf(a2, w2.z, t[2][6]); t[2][7] = fmaf(a2, w2.w, t[2][7]);
        t[3][0] = fmaf(a3, w1.x, t[3][0]); t[3][1] = fmaf(a3, w1.y, t[3][1]);
        t[3][2] = fmaf(a3, w1.z, t[3][2]); t[3][3] = fmaf(a3, w1.w, t[3][3]);
        t[3][4] = fmaf(a3, w2.x, t[3][4]); t[3][5] = fmaf(a3, w2.y, t[3][5]);
        t[3][6] = fmaf(a3, w2.z, t[3][6]); t[3][7] = fmaf(a3, w2.w, t[3][7]);
    }
    #pragma unroll
    for (int g = 0; g < 4; g++) {
        int i = ib + g * 16;
        float s1 = 0.0f;
        #pragma unroll
        for (int j = 0; j < 8; j++) s1 += t[g][j];
        #pragma unroll
        for (int off = 8; off; off >>= 1) s1 += __shfl_xor_sync(0xffffffffu, s1, off, 16);
        float mu = s1 * (1.0f / 128.0f);
        float s2 = 0.0f;
        #pragma unroll
        for (int j = 0; j < 8; j++) { float d = t[g][j] - mu; s2 += d * d; }
        #pragma unroll
        for (int off = 8; off; off >>= 1) s2 += __shfl_xor_sync(0xffffffffu, s2, off, 16);
        float inv = rsqrtf(s2 * (1.0f / 128.0f) + LNEPS);
        if (i < nvalid) {
            #pragma unroll
            for (int j = 0; j < 8; j++) {
                int m = m0 + j;
                float y = (t[g][j] - mu) * inv * ln_g[m] + ln_b[m];
                out[(size_t)(n0 + i) * DEMB + m] = fmaxf(y, 0.0f);
            }
        }
    }
}

// ---------------- launcher ----------------
extern "C" void kernel_launch(void* const* d_in, const int* in_sizes, int n_in,
                              void* d_out, int out_size) {
    const float* hidden   = (const float*)d_in[0];
    const float* edge_attr= (const float*)d_in[1];
    const float* ete      = (const float*)d_in[2];
    const float* boundary = (const float*)d_in[3];
    const float* alpha    = (const float*)d_in[4];
    const float* r1       = (const float*)d_in[5];
    const float* i1       = (const float*)d_in[6];
    const float* rb1      = (const float*)d_in[7];
    const float* ib1      = (const float*)d_in[8];
    const float* fre_w    = (const float*)d_in[9];
    const float* fre_b    = (const float*)d_in[10];
    const float* comb_w   = (const float*)d_in[11];
    const float* comb_b   = (const float*)d_in[12];
    const float* lin_w    = (const float*)d_in[13];
    const float* lin_b    = (const float*)d_in[14];
    const float* ln_g     = (const float*)d_in[15];
    const float* ln_b     = (const float*)d_in[16];
    const int*   ei       = (const int*)d_in[17];
    float* out = (float*)d_out;

    cudaFuncSetAttribute(k_edge_mma, cudaFuncAttributeMaxDynamicSharedMemorySize, DYN_EDGE);
    cudaFuncSetAttribute(k_final,    cudaFuncAttributeMaxDynamicSharedMemorySize, SMEM_FINAL);

    k_buildA<<<768, 192>>>(r1, i1);
    k_buildWrWi<<<384, 128>>>(fre_w);
    k_buildW<<<768, 128>>>(comb_w);
    k_buildCD<<<512, 128>>>(fre_b, comb_w, comb_b, rb1, ib1);
    k_nodenorm<<<NNODE / 8, 256>>>(hidden);
    k_energy<<<NEDGE / 8, 256>>>(edge_attr, ete, ei);
    k_reduce_esum<<<1, 256>>>();
    k_mask<<<NEDGE / 256, 256>>>(alpha);
    k_initacc<<<3125, 256>>>(boundary);
    k_edge_mma<<<NT, 128, DYN_EDGE>>>(hidden, edge_attr, ete, ei, rb1, ib1);
    k_final<<<(NNODE + 63) / 64, 256, SMEM_FINAL>>>(lin_w, lin_b, ln_g, ln_b, out);
}

// round 13
// speedup vs baseline: 8.5215x; 1.1655x over previous
#include <cuda_runtime.h>
#include <cuda_fp16.h>
#include <math.h>
#include <stdint.h>

// Problem constants
#define NNODE 50000
#define NEDGE 320000
#define DEMB  128
#define DIN   192
#define NB    3
#define LAM   0.01f
#define LNEPS 1e-5f

#define TE    64
#define NT    (NEDGE / TE)        // 5000
#define NHT   ((NNODE + 63) / 64) // 782

// ---------------- device scratch ----------------
__device__ float g_Wr[384 * 128];
__device__ float g_Wi[384 * 128];
__device__ float g_W[768 * 128];
__device__ float g_cvec[128];
__device__ float g_dvec[NB * 128];
__device__ float g_nodenorm[NNODE];
__device__ float g_energy[NEDGE];
__device__ float g_esum_part[256];
__device__ float g_esum;
__device__ int   g_banyg[NB];
__device__ unsigned char g_maskb[NEDGE];
__device__ float g_acc[NNODE * DEMB];

// fp16 transposed operands: B1[band][n(256)][k(192)], B2[band][m(128)][c(256)]
__device__ __align__(16) __half g_B1h[NB * 256 * 192];
__device__ __align__(16) __half g_B2h[NB * 128 * 256];
// node-hoisted GEMM1 hidden part: H[(band*2+hh)][node][128] fp16
__device__ __align__(16) __half g_H[NB * 2 * NNODE * 128];

// ---------------- helpers ----------------
__device__ __forceinline__ uint32_t smem_u32(const void* p) {
    uint32_t a;
    asm("{ .reg .u64 t; cvta.to.shared.u64 t, %1; cvt.u32.u64 %0, t; }" : "=r"(a) : "l"(p));
    return a;
}

#define LDSM4(R, addr) \
    asm volatile("ldmatrix.sync.aligned.m8n8.x4.shared.b16 {%0,%1,%2,%3}, [%4];" \
        : "=r"((R)[0]), "=r"((R)[1]), "=r"((R)[2]), "=r"((R)[3]) : "r"(addr))

#define MMA16816(C, A, B0, B1) \
    asm volatile("mma.sync.aligned.m16n8k16.row.col.f32.f16.f16.f32 " \
        "{%0,%1,%2,%3}, {%4,%5,%6,%7}, {%8,%9}, {%0,%1,%2,%3};" \
        : "+f"((C)[0]), "+f"((C)[1]), "+f"((C)[2]), "+f"((C)[3]) \
        : "r"((A)[0]), "r"((A)[1]), "r"((A)[2]), "r"((A)[3]), "r"(B0), "r"(B1))

#define CP_COMMIT() asm volatile("cp.async.commit_group;" ::: "memory")
#define CP_WAIT0()  asm volatile("cp.async.wait_group 0;" ::: "memory")

// stage one 32-K chunk's B slice (8KB across 128 threads; 64B per thread = 1 row)
__device__ __forceinline__ void stage_chunk(uint32_t dst, const __half* src) {
    asm volatile(
        "cp.async.cg.shared.global [%0], [%4], 16;\n\t"
        "cp.async.cg.shared.global [%1], [%5], 16;\n\t"
        "cp.async.cg.shared.global [%2], [%6], 16;\n\t"
        "cp.async.cg.shared.global [%3], [%7], 16;\n\t"
        :: "r"(dst), "r"(dst + 16), "r"(dst + 32), "r"(dst + 48),
           "l"(src), "l"(src + 8), "l"(src + 16), "l"(src + 24) : "memory");
}

// stage 128B of an H row (per thread) into sH
__device__ __forceinline__ void stage_H(uint32_t dst, const __half* src) {
    asm volatile(
        "cp.async.cg.shared.global [%0], [%4], 16;\n\t"
        "cp.async.cg.shared.global [%1], [%5], 16;\n\t"
        "cp.async.cg.shared.global [%2], [%6], 16;\n\t"
        "cp.async.cg.shared.global [%3], [%7], 16;\n\t"
        :: "r"(dst), "r"(dst + 16), "r"(dst + 32), "r"(dst + 48),
           "l"(src), "l"(src + 8), "l"(src + 16), "l"(src + 24) : "memory");
    asm volatile(
        "cp.async.cg.shared.global [%0], [%4], 16;\n\t"
        "cp.async.cg.shared.global [%1], [%5], 16;\n\t"
        "cp.async.cg.shared.global [%2], [%6], 16;\n\t"
        "cp.async.cg.shared.global [%3], [%7], 16;\n\t"
        :: "r"(dst + 64), "r"(dst + 80), "r"(dst + 96), "r"(dst + 112),
           "l"(src + 32), "l"(src + 40), "l"(src + 48), "l"(src + 56) : "memory");
}

// one K=32 chunk, single fp16 term; warp computes 32 rows x 64 cols
__device__ __forceinline__ void chunk1(float (&acc)[2][8][4],
                                       uint32_t aAddr, uint32_t aStride, uint32_t bAddr) {
    #pragma unroll
    for (int k16 = 0; k16 < 32; k16 += 16) {
        uint32_t a0[4], a1[4], b[4][4];
        LDSM4(a0, aAddr + k16 * 2);
        LDSM4(a1, aAddr + 16 * aStride + k16 * 2);
        #pragma unroll
        for (int ntp = 0; ntp < 4; ntp++) LDSM4(b[ntp], bAddr + ntp * 16 * 80 + k16 * 2);
        #pragma unroll
        for (int ntp = 0; ntp < 4; ntp++) {
            MMA16816(acc[0][2 * ntp],     a0, b[ntp][0], b[ntp][1]);
            MMA16816(acc[0][2 * ntp + 1], a0, b[ntp][2], b[ntp][3]);
            MMA16816(acc[1][2 * ntp],     a1, b[ntp][0], b[ntp][1]);
            MMA16816(acc[1][2 * ntp + 1], a1, b[ntp][2], b[ntp][3]);
        }
    }
}

// ---------------- precompute ----------------
__global__ void k_buildA(const float* __restrict__ r1, const float* __restrict__ i1) {
    __shared__ float ct[192], st[192];
    int n = threadIdx.x, c = blockIdx.x;
    ct[n] = (float)cospi(2.0 * n / 192.0);
    st[n] = (float)sinpi(2.0 * n / 192.0);
    __syncthreads();
    int k = c >> 8, cc = c & 255;
    const float* R = r1 + k * DIN * DEMB;
    const float* I = i1 + k * DIN * DEMB;
    float s = 0.0f;
    if (cc < 128) {
        int m = cc;
        for (int j = 0; j < 192; j++) { int t = (j * n) % 192; s += ct[t] * R[j * DEMB + m] + st[t] * I[j * DEMB + m]; }
    } else {
        int m = cc - 128;
        for (int j = 0; j < 192; j++) { int t = (j * n) % 192; s += ct[t] * I[j * DEMB + m] - st[t] * R[j * DEMB + m]; }
    }
    g_B1h[c * 192 + n] = __float2half_rn(s);
}

__global__ void k_buildWrWi(const float* __restrict__ fre_w) {
    __shared__ float ct[384], st[384];
    int p = threadIdx.x, j = blockIdx.x;
    for (int t = p; t < 384; t += 128) {
        ct[t] = (float)cospi(2.0 * t / 384.0);
        st[t] = (float)sinpi(2.0 * t / 384.0);
    }
    __syncthreads();
    float sr = 0.0f, si = 0.0f;
    for (int n = 0; n < 384; n++) {
        int t = (j * n) % 384;
        float w = fre_w[n * 128 + p];
        sr += ct[t] * w; si -= st[t] * w;
    }
    g_Wr[j * 128 + p] = sr * (1.0f / 384.0f);
    g_Wi[j * 128 + p] = si * (1.0f / 384.0f);
}

__global__ void k_buildW(const float* __restrict__ comb_w) {
    int m = threadIdx.x, r = blockIdx.x;
    int k = r >> 8, cc = r & 255;
    int j = k * 128 + (cc & 127);
    const float* src = (cc < 128) ? g_Wr : g_Wi;
    float s = 0.0f;
    for (int p = 0; p < 128; p++) s += src[j * 128 + p] * comb_w[(2 * p) * 128 + m];
    g_W[r * 128 + m] = s;
    g_B2h[k * 32768 + m * 256 + cc] = __float2half_rn(s);
}

// parallel: blocks 0..383 -> dvec[k][m], blocks 384..511 -> cvec[m]; 128-way reduce
__global__ void k_buildCD(const float* __restrict__ fre_b, const float* __restrict__ comb_w,
                          const float* __restrict__ comb_b,
                          const float* __restrict__ rb1, const float* __restrict__ ib1) {
    __shared__ float red[4];
    int b = blockIdx.x, tid = threadIdx.x, lane = tid & 31, wid = tid >> 5;
    float v;
    if (b < 384) {
        int k = b >> 7, m = b & 127, j0 = tid;
        float ar = fmaxf(rb1[k * 128 + j0] - LAM, 0.0f);
        float ai = fmaxf(ib1[k * 128 + j0] - LAM, 0.0f);
        v = ar * g_W[(k * 256 + j0) * 128 + m] + ai * g_W[(k * 256 + 128 + j0) * 128 + m];
    } else {
        int m = b - 384;
        v = fre_b[tid] * comb_w[(2 * tid) * 128 + m];
    }
    #pragma unroll
    for (int off = 16; off; off >>= 1) v += __shfl_xor_sync(0xffffffffu, v, off);
    if (lane == 0) red[wid] = v;
    __syncthreads();
    if (tid == 0) {
        float t = red[0] + red[1] + red[2] + red[3];
        if (b < 384) g_dvec[(b >> 7) * 128 + (b & 127)] = t;
        else         g_cvec[b - 384] = t + comb_b[b - 384];
    }
}

// ---------------- energy / mask / init ----------------
__global__ void k_nodenorm(const float* __restrict__ hidden) {
    int tid = threadIdx.x, w = tid >> 5, lane = tid & 31;
    if (blockIdx.x == 0) {
        g_esum_part[tid] = 0.0f;
        if (tid < NB) g_banyg[tid] = 0;
    }
    int n = blockIdx.x * 8 + w;
    const float* h = hidden + (size_t)n * DEMB;
    float s = 0.0f;
    #pragma unroll
    for (int i = 0; i < 4; i++) { float v = h[lane + 32 * i]; s += v * v; }
    #pragma unroll
    for (int off = 16; off; off >>= 1) s += __shfl_xor_sync(0xffffffffu, s, off);
    if (lane == 0) g_nodenorm[n] = s;
}

__global__ void k_energy(const float* __restrict__ ea, const float* __restrict__ ete,
                         const int* __restrict__ ei) {
    __shared__ float wsum[8];
    int tid = threadIdx.x, w = tid >> 5, lane = tid & 31;
    int e = blockIdx.x * 8 + w;
    float a = ea[(size_t)e * 32 + lane];
    float b = ete[(size_t)e * 32 + lane];
    float s = a * a + b * b;
    #pragma unroll
    for (int off = 16; off; off >>= 1) s += __shfl_xor_sync(0xffffffffu, s, off);
    if (lane == 0) { float en = 192.0f * (g_nodenorm[ei[e]] + s); g_energy[e] = en; wsum[w] = en; }
    __syncthreads();
    if (tid == 0) {
        float t = 0.0f;
        #pragma unroll
        for (int i = 0; i < 8; i++) t += wsum[i];
        atomicAdd(&g_esum_part[blockIdx.x & 255], t);
    }
}

__global__ void k_reduce_esum() {
    __shared__ float rs[8];
    int tid = threadIdx.x;
    float v = g_esum_part[tid];
    #pragma unroll
    for (int off = 16; off; off >>= 1) v += __shfl_xor_sync(0xffffffffu, v, off);
    if ((tid & 31) == 0) rs[tid >> 5] = v;
    __syncthreads();
    if (tid == 0) {
        float t = 0.0f;
        #pragma unroll
        for (int i = 0; i < 8; i++) t += rs[i];
        g_esum = t;
    }
}

__global__ void k_mask(const float* __restrict__ alpha) {
    int e = blockIdx.x * 256 + threadIdx.x;
    float en = g_energy[e], es = g_esum;
    unsigned char mb = 0;
    #pragma unroll
    for (int k = 0; k < NB; k++) {
        float al = alpha[k];
        float factor = (2.0f * (k + 1) - 1.0f) / (2.0f * NB);
        float Q = al * factor * es;
        float bnd = es / (al * (2.0f * NB));
        if (en >= Q - bnd && en <= Q + bnd) mb |= (1 << k);
    }
    g_maskb[e] = mb;
    int a0 = __syncthreads_or(mb & 1);
    int a1 = __syncthreads_or(mb & 2);
    int a2 = __syncthreads_or(mb & 4);
    if (threadIdx.x == 0) {
        if (a0) atomicOr(&g_banyg[0], 1);
        if (a1) atomicOr(&g_banyg[1], 1);
        if (a2) atomicOr(&g_banyg[2], 1);
    }
}

__global__ void k_initacc(const float* __restrict__ boundary) {
    const float4* s = (const float4*)boundary;
    float4* d = (float4*)g_acc;
    int n4 = NNODE * DEMB / 4;
    for (int i = blockIdx.x * blockDim.x + threadIdx.x; i < n4; i += gridDim.x * blockDim.x)
        d[i] = s[i];
}

// ---------------- node-hoisted GEMM1 hidden part ----------------
// H[(band*2+hh)][node][128] = hidden_f16[node][0:128] @ A_hid fp16
// smem: Xh [64][136] halfs @0 (17408), staging 2x10240 @17408
#define NH_STG  17408
#define DYN_NH  37888

__global__ void __launch_bounds__(128, 3)
k_nodeH(const float* __restrict__ hidden) {
    extern __shared__ char sb[];
    __half* s_xh = (__half*)sb;
    uint32_t dynb = smem_u32(sb);
    int tid = threadIdx.x, lane = tid & 31, wid = tid >> 5;
    int n0t = blockIdx.x * 64;

    // segment list from global band flags
    int segs[NB * 2]; int ns = 0;
    #pragma unroll
    for (int k = 0; k < NB; k++)
        if (g_banyg[k]) { segs[ns++] = k * 2; segs[ns++] = k * 2 + 1; }
    if (ns == 0) return;

    // load hidden tile, fp16
    for (int idx = tid; idx < 64 * 32; idx += 128) {
        int r = idx >> 5, q = idx & 31;
        int node = n0t + r; if (node >= NNODE) node = 0;
        float4 v = ((const float4*)hidden)[(size_t)node * 32 + q];
        __half2* ph = (__half2*)(s_xh + r * 136 + q * 4);
        ph[0] = __floats2half2_rn(v.x, v.y);
        ph[1] = __floats2half2_rn(v.z, v.w);
    }
    __syncthreads();

    int m0 = (wid & 1) * 32, n0 = (wid >> 1) * 64;
    int rowA = ((lane >> 3) & 1) * 8 + (lane & 7);
    int colA = ((lane >> 4) & 1) * 8;
    int rowB = ((lane >> 4) & 1) * 8 + (lane & 7);
    int colB = ((lane >> 3) & 1) * 8;
    uint32_t stgDst = dynb + NH_STG + (uint32_t)(tid * 80);

    stage_chunk(stgDst, g_B1h + ((size_t)(segs[0] >> 1) * 256 + (segs[0] & 1) * 128 + tid) * 192);
    CP_COMMIT();

    for (int si = 0; si < ns; si++) {
        int band = segs[si] >> 1, hh = segs[si] & 1;
        const __half* gB = g_B1h + ((size_t)band * 256 + hh * 128 + tid) * 192;
        float acc[2][8][4];
        #pragma unroll
        for (int i = 0; i < 2; i++)
            #pragma unroll
            for (int j = 0; j < 8; j++)
                #pragma unroll
                for (int q = 0; q < 4; q++) acc[i][j][q] = 0.0f;
        #pragma unroll 1
        for (int c = 0; c < 4; c++) {
            CP_WAIT0();
            __syncthreads();
            if (c < 3) stage_chunk(stgDst + ((c + 1) & 1) * 10240, gB + (c + 1) * 32);
            else if (si + 1 < ns)
                stage_chunk(stgDst, g_B1h + ((size_t)(segs[si + 1] >> 1) * 256 + (segs[si + 1] & 1) * 128 + tid) * 192);
            CP_COMMIT();
            uint32_t xh = dynb + (uint32_t)((m0 + rowA) * 272 + (c * 32 + colA) * 2);
            uint32_t bh = dynb + NH_STG + (c & 1) * 10240 + (uint32_t)((n0 + rowB) * 80 + colB * 2);
            chunk1(acc, xh, 272u, bh);
        }
        __half* Hout = g_H + (size_t)(band * 2 + hh) * NNODE * 128;
        #pragma unroll
        for (int mt = 0; mt < 2; mt++) {
            int r0 = m0 + mt * 16 + (lane >> 2);
            int node0 = n0t + r0, node1 = node0 + 8;
            #pragma unroll
            for (int nt = 0; nt < 8; nt++) {
                int cb = n0 + nt * 8 + (lane & 3) * 2;
                if (node0 < NNODE)
                    *(__half2*)(Hout + (size_t)node0 * 128 + cb) = __floats2half2_rn(acc[mt][nt][0], acc[mt][nt][1]);
                if (node1 < NNODE)
                    *(__half2*)(Hout + (size_t)node1 * 128 + cb) = __floats2half2_rn(acc[mt][nt][2], acc[mt][nt][3]);
            }
        }
    }
}

// ---------------- main edge kernel (HMMA fp16, tail GEMM1 + H gather) ----------------
// dynamic smem:
//   Xtail [64][72] halfs @0      (9216)
//   sH    [64][136] halfs @9216  (17408)
//   actH  [64][136] halfs @26624 (17408)
//   staging [2 buf][128][40] @44032 (20480)
//   s_res fp32 [64][132] aliases @0 (post-GEMM only)
#define OFF_SH    9216
#define OFF_ACTH  26624
#define OFF_STG   44032
#define DYN_EDGE  64512

__global__ void __launch_bounds__(128, 3)
k_edge_mma(const float* __restrict__ ea, const float* __restrict__ ete,
           const int* __restrict__ ei,
           const float* __restrict__ rb1, const float* __restrict__ ib1) {
    extern __shared__ char sb[];
    __half* s_xt = (__half*)sb;
    __half* s_ah = (__half*)(sb + OFF_ACTH);
    float*  s_res = (float*)sb;                  // [64][132], post-GEMM alias
    uint32_t dynb = smem_u32(sb);

    __shared__ int s_src[TE], s_dst[TE];
    __shared__ unsigned char s_mk[TE];
    __shared__ int s_any[NB];
    __shared__ float s_bias[256], s_base[128];

    int tid = threadIdx.x, lane = tid & 31, wid = tid >> 5;
    int eb = blockIdx.x * TE;

    if (tid < TE) {
        s_src[tid] = ei[eb + tid];
        s_dst[tid] = ei[NEDGE + eb + tid];
        s_mk[tid]  = g_maskb[eb + tid];
    }
    __syncthreads();
    if (tid < NB) {
        int a = 0;
        for (int e = 0; e < TE; e++) a |= (s_mk[e] >> tid) & 1;
        s_any[tid] = a;
    }
    __syncthreads();
    {
        float b = g_cvec[tid];
        #pragma unroll
        for (int k = 0; k < NB; k++) if (!s_any[k]) b += g_dvec[k * 128 + tid];
        s_base[tid] = b;
    }
    bool anyband = s_any[0] || s_any[1] || s_any[2];

    // fragment geometry: 4 warps = 2m x 2n
    int m0 = (wid & 1) * 32, n0 = (wid >> 1) * 64;
    int rowA = ((lane >> 3) & 1) * 8 + (lane & 7);
    int colA = ((lane >> 4) & 1) * 8;
    int rowB = ((lane >> 4) & 1) * 8 + (lane & 7);
    int colB = ((lane >> 3) & 1) * 8;
    uint32_t stgDst = dynb + OFF_STG + (uint32_t)(tid * 80);
    int hE = tid >> 1, hP = tid & 1;            // H-gather mapping
    uint32_t hDst = dynb + OFF_SH + (uint32_t)(hE * 272 + hP * 128);

    float acc2[2][8][4];
    #pragma unroll
    for (int i = 0; i < 2; i++)
        #pragma unroll
        for (int j = 0; j < 8; j++)
            #pragma unroll
            for (int q = 0; q < 4; q++) acc2[i][j][q] = 0.0f;

    if (anyband) {
        // segment list: (band,hh) pairs
        int segBand[NB]; int nseg = 0;
        #pragma unroll
        for (int k = 0; k < NB; k++) if (s_any[k]) segBand[nseg++] = k;
        int totseg = nseg * 2;

        // prefetch: segment-0 H slice + tail chunk 0
        {
            int b0 = segBand[0];
            stage_H(hDst, g_H + ((size_t)(b0 * 2 + 0) * NNODE + s_src[hE]) * 128 + hP * 64);
            stage_chunk(stgDst, g_B1h + ((size_t)b0 * 256 + tid) * 192 + 128);
            CP_COMMIT();
        }

        // gather X tail (ea|ete), round to fp16
        for (int idx = tid; idx < TE * 16; idx += 128) {
            int r = idx >> 4, q = idx & 15;
            float4 v = (q < 8) ? ((const float4*)(ea + (size_t)(eb + r) * 32))[q]
                               : ((const float4*)(ete + (size_t)(eb + r) * 32))[q - 8];
            __half2* ph = (__half2*)(s_xt + r * 72 + q * 4);
            ph[0] = __floats2half2_rn(v.x, v.y);
            ph[1] = __floats2half2_rn(v.z, v.w);
        }

        for (int s = 0; s < totseg; s++) {
            int band = segBand[s >> 1], hh = s & 1;
            if (hh == 0) {
                s_bias[tid]       = rb1[band * 128 + tid];
                s_bias[tid + 128] = ib1[band * 128 + tid];
            }
            const __half* g1t = g_B1h + ((size_t)band * 256 + hh * 128 + tid) * 192 + 128;
            const __half* g2h = g_B2h + (size_t)band * 32768 + (size_t)tid * 256 + hh * 128;

            float acc1[2][8][4];
            #pragma unroll
            for (int i = 0; i < 2; i++)
                #pragma unroll
                for (int j = 0; j < 8; j++)
                    #pragma unroll
                    for (int q = 0; q < 4; q++) acc1[i][j][q] = 0.0f;

            // ---- GEMM1 tail: 2 K-chunks ----
            #pragma unroll 1
            for (int c = 0; c < 2; c++) {
                CP_WAIT0();
                __syncthreads();
                if (c == 0) stage_chunk(stgDst + 10240, g1t + 32);
                else        stage_chunk(stgDst, g2h);   // GEMM2 chunk 0 -> buf0
                CP_COMMIT();
                uint32_t xh = dynb + (uint32_t)((m0 + rowA) * 144 + (c * 32 + colA) * 2);
                uint32_t bh = dynb + OFF_STG + (c & 1) * 10240 + (uint32_t)((n0 + rowB) * 80 + colB * 2);
                chunk1(acc1, xh, 144u, bh);
            }

            // ---- activation: u = acc + H, then mask/bias/relu-shrink -> act fp16 ----
            #pragma unroll
            for (int mt = 0; mt < 2; mt++) {
                int r0 = m0 + mt * 16 + (lane >> 2);
                float mk0 = (float)((s_mk[r0] >> band) & 1);
                float mk1 = (float)((s_mk[r0 + 8] >> band) & 1);
                #pragma unroll
                for (int nt = 0; nt < 8; nt++) {
                    int cb = n0 + nt * 8 + (lane & 3) * 2;
                    float b0 = s_bias[hh * 128 + cb], b1 = s_bias[hh * 128 + cb + 1];
                    float2 h0 = __half22float2(*(const __half2*)(sb + OFF_SH + r0 * 272 + cb * 2));
                    float2 h1 = __half22float2(*(const __half2*)(sb + OFF_SH + (r0 + 8) * 272 + cb * 2));
                    float a00 = fmaxf(fmaf(mk0, acc1[mt][nt][0] + h0.x, b0) - LAM, 0.0f);
                    float a01 = fmaxf(fmaf(mk0, acc1[mt][nt][1] + h0.y, b1) - LAM, 0.0f);
                    float a10 = fmaxf(fmaf(mk1, acc1[mt][nt][2] + h1.x, b0) - LAM, 0.0f);
                    float a11 = fmaxf(fmaf(mk1, acc1[mt][nt][3] + h1.y, b1) - LAM, 0.0f);
                    *(__half2*)(s_ah + r0 * 136 + cb)       = __floats2half2_rn(a00, a01);
                    *(__half2*)(s_ah + (r0 + 8) * 136 + cb) = __floats2half2_rn(a10, a11);
                }
            }

            // ---- GEMM2: 4 K-chunks ----
            #pragma unroll 1
            for (int c = 0; c < 4; c++) {
                CP_WAIT0();
                __syncthreads();          // publishes act + staged chunk
                if (c < 3) stage_chunk(stgDst + ((c + 1) & 1) * 10240, g2h + (c + 1) * 32);
                else if (s + 1 < totseg) {
                    int nb = segBand[(s + 1) >> 1], nhh = (s + 1) & 1;
                    stage_H(hDst, g_H + ((size_t)(nb * 2 + nhh) * NNODE + s_src[hE]) * 128 + hP * 64);
                    stage_chunk(stgDst, g_B1h + ((size_t)nb * 256 + nhh * 128 + tid) * 192 + 128);
                }
                CP_COMMIT();
                uint32_t ah = dynb + OFF_ACTH + (uint32_t)((m0 + rowA) * 272 + (c * 32 + colA) * 2);
                uint32_t bh = dynb + OFF_STG + (c & 1) * 10240 + (uint32_t)((n0 + rowB) * 80 + colB * 2);
                chunk1(acc2, ah, 272u, bh);
            }
        }
    }

    // ---- stage msg2 into smem (aliases Xtail/sH region) and scatter ----
    __syncthreads();
    if (anyband) {
        #pragma unroll
        for (int mt = 0; mt < 2; mt++) {
            int r0 = m0 + mt * 16 + (lane >> 2);
            #pragma unroll
            for (int nt = 0; nt < 8; nt++) {
                int cb = n0 + nt * 8 + (lane & 3) * 2;
                *(float2*)(s_res + r0 * 132 + cb)       = make_float2(acc2[mt][nt][0], acc2[mt][nt][1]);
                *(float2*)(s_res + (r0 + 8) * 132 + cb) = make_float2(acc2[mt][nt][2], acc2[mt][nt][3]);
            }
        }
    }
    __syncthreads();
    {
        int row = tid >> 1, cb = (tid & 1) * 64;
        int dst = s_dst[row];
        float* p = g_acc + (size_t)dst * DEMB + cb;
        #pragma unroll
        for (int j = 0; j < 16; j++) {
            int c = cb + 4 * j;
            float x0 = s_base[c], x1 = s_base[c + 1], x2 = s_base[c + 2], x3 = s_base[c + 3];
            if (anyband) {
                x0 += s_res[row * 132 + c];     x1 += s_res[row * 132 + c + 1];
                x2 += s_res[row * 132 + c + 2]; x3 += s_res[row * 132 + c + 3];
            }
            asm volatile("red.global.add.v4.f32 [%0], {%1,%2,%3,%4};"
                         :: "l"(p + 4 * j), "f"(x0), "f"(x1), "f"(x2), "f"(x3) : "memory");
        }
    }
}

// ---------------- node epilogue (64 nodes/block, 4 per thread-group, guarded) ----------------
#define SMEM_FINAL ((128 * 128 + 64 * 128) * 4)

__global__ void __launch_bounds__(256, 1)
k_final(const float* __restrict__ lin_w, const float* __restrict__ lin_b,
        const float* __restrict__ ln_g, const float* __restrict__ ln_b,
        float* __restrict__ out) {
    extern __shared__ float sm[];
    float* lw = sm;
    float* at = sm + 128 * 128;
    int tid = threadIdx.x;
    int n0 = blockIdx.x * 64;
    int nvalid = NNODE - n0; if (nvalid > 64) nvalid = 64;

    for (int idx = tid; idx < 128 * 128; idx += 256) lw[idx] = lin_w[idx];
    for (int idx = tid; idx < nvalid * 128; idx += 256) at[idx] = g_acc[(size_t)n0 * DEMB + idx];
    __syncthreads();

    int m0 = (tid & 15) * 8;
    int ib = tid >> 4;                 // 0..15
    float t[4][8];
    #pragma unroll
    for (int g = 0; g < 4; g++)
        #pragma unroll
        for (int j = 0; j < 8; j++) t[g][j] = lin_b[m0 + j];
    const float* ar0 = at + ib * 128;
    bool v1 = (ib + 16 < nvalid), v2 = (ib + 32 < nvalid), v3 = (ib + 48 < nvalid);
    for (int q = 0; q < 128; q++) {
        float4 w1 = *(const float4*)&lw[q * 128 + m0];
        float4 w2 = *(const float4*)&lw[q * 128 + m0 + 4];
        float a0 = ar0[q];
        float a1 = v1 ? ar0[16 * 128 + q] : 0.0f;
        float a2 = v2 ? ar0[32 * 128 + q] : 0.0f;
        float a3 = v3 ? ar0[48 * 128 + q] : 0.0f;
        t[0][0] = fmaf(a0, w1.x, t[0][0]); t[0][1] = fmaf(a0, w1.y, t[0][1]);
        t[0][2] = fmaf(a0, w1.z, t[0][2]); t[0][3] = fmaf(a0, w1.w, t[0][3]);
        t[0][4] = fmaf(a0, w2.x, t[0][4]); t[0][5] = fmaf(a0, w2.y, t[0][5]);
        t[0][6] = fmaf(a0, w2.z, t[0][6]); t[0][7] = fmaf(a0, w2.w, t[0][7]);
        t[1][0] = fmaf(a1, w1.x, t[1][0]); t[1][1] = fmaf(a1, w1.y, t[1][1]);
        t[1][2] = fmaf(a1, w1.z, t[1][2]); t[1][3] = fmaf(a1, w1.w, t[1][3]);
        t[1][4] = fmaf(a1, w2.x, t[1][4]); t[1][5] = fmaf(a1, w2.y, t[1][5]);
        t[1][6] = fmaf(a1, w2.z, t[1][6]); t[1][7] = fmaf(a1, w2.w, t[1][7]);
        t[2][0] = fmaf(a2, w1.x, t[2][0]); t[2][1] = fmaf(a2, w1.y, t[2][1]);
        t[2][2] = fmaf(a2, w1.z, t[2][2]); t[2][3] = fmaf(a2, w1.w, t[2][3]);
        t[2][4] = fmaf(a2, w2.x, t[2][4]); t[2][5] = fmaf(a2, w2.y, t[2][5]);
        t[2][6] = fmaf(a2, w2.z, t[2][6]); t[2][7] = fmaf(a2, w2.w, t[2][7]);
        t[3][0] = fmaf(a3, w1.x, t[3][0]); t[3][1] = fmaf(a3, w1.y, t[3][1]);
        t[3][2] = fmaf(a3, w1.z, t[3][2]); t[3][3] = fmaf(a3, w1.w, t[3][3]);
        t[3][4] = fmaf(a3, w2.x, t[3][4]); t[3][5] = fmaf(a3, w2.y, t[3][5]);
        t[3][6] = fmaf(a3, w2.z, t[3][6]); t[3][7] = fmaf(a3, w2.w, t[3][7]);
    }
    #pragma unroll
    for (int g = 0; g < 4; g++) {
        int i = ib + g * 16;
        float s1 = 0.0f;
        #pragma unroll
        for (int j = 0; j < 8; j++) s1 += t[g][j];
        #pragma unroll
        for (int off = 8; off; off >>= 1) s1 += __shfl_xor_sync(0xffffffffu, s1, off, 16);
        float mu = s1 * (1.0f / 128.0f);
        float s2 = 0.0f;
        #pragma unroll
        for (int j = 0; j < 8; j++) { float d = t[g][j] - mu; s2 += d * d; }
        #pragma unroll
        for (int off = 8; off; off >>= 1) s2 += __shfl_xor_sync(0xffffffffu, s2, off, 16);
        float inv = rsqrtf(s2 * (1.0f / 128.0f) + LNEPS);
        if (i < nvalid) {
            #pragma unroll
            for (int j = 0; j < 8; j++) {
                int m = m0 + j;
                float y = (t[g][j] - mu) * inv * ln_g[m] + ln_b[m];
                out[(size_t)(n0 + i) * DEMB + m] = fmaxf(y, 0.0f);
            }
        }
    }
}

// ---------------- launcher ----------------
extern "C" void kernel_launch(void* const* d_in, const int* in_sizes, int n_in,
                              void* d_out, int out_size) {
    const float* hidden   = (const float*)d_in[0];
    const float* edge_attr= (const float*)d_in[1];
    const float* ete      = (const float*)d_in[2];
    const float* boundary = (const float*)d_in[3];
    const float* alpha    = (const float*)d_in[4];
    const float* r1       = (const float*)d_in[5];
    const float* i1       = (const float*)d_in[6];
    const float* rb1      = (const float*)d_in[7];
    const float* ib1      = (const float*)d_in[8];
    const float* fre_w    = (const float*)d_in[9];
    const float* fre_b    = (const float*)d_in[10];
    const float* comb_w   = (const float*)d_in[11];
    const float* comb_b   = (const float*)d_in[12];
    const float* lin_w    = (const float*)d_in[13];
    const float* lin_b    = (const float*)d_in[14];
    const float* ln_g     = (const float*)d_in[15];
    const float* ln_b     = (const float*)d_in[16];
    const int*   ei       = (const int*)d_in[17];
    float* out = (float*)d_out;

    cudaFuncSetAttribute(k_nodeH,    cudaFuncAttributeMaxDynamicSharedMemorySize, DYN_NH);
    cudaFuncSetAttribute(k_edge_mma, cudaFuncAttributeMaxDynamicSharedMemorySize, DYN_EDGE);
    cudaFuncSetAttribute(k_final,    cudaFuncAttributeMaxDynamicSharedMemorySize, SMEM_FINAL);

    k_buildA<<<768, 192>>>(r1, i1);
    k_buildWrWi<<<384, 128>>>(fre_w);
    k_buildW<<<768, 128>>>(comb_w);
    k_buildCD<<<512, 128>>>(fre_b, comb_w, comb_b, rb1, ib1);
    k_nodenorm<<<NNODE / 8, 256>>>(hidden);
    k_energy<<<NEDGE / 8, 256>>>(edge_attr, ete, ei);
    k_reduce_esum<<<1, 256>>>();
    k_mask<<<NEDGE / 256, 256>>>(alpha);
    k_nodeH<<<NHT, 128, DYN_NH>>>(hidden);
    k_initacc<<<3125, 256>>>(boundary);
    k_edge_mma<<<NT, 128, DYN_EDGE>>>(edge_attr, ete, ei, rb1, ib1);
    k_final<<<(NNODE + 63) / 64, 256, SMEM_FINAL>>>(lin_w, lin_b, ln_g, ln_b, out);
}